// round 1
// baseline (speedup 1.0000x reference)
#include <cuda_runtime.h>
#include <math.h>

#define DEV_INLINE __device__ __forceinline__

// ---------------- static scratch (allocation-free rule) ----------------
__device__ float g_q[2048 * 4 * 98 * 24];     // (win, head, n, d), q pre-scaled
__device__ float g_k[2048 * 4 * 98 * 24];
__device__ float g_v[2048 * 4 * 98 * 24];
__device__ float g_att[2048 * 98 * 96];       // attention out, window layout
__device__ float g_x2[200704 * 96];           // x + attn branch (spatial layout)
__device__ float g_hid[200704 * 384];         // MLP hidden
__device__ float g_bias[4 * 98 * 98];         // rel-pos bias table per head

// window token (B_, i) -> spatial element base offset (token*96), including the
// shifted-window roll (identical mapping for gather on the way in and scatter
// on the way out, since roll(+S) o reverse is the inverse of roll(-S) o partition).
DEV_INLINE int spat_base(int B_, int i) {
    int b = B_ >> 8, rem = B_ & 255;
    int wd = rem >> 6, wh = (rem >> 3) & 7, ww = rem & 7;
    int td = i / 49, r = i - td * 49;
    int th = r / 7, tw = r - th * 7;
    int d = (wd * 2 + td + 1) & 7;
    int hh = wh * 7 + th + 3; if (hh >= 56) hh -= 56;
    int w2 = ww * 7 + tw + 3; if (w2 >= 56) w2 -= 56;
    return (((b * 8 + d) * 56 + hh) * 56 + w2) * 96;
}

DEV_INLINE float warp_sum(float v) {
    #pragma unroll
    for (int o = 16; o; o >>= 1) v += __shfl_xor_sync(0xffffffffu, v, o);
    return v;
}
DEV_INLINE float warp_max(float v) {
    #pragma unroll
    for (int o = 16; o; o >>= 1) v = fmaxf(v, __shfl_xor_sync(0xffffffffu, v, o));
    return v;
}

// ---------------- kernel 0: relative-position bias table ----------------
__global__ void k_bias(const float* __restrict__ rpb) {
    int i = blockIdx.x;        // 0..97
    int j = threadIdx.x;       // 0..127
    if (j >= 98) return;
    int di = i / 49, ri = i - di * 49, hi = ri / 7, wi = ri - hi * 7;
    int dj = j / 49, rj = j - dj * 49, hj = rj / 7, wj = rj - hj * 7;
    int r = (di - dj + 1) * 169 + (hi - hj + 6) * 13 + (wi - wj + 6);
    #pragma unroll
    for (int h = 0; h < 4; ++h)
        g_bias[h * 9604 + i * 98 + j] = rpb[r * 4 + h];
}

// ---------------- kernel 1: LN1 + roll + partition + QKV GEMM ----------------
// One block per window. SMEM: qkv weights (96x288) + x tile (104x97, rows 98+ zero).
__global__ __launch_bounds__(256) void k_qkv(const float* __restrict__ x,
                                             const float* __restrict__ n1g,
                                             const float* __restrict__ n1b,
                                             const float* __restrict__ qw,
                                             const float* __restrict__ qb) {
    extern __shared__ float sm[];
    float* ws = sm;                 // 27648
    float* xt = ws + 96 * 288;      // 104*97
    float* bb = xt + 104 * 97;      // 288
    int*   ro = (int*)(bb + 288);   // 98
    const int tid = threadIdx.x, B_ = blockIdx.x;
    const int warp = tid >> 5, lane = tid & 31;

    for (int i = tid; i < 96 * 288; i += 256) ws[i] = qw[i];
    for (int i = tid; i < 288; i += 256) bb[i] = qb[i];
    if (tid < 98) ro[tid] = spat_base(B_, tid);
    __syncthreads();

    for (int i = tid; i < 104 * 96; i += 256) {
        int r = i / 96, c = i - r * 96;
        xt[r * 97 + c] = (r < 98) ? x[ro[r] + c] : 0.f;
    }
    __syncthreads();

    // LayerNorm per token (one warp per token)
    float g0 = n1g[lane], g1 = n1g[lane + 32], g2 = n1g[lane + 64];
    float b0 = n1b[lane], b1 = n1b[lane + 32], b2 = n1b[lane + 64];
    for (int t = warp; t < 98; t += 8) {
        float v0 = xt[t * 97 + lane], v1 = xt[t * 97 + lane + 32], v2 = xt[t * 97 + lane + 64];
        float mean = warp_sum(v0 + v1 + v2) * (1.f / 96.f);
        float d0 = v0 - mean, d1 = v1 - mean, d2 = v2 - mean;
        float var = warp_sum(d0 * d0 + d1 * d1 + d2 * d2) * (1.f / 96.f);
        float rstd = rsqrtf(var + 1e-5f);
        xt[t * 97 + lane]      = d0 * rstd * g0 + b0;
        xt[t * 97 + lane + 32] = d1 * rstd * g1 + b1;
        xt[t * 97 + lane + 64] = d2 * rstd * g2 + b2;
    }
    __syncthreads();

    // GEMM 104x288, 4-row x 9-col register tiles
    for (int t = 0; t < 4; ++t) {
        int r0 = t * 32 + warp * 4;
        if (r0 >= 104) continue;
        float acc[4][9];
        #pragma unroll
        for (int i = 0; i < 4; ++i)
            #pragma unroll
            for (int j = 0; j < 9; ++j) acc[i][j] = 0.f;
        const float* xr = xt + r0 * 97;
        #pragma unroll 4
        for (int k = 0; k < 96; ++k) {
            float a0 = xr[k], a1 = xr[97 + k], a2 = xr[194 + k], a3 = xr[291 + k];
            const float* wk = ws + k * 288 + lane;
            #pragma unroll
            for (int j = 0; j < 9; ++j) {
                float w = wk[32 * j];
                acc[0][j] += a0 * w; acc[1][j] += a1 * w;
                acc[2][j] += a2 * w; acc[3][j] += a3 * w;
            }
        }
        #pragma unroll
        for (int i = 0; i < 4; ++i) {
            int row = r0 + i;
            if (row >= 98) break;
            #pragma unroll
            for (int j = 0; j < 9; ++j) {
                int col = lane + 32 * j;
                float v = acc[i][j] + bb[col];
                int which = col / 96;
                int cc = col - which * 96;
                int head = cc / 24;
                int dd = cc - head * 24;
                int off = ((B_ * 4 + head) * 98 + row) * 24 + dd;
                if (which == 0)      g_q[off] = v * 0.20412414523193154f;  // 1/sqrt(24)
                else if (which == 1) g_k[off] = v;
                else                 g_v[off] = v;
            }
        }
    }
}

// ---------------- kernel 2: attention per (window, head) ----------------
__global__ __launch_bounds__(256) void k_attn(const float* __restrict__ mask) {
    extern __shared__ float sm[];
    float* qt = sm;             // 104*25
    float* kt = qt + 2600;
    float* vt = kt + 2600;
    float* s  = vt + 2600;      // 104*105
    const int B_ = blockIdx.x, head = blockIdx.y;
    const int tid = threadIdx.x, warp = tid >> 5, lane = tid & 31;
    const int base = ((B_ * 4 + head) * 98) * 24;

    for (int i = tid; i < 104 * 24; i += 256) {
        int r = i / 24, c = i - r * 24;
        float qv = 0.f, kv = 0.f, vv = 0.f;
        if (r < 98) {
            int off = base + r * 24 + c;
            qv = g_q[off]; kv = g_k[off]; vv = g_v[off];
        }
        qt[r * 25 + c] = qv; kt[r * 25 + c] = kv; vt[r * 25 + c] = vv;
    }
    __syncthreads();

    const float* bi = g_bias + head * 9604;
    const float* mk = mask + (B_ & 255) * 9604;

    // scores: 4-row x 4-col register tiles
    for (int t = 0; t < 4; ++t) {
        int r0 = t * 32 + warp * 4;
        if (r0 >= 104) continue;
        float acc[4][4];
        #pragma unroll
        for (int i = 0; i < 4; ++i)
            #pragma unroll
            for (int j = 0; j < 4; ++j) acc[i][j] = 0.f;
        const float* qr = qt + r0 * 25;
        #pragma unroll
        for (int k = 0; k < 24; ++k) {
            float a0 = qr[k], a1 = qr[25 + k], a2 = qr[50 + k], a3 = qr[75 + k];
            #pragma unroll
            for (int j = 0; j < 4; ++j) {
                float kk = kt[(lane + 32 * j) * 25 + k];
                acc[0][j] += a0 * kk; acc[1][j] += a1 * kk;
                acc[2][j] += a2 * kk; acc[3][j] += a3 * kk;
            }
        }
        #pragma unroll
        for (int i = 0; i < 4; ++i) {
            int row = r0 + i;
            #pragma unroll
            for (int j = 0; j < 4; ++j) {
                int col = lane + 32 * j;
                if (col < 98) {
                    float v = (row < 98) ? acc[i][j] + bi[row * 98 + col] + mk[row * 98 + col] : 0.f;
                    s[row * 105 + col] = v;
                }
            }
        }
    }
    __syncthreads();

    // softmax: one warp per row
    for (int i = warp; i < 98; i += 8) {
        float mx = -1e30f;
        for (int j = lane; j < 98; j += 32) mx = fmaxf(mx, s[i * 105 + j]);
        mx = warp_max(mx);
        float sum = 0.f;
        for (int j = lane; j < 98; j += 32) {
            float e = __expf(s[i * 105 + j] - mx);
            s[i * 105 + j] = e;
            sum += e;
        }
        sum = warp_sum(sum);
        float inv = 1.f / sum;
        for (int j = lane; j < 98; j += 32) s[i * 105 + j] *= inv;
    }
    __syncthreads();

    // PV: 4 rows per thread-chunk, lane = output dim (<24)
    for (int t = 0; t < 4; ++t) {
        int r0 = t * 32 + warp * 4;
        if (r0 >= 98) continue;
        float acc[4] = {0.f, 0.f, 0.f, 0.f};
        if (lane < 24) {
            const float* p0 = s + r0 * 105;
            #pragma unroll 2
            for (int j = 0; j < 98; ++j) {
                float vv = vt[j * 25 + lane];
                acc[0] += p0[j] * vv;
                acc[1] += p0[105 + j] * vv;
                acc[2] += p0[210 + j] * vv;
                acc[3] += p0[315 + j] * vv;
            }
        }
        #pragma unroll
        for (int i = 0; i < 4; ++i) {
            int row = r0 + i;
            if (row < 98 && lane < 24)
                g_att[(B_ * 98 + row) * 96 + head * 24 + lane] = acc[i];
        }
    }
}

// ---------------- kernel 3: proj + inverse roll/reverse + residual ----------------
__global__ __launch_bounds__(256) void k_proj(const float* __restrict__ x,
                                              const float* __restrict__ pw,
                                              const float* __restrict__ pb) {
    extern __shared__ float sm[];
    float* ws = sm;                 // 96*96
    float* at = ws + 96 * 96;       // 104*97
    float* bbp = at + 104 * 97;     // 96
    int* ro = (int*)(bbp + 96);     // 98
    const int tid = threadIdx.x, B_ = blockIdx.x;
    const int warp = tid >> 5, lane = tid & 31;

    for (int i = tid; i < 96 * 96; i += 256) ws[i] = pw[i];
    if (tid < 96) bbp[tid] = pb[tid];
    if (tid < 98) ro[tid] = spat_base(B_, tid);
    __syncthreads();

    for (int i = tid; i < 104 * 96; i += 256) {
        int r = i / 96, c = i - r * 96;
        at[r * 97 + c] = (r < 98) ? g_att[(B_ * 98 + r) * 96 + c] : 0.f;
    }
    __syncthreads();

    for (int t = 0; t < 4; ++t) {
        int r0 = t * 32 + warp * 4;
        if (r0 >= 104) continue;
        float acc[4][3];
        #pragma unroll
        for (int i = 0; i < 4; ++i)
            #pragma unroll
            for (int j = 0; j < 3; ++j) acc[i][j] = 0.f;
        const float* ar = at + r0 * 97;
        #pragma unroll 4
        for (int k = 0; k < 96; ++k) {
            float a0 = ar[k], a1 = ar[97 + k], a2 = ar[194 + k], a3 = ar[291 + k];
            const float* wk = ws + k * 96 + lane;
            #pragma unroll
            for (int j = 0; j < 3; ++j) {
                float w = wk[32 * j];
                acc[0][j] += a0 * w; acc[1][j] += a1 * w;
                acc[2][j] += a2 * w; acc[3][j] += a3 * w;
            }
        }
        #pragma unroll
        for (int i = 0; i < 4; ++i) {
            int row = r0 + i;
            if (row >= 98) break;
            int base = ro[row];
            #pragma unroll
            for (int j = 0; j < 3; ++j) {
                int col = lane + 32 * j;
                g_x2[base + col] = x[base + col] + acc[i][j] + bbp[col];
            }
        }
    }
}

// ---------------- kernel 4: LN2 + fc1 + GELU ----------------
__global__ __launch_bounds__(256) void k_mlp1(const float* __restrict__ n2g,
                                              const float* __restrict__ n2b,
                                              const float* __restrict__ f1w,
                                              const float* __restrict__ f1b) {
    extern __shared__ float sm[];
    float* ws = sm;                 // 96*384
    float* xt = ws + 96 * 384;      // 64*97
    float* bb = xt + 64 * 97;       // 384
    const int tid = threadIdx.x, warp = tid >> 5, lane = tid & 31;
    const int tok0 = blockIdx.x * 64;

    for (int i = tid; i < 96 * 384; i += 256) ws[i] = f1w[i];
    for (int i = tid; i < 384; i += 256) bb[i] = f1b[i];
    for (int i = tid; i < 64 * 96; i += 256) {
        int r = i / 96, c = i - r * 96;
        xt[r * 97 + c] = g_x2[(tok0 + r) * 96 + c];
    }
    __syncthreads();

    float g0 = n2g[lane], g1 = n2g[lane + 32], g2 = n2g[lane + 64];
    float b0 = n2b[lane], b1 = n2b[lane + 32], b2 = n2b[lane + 64];
    for (int t = warp; t < 64; t += 8) {
        float v0 = xt[t * 97 + lane], v1 = xt[t * 97 + lane + 32], v2 = xt[t * 97 + lane + 64];
        float mean = warp_sum(v0 + v1 + v2) * (1.f / 96.f);
        float d0 = v0 - mean, d1 = v1 - mean, d2 = v2 - mean;
        float var = warp_sum(d0 * d0 + d1 * d1 + d2 * d2) * (1.f / 96.f);
        float rstd = rsqrtf(var + 1e-5f);
        xt[t * 97 + lane]      = d0 * rstd * g0 + b0;
        xt[t * 97 + lane + 32] = d1 * rstd * g1 + b1;
        xt[t * 97 + lane + 64] = d2 * rstd * g2 + b2;
    }
    __syncthreads();

    for (int rc = 0; rc < 2; ++rc) {
        int r0 = warp * 8 + rc * 4;
        float acc[4][12];
        #pragma unroll
        for (int i = 0; i < 4; ++i)
            #pragma unroll
            for (int j = 0; j < 12; ++j) acc[i][j] = 0.f;
        const float* xr = xt + r0 * 97;
        #pragma unroll 2
        for (int k = 0; k < 96; ++k) {
            float a0 = xr[k], a1 = xr[97 + k], a2 = xr[194 + k], a3 = xr[291 + k];
            const float* wk = ws + k * 384 + lane;
            #pragma unroll
            for (int j = 0; j < 12; ++j) {
                float w = wk[32 * j];
                acc[0][j] += a0 * w; acc[1][j] += a1 * w;
                acc[2][j] += a2 * w; acc[3][j] += a3 * w;
            }
        }
        #pragma unroll
        for (int i = 0; i < 4; ++i) {
            int row = tok0 + r0 + i;
            #pragma unroll
            for (int j = 0; j < 12; ++j) {
                int col = lane + 32 * j;
                float u = acc[i][j] + bb[col];
                g_hid[row * 384 + col] = 0.5f * u * (1.f + erff(u * 0.70710678118654752f));
            }
        }
    }
}

// ---------------- kernel 5: fc2 + bias + residual -> out ----------------
__global__ __launch_bounds__(256) void k_mlp2(const float* __restrict__ f2w,
                                              const float* __restrict__ f2b,
                                              float* __restrict__ out) {
    extern __shared__ float sm[];
    float* hid = sm;                // 128*385
    const int tid = threadIdx.x, warp = tid >> 5, lane = tid & 31;
    const int tok0 = blockIdx.x * 128;

    for (int i = tid; i < 128 * 384; i += 256) {
        int r = i / 384, c = i - r * 384;
        hid[r * 385 + c] = g_hid[(tok0 + r) * 384 + c];
    }
    __syncthreads();

    float acc[4][4][3];
    #pragma unroll
    for (int rc = 0; rc < 4; ++rc)
        #pragma unroll
        for (int i = 0; i < 4; ++i)
            #pragma unroll
            for (int j = 0; j < 3; ++j) acc[rc][i][j] = 0.f;

    #pragma unroll 2
    for (int k = 0; k < 384; ++k) {
        const float* wk = f2w + k * 96 + lane;
        float w0 = __ldg(wk), w1 = __ldg(wk + 32), w2 = __ldg(wk + 64);
        #pragma unroll
        for (int rc = 0; rc < 4; ++rc) {
            const float* hr = hid + (warp * 16 + rc * 4) * 385 + k;
            float a0 = hr[0], a1 = hr[385], a2 = hr[770], a3 = hr[1155];
            acc[rc][0][0] += a0 * w0; acc[rc][0][1] += a0 * w1; acc[rc][0][2] += a0 * w2;
            acc[rc][1][0] += a1 * w0; acc[rc][1][1] += a1 * w1; acc[rc][1][2] += a1 * w2;
            acc[rc][2][0] += a2 * w0; acc[rc][2][1] += a2 * w1; acc[rc][2][2] += a2 * w2;
            acc[rc][3][0] += a3 * w0; acc[rc][3][1] += a3 * w1; acc[rc][3][2] += a3 * w2;
        }
    }

    float fb0 = f2b[lane], fb1 = f2b[lane + 32], fb2 = f2b[lane + 64];
    #pragma unroll
    for (int rc = 0; rc < 4; ++rc) {
        #pragma unroll
        for (int i = 0; i < 4; ++i) {
            int row = tok0 + warp * 16 + rc * 4 + i;
            int base = row * 96;
            out[base + lane]      = g_x2[base + lane]      + acc[rc][i][0] + fb0;
            out[base + lane + 32] = g_x2[base + lane + 32] + acc[rc][i][1] + fb1;
            out[base + lane + 64] = g_x2[base + lane + 64] + acc[rc][i][2] + fb2;
        }
    }
}

// ---------------- launch ----------------
static const int SM_QKV  = (96 * 288 + 104 * 97 + 288) * 4 + 98 * 4;   // 152488
static const int SM_ATT  = (104 * 25 * 3 + 104 * 105) * 4;             // 74880
static const int SM_PROJ = (96 * 96 + 104 * 97 + 96) * 4 + 98 * 4;     // 77992
static const int SM_M1   = (96 * 384 + 64 * 97 + 384) * 4;             // 173824
static const int SM_M2   = (128 * 385) * 4;                            // 197120

extern "C" void kernel_launch(void* const* d_in, const int* in_sizes, int n_in,
                              void* d_out, int out_size) {
    const float* x    = (const float*)d_in[0];
    const float* mask = (const float*)d_in[1];
    const float* n1g  = (const float*)d_in[2];
    const float* n1b  = (const float*)d_in[3];
    const float* qkvw = (const float*)d_in[4];
    const float* qkvb = (const float*)d_in[5];
    const float* rpb  = (const float*)d_in[6];
    const float* pw   = (const float*)d_in[7];
    const float* pb   = (const float*)d_in[8];
    const float* n2g  = (const float*)d_in[9];
    const float* n2b  = (const float*)d_in[10];
    const float* f1w  = (const float*)d_in[11];
    const float* f1b  = (const float*)d_in[12];
    const float* f2w  = (const float*)d_in[13];
    const float* f2b  = (const float*)d_in[14];
    float* out = (float*)d_out;

    cudaFuncSetAttribute(k_qkv,  cudaFuncAttributeMaxDynamicSharedMemorySize, SM_QKV);
    cudaFuncSetAttribute(k_attn, cudaFuncAttributeMaxDynamicSharedMemorySize, SM_ATT);
    cudaFuncSetAttribute(k_proj, cudaFuncAttributeMaxDynamicSharedMemorySize, SM_PROJ);
    cudaFuncSetAttribute(k_mlp1, cudaFuncAttributeMaxDynamicSharedMemorySize, SM_M1);
    cudaFuncSetAttribute(k_mlp2, cudaFuncAttributeMaxDynamicSharedMemorySize, SM_M2);

    k_bias<<<98, 128>>>(rpb);
    k_qkv<<<2048, 256, SM_QKV>>>(x, n1g, n1b, qkvw, qkvb);
    k_attn<<<dim3(2048, 4), 256, SM_ATT>>>(mask);
    k_proj<<<2048, 256, SM_PROJ>>>(x, pw, pb);
    k_mlp1<<<3136, 256, SM_M1>>>(n2g, n2b, f1w, f1b);
    k_mlp2<<<1568, 256, SM_M2>>>(f2w, f2b, out);
}

// round 2
// speedup vs baseline: 1.3973x; 1.3973x over previous
#include <cuda_runtime.h>
#include <math.h>

#define DEV_INLINE __device__ __forceinline__

// ---------------- static scratch (allocation-free rule) ----------------
__device__ float g_x2[200704 * 96];           // x + attn branch (spatial layout)
__device__ float g_bias[4 * 98 * 98];         // rel-pos bias table per head

// window token (B_, i) -> spatial element base offset (token*96), including the
// shifted-window roll (same mapping for gather in and scatter out).
DEV_INLINE int spat_base(int B_, int i) {
    int b = B_ >> 8, rem = B_ & 255;
    int wd = rem >> 6, wh = (rem >> 3) & 7, ww = rem & 7;
    int td = i / 49, r = i - td * 49;
    int th = r / 7, tw = r - th * 7;
    int d = (wd * 2 + td + 1) & 7;
    int hh = wh * 7 + th + 3; if (hh >= 56) hh -= 56;
    int w2 = ww * 7 + tw + 3; if (w2 >= 56) w2 -= 56;
    return (((b * 8 + d) * 56 + hh) * 56 + w2) * 96;
}

DEV_INLINE float warp_sum(float v) {
    #pragma unroll
    for (int o = 16; o; o >>= 1) v += __shfl_xor_sync(0xffffffffu, v, o);
    return v;
}
DEV_INLINE float warp_max(float v) {
    #pragma unroll
    for (int o = 16; o; o >>= 1) v = fmaxf(v, __shfl_xor_sync(0xffffffffu, v, o));
    return v;
}

// ---------------- kernel 0: relative-position bias table ----------------
__global__ void k_bias(const float* __restrict__ rpb) {
    int i = blockIdx.x;        // 0..97
    int j = threadIdx.x;       // 0..127
    if (j >= 98) return;
    int di = i / 49, ri = i - di * 49, hi = ri / 7, wi = ri - hi * 7;
    int dj = j / 49, rj = j - dj * 49, hj = rj / 7, wj = rj - hj * 7;
    int r = (di - dj + 1) * 169 + (hi - hj + 6) * 13 + (wi - wj + 6);
    #pragma unroll
    for (int h = 0; h < 4; ++h)
        g_bias[h * 9604 + i * 98 + j] = rpb[r * 4 + h];
}

// ---------------- fused window kernel ----------------
// LN1 + roll/partition + QKV + 4x(scores+softmax+PV) + proj + residual scatter.
// One block per window (2048 blocks), 512 threads.
// SMEM floats: xt 104*97 | qbuf/kbuf/vbuf 4*104*25 each | s 104*105 | bb 288 | ro 98 ints
#define XT_OFF   0
#define QB_OFF   10088
#define KB_OFF   20488
#define VB_OFF   30888
#define S_OFF    41288
#define BB_OFF   52208
#define RO_OFF   52496
#define WIN_SMEM ((52496 + 98) * 4)

__global__ __launch_bounds__(512, 1) void k_win(const float* __restrict__ x,
                                                const float* __restrict__ mask,
                                                const float* __restrict__ n1g,
                                                const float* __restrict__ n1b,
                                                const float* __restrict__ qw,
                                                const float* __restrict__ qb,
                                                const float* __restrict__ pw,
                                                const float* __restrict__ pb) {
    extern __shared__ float sm[];
    float* xt = sm + XT_OFF;
    float* qbuf = sm + QB_OFF;
    float* kbuf = sm + KB_OFF;
    float* vbuf = sm + VB_OFF;
    float* s = sm + S_OFF;
    float* bb = sm + BB_OFF;
    int* ro = (int*)(sm + RO_OFF);
    const int tid = threadIdx.x, B_ = blockIdx.x;
    const int warp = tid >> 5, lane = tid & 31;

    // ---- phase 0: indices, gather x, qkv bias ----
    if (tid < 98) ro[tid] = spat_base(B_, tid);
    if (tid < 288) bb[tid] = qb[tid];
    __syncthreads();
    for (int i = tid; i < 104 * 96; i += 512) {
        int r = i / 96, c = i - r * 96;
        xt[r * 97 + c] = (r < 98) ? x[ro[r] + c] : 0.f;
    }
    __syncthreads();

    // ---- phase 1: LayerNorm (one warp per token) ----
    {
        float g0 = n1g[lane], g1 = n1g[lane + 32], g2 = n1g[lane + 64];
        float b0 = n1b[lane], b1 = n1b[lane + 32], b2 = n1b[lane + 64];
        for (int t = warp; t < 98; t += 16) {
            float v0 = xt[t * 97 + lane], v1 = xt[t * 97 + lane + 32], v2 = xt[t * 97 + lane + 64];
            float mean = warp_sum(v0 + v1 + v2) * (1.f / 96.f);
            float d0 = v0 - mean, d1 = v1 - mean, d2 = v2 - mean;
            float var = warp_sum(d0 * d0 + d1 * d1 + d2 * d2) * (1.f / 96.f);
            float rstd = rsqrtf(var + 1e-5f);
            xt[t * 97 + lane]      = d0 * rstd * g0 + b0;
            xt[t * 97 + lane + 32] = d1 * rstd * g1 + b1;
            xt[t * 97 + lane + 64] = d2 * rstd * g2 + b2;
        }
    }

    // ---- phase 2: QKV GEMM (104x288), weights staged through s in 3 chunks ----
    {
        float acc[2][4][9];
        #pragma unroll
        for (int p = 0; p < 2; ++p)
            #pragma unroll
            for (int i = 0; i < 4; ++i)
                #pragma unroll
                for (int j = 0; j < 9; ++j) acc[p][i][j] = 0.f;

        for (int c = 0; c < 3; ++c) {
            __syncthreads();
            for (int idx = tid; idx < 32 * 288; idx += 512) s[idx] = qw[c * 9216 + idx];
            __syncthreads();
            #pragma unroll
            for (int p = 0; p < 2; ++p) {
                int r0 = p * 64 + warp * 4;
                if (r0 >= 104) continue;
                const float* xr = xt + r0 * 97 + c * 32;
                #pragma unroll 4
                for (int kk = 0; kk < 32; ++kk) {
                    float a0 = xr[kk], a1 = xr[97 + kk], a2 = xr[194 + kk], a3 = xr[291 + kk];
                    const float* wk = s + kk * 288 + lane;
                    #pragma unroll
                    for (int j = 0; j < 9; ++j) {
                        float w = wk[32 * j];
                        acc[p][0][j] += a0 * w; acc[p][1][j] += a1 * w;
                        acc[p][2][j] += a2 * w; acc[p][3][j] += a3 * w;
                    }
                }
            }
        }
        __syncthreads();
        // scatter q/k/v into per-head smem buffers
        #pragma unroll
        for (int p = 0; p < 2; ++p) {
            int r0 = p * 64 + warp * 4;
            #pragma unroll
            for (int i = 0; i < 4; ++i) {
                int row = r0 + i;
                if (row >= 98) continue;
                #pragma unroll
                for (int j = 0; j < 9; ++j) {
                    int col = lane + 32 * j;
                    float v = acc[p][i][j] + bb[col];
                    int which = col / 96;
                    int cc = col - which * 96;
                    int head = cc / 24;
                    int dd = cc - head * 24;
                    int off = head * 2600 + row * 25 + dd;
                    if (which == 0)      qbuf[off] = v * 0.20412414523193154f; // 1/sqrt(24)
                    else if (which == 1) kbuf[off] = v;
                    else                 vbuf[off] = v;
                }
            }
        }
    }

    // ---- phase 3: per-head attention ----
    const float* mk = mask + (B_ & 255) * 9604;
    for (int h = 0; h < 4; ++h) {
        const float* bi = g_bias + h * 9604;
        const float* qh = qbuf + h * 2600;
        const float* kh = kbuf + h * 2600;
        const float* vh = vbuf + h * 2600;
        __syncthreads();   // s reuse / prior-head PV done

        // scores 98x98 + bias + mask
        #pragma unroll
        for (int t = 0; t < 2; ++t) {
            int r0 = t * 64 + warp * 4;
            if (r0 >= 104) continue;
            float acc[4][4];
            #pragma unroll
            for (int i = 0; i < 4; ++i)
                #pragma unroll
                for (int j = 0; j < 4; ++j) acc[i][j] = 0.f;
            const float* qr = qh + r0 * 25;
            #pragma unroll
            for (int k = 0; k < 24; ++k) {
                float a0 = qr[k], a1 = qr[25 + k], a2 = qr[50 + k], a3 = qr[75 + k];
                #pragma unroll
                for (int j = 0; j < 4; ++j) {
                    int col = lane + 32 * j;
                    float kk = (col < 104) ? kh[col * 25 + k] : 0.f;
                    acc[0][j] += a0 * kk; acc[1][j] += a1 * kk;
                    acc[2][j] += a2 * kk; acc[3][j] += a3 * kk;
                }
            }
            #pragma unroll
            for (int i = 0; i < 4; ++i) {
                int row = r0 + i;
                if (row >= 98) continue;
                #pragma unroll
                for (int j = 0; j < 4; ++j) {
                    int col = lane + 32 * j;
                    if (col < 98)
                        s[row * 105 + col] = acc[i][j] + bi[row * 98 + col] + mk[row * 98 + col];
                }
            }
        }
        __syncthreads();

        // softmax, one warp per row
        for (int i = warp; i < 98; i += 16) {
            float mx = -1e30f;
            for (int j = lane; j < 98; j += 32) mx = fmaxf(mx, s[i * 105 + j]);
            mx = warp_max(mx);
            float sum = 0.f;
            for (int j = lane; j < 98; j += 32) {
                float e = __expf(s[i * 105 + j] - mx);
                s[i * 105 + j] = e;
                sum += e;
            }
            sum = warp_sum(sum);
            float inv = 1.f / sum;
            for (int j = lane; j < 98; j += 32) s[i * 105 + j] *= inv;
        }
        __syncthreads();

        // PV: write attention output over this head's q region
        #pragma unroll
        for (int t = 0; t < 2; ++t) {
            int r0 = t * 64 + warp * 4;
            if (r0 >= 98) continue;
            float acc[4] = {0.f, 0.f, 0.f, 0.f};
            if (lane < 24) {
                const float* p0 = s + r0 * 105;
                #pragma unroll 2
                for (int j = 0; j < 98; ++j) {
                    float vv = vh[j * 25 + lane];
                    acc[0] += p0[j] * vv;
                    acc[1] += p0[105 + j] * vv;
                    acc[2] += p0[210 + j] * vv;
                    acc[3] += p0[315 + j] * vv;
                }
            }
            if (lane < 24) {
                #pragma unroll
                for (int i = 0; i < 4; ++i) {
                    int row = r0 + i;
                    if (row < 98)
                        qbuf[h * 2600 + row * 25 + lane] = acc[i];
                }
            }
        }
    }

    // ---- phase 4: proj + residual + scatter ----
    __syncthreads();
    for (int idx = tid; idx < 96 * 96; idx += 512) s[idx] = pw[idx];
    if (tid < 96) bb[tid] = pb[tid];
    __syncthreads();

    #pragma unroll
    for (int t = 0; t < 2; ++t) {
        int r0 = t * 64 + warp * 4;
        if (r0 >= 98) continue;
        float acc[4][3];
        #pragma unroll
        for (int i = 0; i < 4; ++i)
            #pragma unroll
            for (int j = 0; j < 3; ++j) acc[i][j] = 0.f;
        #pragma unroll
        for (int hd = 0; hd < 4; ++hd) {
            const float* ab = qbuf + hd * 2600 + r0 * 25;
            #pragma unroll 4
            for (int kk = 0; kk < 24; ++kk) {
                float a0 = ab[kk], a1 = ab[25 + kk], a2 = ab[50 + kk], a3 = ab[75 + kk];
                const float* wk = s + (hd * 24 + kk) * 96 + lane;
                #pragma unroll
                for (int j = 0; j < 3; ++j) {
                    float w = wk[32 * j];
                    acc[0][j] += a0 * w; acc[1][j] += a1 * w;
                    acc[2][j] += a2 * w; acc[3][j] += a3 * w;
                }
            }
        }
        #pragma unroll
        for (int i = 0; i < 4; ++i) {
            int row = r0 + i;
            if (row >= 98) continue;
            int base = ro[row];
            #pragma unroll
            for (int j = 0; j < 3; ++j) {
                int col = lane + 32 * j;
                g_x2[base + col] = x[base + col] + acc[i][j] + bb[col];
            }
        }
    }
}

// ---------------- fused MLP kernel ----------------
// LN2 + fc1 + GELU + fc2 + residual.  64 tokens per block, 512 threads.
// SMEM floats: xt 64*97 | hid 64*385 | wbuf 32*384 (=128*96) | bbuf 384
#define M_XT   0
#define M_HID  6208
#define M_WB   30848
#define M_BB   43136
#define MLP_SMEM ((43136 + 384) * 4)

__global__ __launch_bounds__(512, 1) void k_mlp(const float* __restrict__ n2g,
                                                const float* __restrict__ n2b,
                                                const float* __restrict__ f1w,
                                                const float* __restrict__ f1b,
                                                const float* __restrict__ f2w,
                                                const float* __restrict__ f2b,
                                                float* __restrict__ out) {
    extern __shared__ float sm[];
    float* xt = sm + M_XT;
    float* hid = sm + M_HID;
    float* wbuf = sm + M_WB;
    float* bbuf = sm + M_BB;
    const int tid = threadIdx.x, warp = tid >> 5, lane = tid & 31;
    const int tok0 = blockIdx.x * 64;

    if (tid < 384) bbuf[tid] = f1b[tid];
    for (int i = tid; i < 64 * 96; i += 512) {
        int r = i / 96, c = i - r * 96;
        xt[r * 97 + c] = g_x2[(tok0 + r) * 96 + c];
    }
    __syncthreads();

    // LN2
    {
        float g0 = n2g[lane], g1 = n2g[lane + 32], g2 = n2g[lane + 64];
        float b0 = n2b[lane], b1 = n2b[lane + 32], b2 = n2b[lane + 64];
        for (int t = warp; t < 64; t += 16) {
            float v0 = xt[t * 97 + lane], v1 = xt[t * 97 + lane + 32], v2 = xt[t * 97 + lane + 64];
            float mean = warp_sum(v0 + v1 + v2) * (1.f / 96.f);
            float d0 = v0 - mean, d1 = v1 - mean, d2 = v2 - mean;
            float var = warp_sum(d0 * d0 + d1 * d1 + d2 * d2) * (1.f / 96.f);
            float rstd = rsqrtf(var + 1e-5f);
            xt[t * 97 + lane]      = d0 * rstd * g0 + b0;
            xt[t * 97 + lane + 32] = d1 * rstd * g1 + b1;
            xt[t * 97 + lane + 64] = d2 * rstd * g2 + b2;
        }
    }

    // fc1 (64x384, K=96) with weight chunks of 32 k-rows
    {
        float acc[4][12];
        #pragma unroll
        for (int i = 0; i < 4; ++i)
            #pragma unroll
            for (int j = 0; j < 12; ++j) acc[i][j] = 0.f;
        int r0 = warp * 4;
        for (int c = 0; c < 3; ++c) {
            __syncthreads();
            for (int idx = tid; idx < 32 * 384; idx += 512) wbuf[idx] = f1w[c * 12288 + idx];
            __syncthreads();
            const float* xr = xt + r0 * 97 + c * 32;
            #pragma unroll 4
            for (int kk = 0; kk < 32; ++kk) {
                float a0 = xr[kk], a1 = xr[97 + kk], a2 = xr[194 + kk], a3 = xr[291 + kk];
                const float* wk = wbuf + kk * 384 + lane;
                #pragma unroll
                for (int j = 0; j < 12; ++j) {
                    float w = wk[32 * j];
                    acc[0][j] += a0 * w; acc[1][j] += a1 * w;
                    acc[2][j] += a2 * w; acc[3][j] += a3 * w;
                }
            }
        }
        // bias + exact GELU -> hid
        #pragma unroll
        for (int i = 0; i < 4; ++i) {
            #pragma unroll
            for (int j = 0; j < 12; ++j) {
                int col = lane + 32 * j;
                float u = acc[i][j] + bbuf[col];
                hid[(r0 + i) * 385 + col] = 0.5f * u * (1.f + erff(u * 0.70710678118654752f));
            }
        }
    }

    // fc2 (64x96, K=384) with weight chunks of 128 k-rows
    {
        float acc[4][3];
        #pragma unroll
        for (int i = 0; i < 4; ++i)
            #pragma unroll
            for (int j = 0; j < 3; ++j) acc[i][j] = 0.f;
        int r0 = warp * 4;
        for (int c = 0; c < 3; ++c) {
            __syncthreads();
            for (int idx = tid; idx < 128 * 96; idx += 512) wbuf[idx] = f2w[c * 12288 + idx];
            __syncthreads();
            const float* hr = hid + r0 * 385 + c * 128;
            #pragma unroll 4
            for (int kk = 0; kk < 128; ++kk) {
                float a0 = hr[kk], a1 = hr[385 + kk], a2 = hr[770 + kk], a3 = hr[1155 + kk];
                const float* wk = wbuf + kk * 96 + lane;
                #pragma unroll
                for (int j = 0; j < 3; ++j) {
                    float w = wk[32 * j];
                    acc[0][j] += a0 * w; acc[1][j] += a1 * w;
                    acc[2][j] += a2 * w; acc[3][j] += a3 * w;
                }
            }
        }
        float fb0 = f2b[lane], fb1 = f2b[lane + 32], fb2 = f2b[lane + 64];
        #pragma unroll
        for (int i = 0; i < 4; ++i) {
            int row = tok0 + r0 + i;
            int base = row * 96;
            out[base + lane]      = g_x2[base + lane]      + acc[i][0] + fb0;
            out[base + lane + 32] = g_x2[base + lane + 32] + acc[i][1] + fb1;
            out[base + lane + 64] = g_x2[base + lane + 64] + acc[i][2] + fb2;
        }
    }
}

extern "C" void kernel_launch(void* const* d_in, const int* in_sizes, int n_in,
                              void* d_out, int out_size) {
    const float* x    = (const float*)d_in[0];
    const float* mask = (const float*)d_in[1];
    const float* n1g  = (const float*)d_in[2];
    const float* n1b  = (const float*)d_in[3];
    const float* qkvw = (const float*)d_in[4];
    const float* qkvb = (const float*)d_in[5];
    const float* rpb  = (const float*)d_in[6];
    const float* pw   = (const float*)d_in[7];
    const float* pb   = (const float*)d_in[8];
    const float* n2g  = (const float*)d_in[9];
    const float* n2b  = (const float*)d_in[10];
    const float* f1w  = (const float*)d_in[11];
    const float* f1b  = (const float*)d_in[12];
    const float* f2w  = (const float*)d_in[13];
    const float* f2b  = (const float*)d_in[14];
    float* out = (float*)d_out;

    cudaFuncSetAttribute(k_win, cudaFuncAttributeMaxDynamicSharedMemorySize, WIN_SMEM);
    cudaFuncSetAttribute(k_mlp, cudaFuncAttributeMaxDynamicSharedMemorySize, MLP_SMEM);

    k_bias<<<98, 128>>>(rpb);
    k_win<<<2048, 512, WIN_SMEM>>>(x, mask, n1g, n1b, qkvw, qkvb, pw, pb);
    k_mlp<<<3136, 512, MLP_SMEM>>>(n2g, n2b, f1w, f1b, f2w, f2b, out);
}

// round 4
// speedup vs baseline: 2.1137x; 1.5127x over previous
#include <cuda_runtime.h>
#include <cuda_bf16.h>
#include <math.h>
#include <stdint.h>

#define DEV_INLINE __device__ __forceinline__

// ---------------- static scratch (allocation-free rule) ----------------
__device__ float g_x2[200704 * 96];                  // x + attn branch
__device__ float g_bias[4 * 98 * 98];                // rel-pos bias table
__device__ __align__(16) uint32_t g_w1t[18432];      // fc1^T bf16 (384 n x 96 k), k-contig
__device__ __align__(16) uint32_t g_w2t[18432];      // fc2^T bf16 (96 n x 384 k), k-contig

DEV_INLINE float warp_sum(float v) {
    #pragma unroll
    for (int o = 16; o; o >>= 1) v += __shfl_xor_sync(0xffffffffu, v, o);
    return v;
}
DEV_INLINE float warp_max(float v) {
    #pragma unroll
    for (int o = 16; o; o >>= 1) v = fmaxf(v, __shfl_xor_sync(0xffffffffu, v, o));
    return v;
}
DEV_INLINE uint32_t pack_bf(float a, float b) {
    uint32_t lo = __bfloat16_as_ushort(__float2bfloat16(a));
    uint32_t hi = __bfloat16_as_ushort(__float2bfloat16(b));
    return (hi << 16) | lo;
}
DEV_INLINE void mma16816(float* d, const uint32_t* a, const uint32_t* b) {
    asm volatile("mma.sync.aligned.m16n8k16.row.col.f32.bf16.bf16.f32 "
        "{%0,%1,%2,%3}, {%4,%5,%6,%7}, {%8,%9}, {%0,%1,%2,%3};"
        : "+f"(d[0]), "+f"(d[1]), "+f"(d[2]), "+f"(d[3])
        : "r"(a[0]), "r"(a[1]), "r"(a[2]), "r"(a[3]), "r"(b[0]), "r"(b[1]));
}

// window token (B_, i) -> spatial element base offset (incl. shifted-window roll)
DEV_INLINE int spat_base(int B_, int i) {
    int b = B_ >> 8, rem = B_ & 255;
    int wd = rem >> 6, wh = (rem >> 3) & 7, ww = rem & 7;
    int td = i / 49, r = i - td * 49;
    int th = r / 7, tw = r - th * 7;
    int d = (wd * 2 + td + 1) & 7;
    int hh = wh * 7 + th + 3; if (hh >= 56) hh -= 56;
    int w2 = ww * 7 + tw + 3; if (w2 >= 56) w2 -= 56;
    return (((b * 8 + d) * 56 + hh) * 56 + w2) * 96;
}

// ---------------- kernel 0: rel-pos bias table ----------------
__global__ void k_bias(const float* __restrict__ rpb) {
    int i = blockIdx.x, j = threadIdx.x;
    if (j >= 98) return;
    int di = i / 49, ri = i - di * 49, hi = ri / 7, wi = ri - hi * 7;
    int dj = j / 49, rj = j - dj * 49, hj = rj / 7, wj = rj - hj * 7;
    int r = (di - dj + 1) * 169 + (hi - hj + 6) * 13 + (wi - wj + 6);
    #pragma unroll
    for (int h = 0; h < 4; ++h)
        g_bias[h * 9604 + i * 98 + j] = rpb[r * 4 + h];
}

// ---------------- kernel: weight transpose to bf16 (N,K) k-contig ----------------
__global__ void k_wprep(const float* __restrict__ f1w, const float* __restrict__ f2w) {
    int g = blockIdx.x * 256 + threadIdx.x;          // 0..36863
    if (g < 18432) {                                 // W1: n<384, j<48 (k pair)
        int n = g / 48, j = g % 48;
        g_w1t[g] = pack_bf(f1w[(2 * j) * 384 + n], f1w[(2 * j + 1) * 384 + n]);
    } else {                                         // W2: n<96, j<192
        int i = g - 18432;
        int n = i / 192, j = i % 192;
        g_w2t[i] = pack_bf(f2w[(2 * j) * 96 + n], f2w[(2 * j + 1) * 96 + n]);
    }
}

// ---------------- fused window kernel (unchanged, passing) ----------------
#define XT_OFF   0
#define QB_OFF   10088
#define KB_OFF   20488
#define VB_OFF   30888
#define S_OFF    41288
#define BB_OFF   52208
#define RO_OFF   52496
#define WIN_SMEM ((52496 + 98) * 4)

__global__ __launch_bounds__(512, 1) void k_win(const float* __restrict__ x,
                                                const float* __restrict__ mask,
                                                const float* __restrict__ n1g,
                                                const float* __restrict__ n1b,
                                                const float* __restrict__ qw,
                                                const float* __restrict__ qb,
                                                const float* __restrict__ pw,
                                                const float* __restrict__ pb) {
    extern __shared__ float sm[];
    float* xt = sm + XT_OFF;
    float* qbuf = sm + QB_OFF;
    float* kbuf = sm + KB_OFF;
    float* vbuf = sm + VB_OFF;
    float* s = sm + S_OFF;
    float* bb = sm + BB_OFF;
    int* ro = (int*)(sm + RO_OFF);
    const int tid = threadIdx.x, B_ = blockIdx.x;
    const int warp = tid >> 5, lane = tid & 31;

    if (tid < 98) ro[tid] = spat_base(B_, tid);
    if (tid < 288) bb[tid] = qb[tid];
    __syncthreads();
    for (int i = tid; i < 104 * 96; i += 512) {
        int r = i / 96, c = i - r * 96;
        xt[r * 97 + c] = (r < 98) ? x[ro[r] + c] : 0.f;
    }
    __syncthreads();

    {
        float g0 = n1g[lane], g1 = n1g[lane + 32], g2 = n1g[lane + 64];
        float b0 = n1b[lane], b1 = n1b[lane + 32], b2 = n1b[lane + 64];
        for (int t = warp; t < 98; t += 16) {
            float v0 = xt[t * 97 + lane], v1 = xt[t * 97 + lane + 32], v2 = xt[t * 97 + lane + 64];
            float mean = warp_sum(v0 + v1 + v2) * (1.f / 96.f);
            float d0 = v0 - mean, d1 = v1 - mean, d2 = v2 - mean;
            float var = warp_sum(d0 * d0 + d1 * d1 + d2 * d2) * (1.f / 96.f);
            float rstd = rsqrtf(var + 1e-5f);
            xt[t * 97 + lane]      = d0 * rstd * g0 + b0;
            xt[t * 97 + lane + 32] = d1 * rstd * g1 + b1;
            xt[t * 97 + lane + 64] = d2 * rstd * g2 + b2;
        }
    }

    {
        float acc[2][4][9];
        #pragma unroll
        for (int p = 0; p < 2; ++p)
            #pragma unroll
            for (int i = 0; i < 4; ++i)
                #pragma unroll
                for (int j = 0; j < 9; ++j) acc[p][i][j] = 0.f;

        for (int c = 0; c < 3; ++c) {
            __syncthreads();
            for (int idx = tid; idx < 32 * 288; idx += 512) s[idx] = qw[c * 9216 + idx];
            __syncthreads();
            #pragma unroll
            for (int p = 0; p < 2; ++p) {
                int r0 = p * 64 + warp * 4;
                if (r0 >= 104) continue;
                const float* xr = xt + r0 * 97 + c * 32;
                #pragma unroll 4
                for (int kk = 0; kk < 32; ++kk) {
                    float a0 = xr[kk], a1 = xr[97 + kk], a2 = xr[194 + kk], a3 = xr[291 + kk];
                    const float* wk = s + kk * 288 + lane;
                    #pragma unroll
                    for (int j = 0; j < 9; ++j) {
                        float w = wk[32 * j];
                        acc[p][0][j] += a0 * w; acc[p][1][j] += a1 * w;
                        acc[p][2][j] += a2 * w; acc[p][3][j] += a3 * w;
                    }
                }
            }
        }
        __syncthreads();
        #pragma unroll
        for (int p = 0; p < 2; ++p) {
            int r0 = p * 64 + warp * 4;
            #pragma unroll
            for (int i = 0; i < 4; ++i) {
                int row = r0 + i;
                if (row >= 98) continue;
                #pragma unroll
                for (int j = 0; j < 9; ++j) {
                    int col = lane + 32 * j;
                    float v = acc[p][i][j] + bb[col];
                    int which = col / 96;
                    int cc = col - which * 96;
                    int head = cc / 24;
                    int dd = cc - head * 24;
                    int off = head * 2600 + row * 25 + dd;
                    if (which == 0)      qbuf[off] = v * 0.20412414523193154f;
                    else if (which == 1) kbuf[off] = v;
                    else                 vbuf[off] = v;
                }
            }
        }
    }

    const float* mk = mask + (B_ & 255) * 9604;
    for (int h = 0; h < 4; ++h) {
        const float* bi = g_bias + h * 9604;
        const float* qh = qbuf + h * 2600;
        const float* kh = kbuf + h * 2600;
        const float* vh = vbuf + h * 2600;
        __syncthreads();

        #pragma unroll
        for (int t = 0; t < 2; ++t) {
            int r0 = t * 64 + warp * 4;
            if (r0 >= 104) continue;
            float acc[4][4];
            #pragma unroll
            for (int i = 0; i < 4; ++i)
                #pragma unroll
                for (int j = 0; j < 4; ++j) acc[i][j] = 0.f;
            const float* qr = qh + r0 * 25;
            #pragma unroll
            for (int k = 0; k < 24; ++k) {
                float a0 = qr[k], a1 = qr[25 + k], a2 = qr[50 + k], a3 = qr[75 + k];
                #pragma unroll
                for (int j = 0; j < 4; ++j) {
                    int col = lane + 32 * j;
                    float kk = (col < 104) ? kh[col * 25 + k] : 0.f;
                    acc[0][j] += a0 * kk; acc[1][j] += a1 * kk;
                    acc[2][j] += a2 * kk; acc[3][j] += a3 * kk;
                }
            }
            #pragma unroll
            for (int i = 0; i < 4; ++i) {
                int row = r0 + i;
                if (row >= 98) continue;
                #pragma unroll
                for (int j = 0; j < 4; ++j) {
                    int col = lane + 32 * j;
                    if (col < 98)
                        s[row * 105 + col] = acc[i][j] + bi[row * 98 + col] + mk[row * 98 + col];
                }
            }
        }
        __syncthreads();

        for (int i = warp; i < 98; i += 16) {
            float mx = -1e30f;
            for (int j = lane; j < 98; j += 32) mx = fmaxf(mx, s[i * 105 + j]);
            mx = warp_max(mx);
            float sum = 0.f;
            for (int j = lane; j < 98; j += 32) {
                float e = __expf(s[i * 105 + j] - mx);
                s[i * 105 + j] = e;
                sum += e;
            }
            sum = warp_sum(sum);
            float inv = 1.f / sum;
            for (int j = lane; j < 98; j += 32) s[i * 105 + j] *= inv;
        }
        __syncthreads();

        #pragma unroll
        for (int t = 0; t < 2; ++t) {
            int r0 = t * 64 + warp * 4;
            if (r0 >= 98) continue;
            float acc[4] = {0.f, 0.f, 0.f, 0.f};
            if (lane < 24) {
                const float* p0 = s + r0 * 105;
                #pragma unroll 2
                for (int j = 0; j < 98; ++j) {
                    float vv = vh[j * 25 + lane];
                    acc[0] += p0[j] * vv;
                    acc[1] += p0[105 + j] * vv;
                    acc[2] += p0[210 + j] * vv;
                    acc[3] += p0[315 + j] * vv;
                }
                #pragma unroll
                for (int i = 0; i < 4; ++i) {
                    int row = r0 + i;
                    if (row < 98)
                        qbuf[h * 2600 + row * 25 + lane] = acc[i];
                }
            }
        }
    }

    __syncthreads();
    for (int idx = tid; idx < 96 * 96; idx += 512) s[idx] = pw[idx];
    if (tid < 96) bb[tid] = pb[tid];
    __syncthreads();

    #pragma unroll
    for (int t = 0; t < 2; ++t) {
        int r0 = t * 64 + warp * 4;
        if (r0 >= 98) continue;
        float acc[4][3];
        #pragma unroll
        for (int i = 0; i < 4; ++i)
            #pragma unroll
            for (int j = 0; j < 3; ++j) acc[i][j] = 0.f;
        #pragma unroll
        for (int hd = 0; hd < 4; ++hd) {
            const float* ab = qbuf + hd * 2600 + r0 * 25;
            #pragma unroll 4
            for (int kk = 0; kk < 24; ++kk) {
                float a0 = ab[kk], a1 = ab[25 + kk], a2 = ab[50 + kk], a3 = ab[75 + kk];
                const float* wk = s + (hd * 24 + kk) * 96 + lane;
                #pragma unroll
                for (int j = 0; j < 3; ++j) {
                    float w = wk[32 * j];
                    acc[0][j] += a0 * w; acc[1][j] += a1 * w;
                    acc[2][j] += a2 * w; acc[3][j] += a3 * w;
                }
            }
        }
        #pragma unroll
        for (int i = 0; i < 4; ++i) {
            int row = r0 + i;
            if (row >= 98) continue;
            int base = ro[row];
            #pragma unroll
            for (int j = 0; j < 3; ++j) {
                int col = lane + 32 * j;
                g_x2[base + col] = x[base + col] + acc[i][j] + bb[col];
            }
        }
    }
}

// ---------------- fused MLP via mma.sync bf16 ----------------
// smem bytes: hid[128][196]u32 @0 (100352) | R @100352 (75264) | f1b @175616 | f2b @177152
#define MH_HID  0
#define MH_R    100352
#define MH_A    (MH_R)                 // A bf16 128x104, u32 stride 52 (26624 B)
#define MH_W1   (MH_R + 26624)         // w1 chunk bf16 128x104, u32 stride 52 (26624 B)
#define MH_F1B  175616
#define MH_F2B  177152
#define MH_SMEM 177536

__global__ __launch_bounds__(512, 1) void k_mlpT(const float* __restrict__ n2g,
                                                 const float* __restrict__ n2b,
                                                 const float* __restrict__ f1b,
                                                 const float* __restrict__ f2b,
                                                 float* __restrict__ out) {
    extern __shared__ char smc[];
    uint32_t* hid32 = (uint32_t*)(smc + MH_HID);     // stride 196
    uint32_t* A32   = (uint32_t*)(smc + MH_A);       // stride 52
    uint32_t* w1c32 = (uint32_t*)(smc + MH_W1);      // stride 52
    uint32_t* w2s32 = (uint32_t*)(smc + MH_R);       // stride 196 (after fc1)
    float* obufF    = (float*)(smc + MH_R);          // stride 100 (after fc2)
    float* sf1b     = (float*)(smc + MH_F1B);
    float* sf2b     = (float*)(smc + MH_F2B);

    const int tid = threadIdx.x, wid = tid >> 5, lane = tid & 31;
    const int g = lane >> 2, t = lane & 3;           // mma groupID / tid-in-group
    const int tok0 = blockIdx.x * 128;

    for (int i = tid; i < 384; i += 512) sf1b[i] = f1b[i];
    if (tid < 96) sf2b[tid] = f2b[tid];

    // ---- LN2 -> bf16 A (stride 52 u32) ----
    {
        float g0 = n2g[lane], g1 = n2g[lane + 32], g2 = n2g[lane + 64];
        float b0 = n2b[lane], b1 = n2b[lane + 32], b2 = n2b[lane + 64];
        for (int tr = wid; tr < 128; tr += 16) {
            const float* xr = g_x2 + (tok0 + tr) * 96;
            float v0 = xr[lane], v1 = xr[lane + 32], v2 = xr[lane + 64];
            float mean = warp_sum(v0 + v1 + v2) * (1.f / 96.f);
            float d0 = v0 - mean, d1 = v1 - mean, d2 = v2 - mean;
            float var = warp_sum(d0 * d0 + d1 * d1 + d2 * d2) * (1.f / 96.f);
            float rstd = rsqrtf(var + 1e-5f);
            float y0 = d0 * rstd * g0 + b0;
            float y1 = d1 * rstd * g1 + b1;
            float y2 = d2 * rstd * g2 + b2;
            float o0 = __shfl_xor_sync(0xffffffffu, y0, 1);
            float o1 = __shfl_xor_sync(0xffffffffu, y1, 1);
            float o2 = __shfl_xor_sync(0xffffffffu, y2, 1);
            if ((lane & 1) == 0) {
                A32[tr * 52 + (lane >> 1)]      = pack_bf(y0, o0);
                A32[tr * 52 + (lane >> 1) + 16] = pack_bf(y1, o1);
                A32[tr * 52 + (lane >> 1) + 32] = pack_bf(y2, o2);
            }
        }
    }
    __syncthreads();

    const int mrow = (wid & 7) * 16;
    const int nhalf = wid >> 3;

    // ---- fc1: (128x96)@(96x384), 3 n-chunks of 128 cols ----
    for (int c = 0; c < 3; ++c) {
        for (int i = tid; i < 6144; i += 512) {
            int n = i / 48, j = i - n * 48;
            w1c32[n * 52 + j] = g_w1t[c * 6144 + i];
        }
        __syncthreads();

        float acc[8][4];
        #pragma unroll
        for (int f = 0; f < 8; ++f)
            #pragma unroll
            for (int q = 0; q < 4; ++q) acc[f][q] = 0.f;

        const int n0 = nhalf * 64;
        #pragma unroll
        for (int k = 0; k < 6; ++k) {
            const int k8 = k * 8;
            uint32_t a[4];
            a[0] = A32[(mrow + g) * 52 + k8 + t];
            a[1] = A32[(mrow + g + 8) * 52 + k8 + t];
            a[2] = A32[(mrow + g) * 52 + k8 + t + 4];
            a[3] = A32[(mrow + g + 8) * 52 + k8 + t + 4];
            #pragma unroll
            for (int f = 0; f < 8; ++f) {
                uint32_t b[2];
                b[0] = w1c32[(n0 + f * 8 + g) * 52 + k8 + t];
                b[1] = w1c32[(n0 + f * 8 + g) * 52 + k8 + t + 4];
                mma16816(acc[f], a, b);
            }
        }

        // bias + exact GELU -> bf16 hid
        #pragma unroll
        for (int f = 0; f < 8; ++f) {
            int gcol = c * 128 + n0 + f * 8 + 2 * t;
            float u0 = acc[f][0] + sf1b[gcol];
            float u1 = acc[f][1] + sf1b[gcol + 1];
            float u2 = acc[f][2] + sf1b[gcol];
            float u3 = acc[f][3] + sf1b[gcol + 1];
            float e0 = 0.5f * u0 * (1.f + erff(u0 * 0.70710678118654752f));
            float e1 = 0.5f * u1 * (1.f + erff(u1 * 0.70710678118654752f));
            float e2 = 0.5f * u2 * (1.f + erff(u2 * 0.70710678118654752f));
            float e3 = 0.5f * u3 * (1.f + erff(u3 * 0.70710678118654752f));
            int hc = (gcol >> 1);
            hid32[(mrow + g) * 196 + hc]     = pack_bf(e0, e1);
            hid32[(mrow + g + 8) * 196 + hc] = pack_bf(e2, e3);
        }
        __syncthreads();   // before overwriting w1 chunk (or A region by W2)
    }

    // ---- W2 copy (overwrites A + w1 chunk) ----
    for (int i = tid; i < 18432; i += 512) {
        int n = i / 192, j = i - n * 192;
        w2s32[n * 196 + j] = g_w2t[i];
    }
    __syncthreads();

    // ---- fc2: (128x384)@(384x96) ----
    {
        float acc[6][4];
        #pragma unroll
        for (int f = 0; f < 6; ++f)
            #pragma unroll
            for (int q = 0; q < 4; ++q) acc[f][q] = 0.f;

        const int n0 = nhalf * 48;
        #pragma unroll 4
        for (int k = 0; k < 24; ++k) {
            const int k8 = k * 8;
            uint32_t a[4];
            a[0] = hid32[(mrow + g) * 196 + k8 + t];
            a[1] = hid32[(mrow + g + 8) * 196 + k8 + t];
            a[2] = hid32[(mrow + g) * 196 + k8 + t + 4];
            a[3] = hid32[(mrow + g + 8) * 196 + k8 + t + 4];
            #pragma unroll
            for (int f = 0; f < 6; ++f) {
                uint32_t b[2];
                b[0] = w2s32[(n0 + f * 8 + g) * 196 + k8 + t];
                b[1] = w2s32[(n0 + f * 8 + g) * 196 + k8 + t + 4];
                mma16816(acc[f], a, b);
            }
        }
        __syncthreads();   // all B reads done before obuf overwrites W2

        #pragma unroll
        for (int f = 0; f < 6; ++f) {
            int col = n0 + f * 8 + 2 * t;
            *(float2*)(obufF + (mrow + g) * 100 + col)     = make_float2(acc[f][0], acc[f][1]);
            *(float2*)(obufF + (mrow + g + 8) * 100 + col) = make_float2(acc[f][2], acc[f][3]);
        }
    }
    __syncthreads();

    // ---- coalesced writeout: out = x2 + fc2 + bias ----
    {
        const float* x2t = g_x2 + tok0 * 96;
        float* outt = out + tok0 * 96;
        for (int i = tid; i < 12288; i += 512) {
            int row = i / 96, col = i - row * 96;
            outt[i] = obufF[row * 100 + col] + sf2b[col] + x2t[i];
        }
    }
}

// ---------------- launch ----------------
extern "C" void kernel_launch(void* const* d_in, const int* in_sizes, int n_in,
                              void* d_out, int out_size) {
    const float* x    = (const float*)d_in[0];
    const float* mask = (const float*)d_in[1];
    const float* n1g  = (const float*)d_in[2];
    const float* n1b  = (const float*)d_in[3];
    const float* qkvw = (const float*)d_in[4];
    const float* qkvb = (const float*)d_in[5];
    const float* rpb  = (const float*)d_in[6];
    const float* pw   = (const float*)d_in[7];
    const float* pb   = (const float*)d_in[8];
    const float* n2g  = (const float*)d_in[9];
    const float* n2b  = (const float*)d_in[10];
    const float* f1w  = (const float*)d_in[11];
    const float* f1b  = (const float*)d_in[12];
    const float* f2w  = (const float*)d_in[13];
    const float* f2b  = (const float*)d_in[14];
    float* out = (float*)d_out;

    cudaFuncSetAttribute(k_win,  cudaFuncAttributeMaxDynamicSharedMemorySize, WIN_SMEM);
    cudaFuncSetAttribute(k_mlpT, cudaFuncAttributeMaxDynamicSharedMemorySize, MH_SMEM);

    k_bias<<<98, 128>>>(rpb);
    k_wprep<<<144, 256>>>(f1w, f2w);
    k_win<<<2048, 512, WIN_SMEM>>>(x, mask, n1g, n1b, qkvw, qkvb, pw, pb);
    k_mlpT<<<1568, 512, MH_SMEM>>>(n2g, n2b, f1b, f2b, out);
}

// round 7
// speedup vs baseline: 3.4546x; 1.6344x over previous
#include <cuda_runtime.h>
#include <cuda_bf16.h>
#include <math.h>
#include <stdint.h>

#define DEV_INLINE __device__ __forceinline__

// ---------------- static scratch (allocation-free rule) ----------------
__device__ float g_x2[200704 * 96];                  // x + attn branch
__device__ float g_bias[4 * 98 * 98];                // rel-pos bias table
__device__ __align__(16) uint32_t g_w1t[18432];      // fc1^T bf16 (384 n x 96 k)
__device__ __align__(16) uint32_t g_w2t[18432];      // fc2^T bf16 (96 n x 384 k)
__device__ __align__(16) uint32_t g_qkvt[13824];     // qkv_w^T bf16 (288 n x 96 k)
__device__ __align__(16) uint32_t g_pwt[4608];       // proj_w^T bf16 (96 n x 96 k)

DEV_INLINE float warp_sum(float v) {
    #pragma unroll
    for (int o = 16; o; o >>= 1) v += __shfl_xor_sync(0xffffffffu, v, o);
    return v;
}
DEV_INLINE float warp_max(float v) {
    #pragma unroll
    for (int o = 16; o; o >>= 1) v = fmaxf(v, __shfl_xor_sync(0xffffffffu, v, o));
    return v;
}
DEV_INLINE uint32_t pack_bf(float a, float b) {
    uint32_t lo = __bfloat16_as_ushort(__float2bfloat16(a));
    uint32_t hi = __bfloat16_as_ushort(__float2bfloat16(b));
    return (hi << 16) | lo;
}
DEV_INLINE void mma16816(float* d, const uint32_t* a, const uint32_t* b) {
    asm volatile("mma.sync.aligned.m16n8k16.row.col.f32.bf16.bf16.f32 "
        "{%0,%1,%2,%3}, {%4,%5,%6,%7}, {%8,%9}, {%0,%1,%2,%3};"
        : "+f"(d[0]), "+f"(d[1]), "+f"(d[2]), "+f"(d[3])
        : "r"(a[0]), "r"(a[1]), "r"(a[2]), "r"(a[3]), "r"(b[0]), "r"(b[1]));
}

DEV_INLINE int spat_base(int B_, int i) {
    int b = B_ >> 8, rem = B_ & 255;
    int wd = rem >> 6, wh = (rem >> 3) & 7, ww = rem & 7;
    int td = i / 49, r = i - td * 49;
    int th = r / 7, tw = r - th * 7;
    int d = (wd * 2 + td + 1) & 7;
    int hh = wh * 7 + th + 3; if (hh >= 56) hh -= 56;
    int w2 = ww * 7 + tw + 3; if (w2 >= 56) w2 -= 56;
    return (((b * 8 + d) * 56 + hh) * 56 + w2) * 96;
}

// ---------------- kernel 0: rel-pos bias table ----------------
__global__ void k_bias(const float* __restrict__ rpb) {
    int i = blockIdx.x, j = threadIdx.x;
    if (j >= 98) return;
    int di = i / 49, ri = i - di * 49, hi = ri / 7, wi = ri - hi * 7;
    int dj = j / 49, rj = j - dj * 49, hj = rj / 7, wj = rj - hj * 7;
    int r = (di - dj + 1) * 169 + (hi - hj + 6) * 13 + (wi - wj + 6);
    #pragma unroll
    for (int h = 0; h < 4; ++h)
        g_bias[h * 9604 + i * 98 + j] = rpb[r * 4 + h];
}

// ---------------- kernel: weight transposes to bf16 (N,K) k-contig ----------------
__global__ void k_wprep(const float* __restrict__ f1w, const float* __restrict__ f2w,
                        const float* __restrict__ qw, const float* __restrict__ pw) {
    int g = blockIdx.x * 256 + threadIdx.x;          // 0..55295
    if (g < 18432) {
        int n = g / 48, j = g % 48;
        g_w1t[g] = pack_bf(f1w[(2 * j) * 384 + n], f1w[(2 * j + 1) * 384 + n]);
    } else if (g < 36864) {
        int i = g - 18432;
        int n = i / 192, j = i % 192;
        g_w2t[i] = pack_bf(f2w[(2 * j) * 96 + n], f2w[(2 * j + 1) * 96 + n]);
    } else if (g < 50688) {
        int i = g - 36864;
        int n = i / 48, j = i % 48;
        g_qkvt[i] = pack_bf(qw[(2 * j) * 288 + n], qw[(2 * j + 1) * 288 + n]);
    } else if (g < 55296) {
        int i = g - 50688;
        int n = i / 48, j = i % 48;
        g_pwt[i] = pack_bf(pw[(2 * j) * 96 + n], pw[(2 * j + 1) * 96 + n]);
    }
}

// ---------------- fused window kernel via mma.sync bf16 ----------------
// u32 offsets in dynamic smem:
#define Q_OFF   0          // 4 heads x 112 x 20
#define K_OFF   8960
#define V_OFF   17920      // 4 heads x 32 dims x 60 (token pairs)
#define AT_OFF  25600      // 112 x 52
#define RO_OFF  31424      // 112 ints
#define B3_OFF  31536      // 288 floats
#define RB      31824
#define XL_OFF  RB             // 112 x 52
#define WQ_OFF  (RB + 5824)    // 288 x 52
#define S_OFF2  RB             // 112 x 114 fp32
#define P_OFF   (RB + 12768)   // 112 x 60
#define WP_OFF  (RB + 12768)   // 96 x 52 (reuses P in phase C)
#define WIN_U32 52624
#define WIN_SMEM (WIN_U32 * 4)

__global__ __launch_bounds__(512, 1) void k_win(const float* __restrict__ x,
                                                const float* __restrict__ mask,
                                                const float* __restrict__ n1g,
                                                const float* __restrict__ n1b,
                                                const float* __restrict__ qb,
                                                const float* __restrict__ pb) {
    extern __shared__ uint32_t sm32[];
    float* smF = (float*)sm32;
    int* ro = (int*)(sm32 + RO_OFF);
    float* bias3 = smF + B3_OFF;
    float* sF = smF + S_OFF2;
    const int tid = threadIdx.x, B_ = blockIdx.x;
    const int wid = tid >> 5, lane = tid & 31;
    const int g = lane >> 2, t = lane & 3;

    // ---- phase A0: indices / weights / bias / padding ----
    if (tid < 98) ro[tid] = spat_base(B_, tid);
    for (int i = tid; i < 288; i += 512) bias3[i] = qb[i];
    for (int i = tid; i < 13824; i += 512) {            // Wqkv image
        int n = i / 48, j = i - n * 48;
        sm32[WQ_OFF + n * 52 + j] = g_qkvt[i];
    }
    for (int i = tid; i < 14 * 52; i += 512)            // zero xln pad rows
        sm32[XL_OFF + (98 + i / 52) * 52 + (i % 52)] = 0;
    for (int i = tid; i < 4 * 112 * 4; i += 512) {      // zero q/k dim-pad cols 12..15
        int h = i / 448, r = (i >> 2) % 112, c = 12 + (i & 3);
        sm32[Q_OFF + h * 2240 + r * 20 + c] = 0;
        sm32[K_OFF + h * 2240 + r * 20 + c] = 0;
    }
    __syncthreads();

    // ---- phase A1: LN1 -> bf16 A image (rows 0..97) ----
    {
        float g0 = n1g[lane], g1 = n1g[lane + 32], g2 = n1g[lane + 64];
        float b0 = n1b[lane], b1 = n1b[lane + 32], b2 = n1b[lane + 64];
        for (int tr = wid; tr < 98; tr += 16) {
            const float* xr = x + ro[tr];
            float v0 = xr[lane], v1 = xr[lane + 32], v2 = xr[lane + 64];
            float mean = warp_sum(v0 + v1 + v2) * (1.f / 96.f);
            float d0 = v0 - mean, d1 = v1 - mean, d2 = v2 - mean;
            float var = warp_sum(d0 * d0 + d1 * d1 + d2 * d2) * (1.f / 96.f);
            float rstd = rsqrtf(var + 1e-5f);
            float y0 = d0 * rstd * g0 + b0;
            float y1 = d1 * rstd * g1 + b1;
            float y2 = d2 * rstd * g2 + b2;
            float o0 = __shfl_xor_sync(0xffffffffu, y0, 1);
            float o1 = __shfl_xor_sync(0xffffffffu, y1, 1);
            float o2 = __shfl_xor_sync(0xffffffffu, y2, 1);
            if ((lane & 1) == 0) {
                int j = lane >> 1;
                sm32[XL_OFF + tr * 52 + j]      = pack_bf(y0, o0);
                sm32[XL_OFF + tr * 52 + j + 16] = pack_bf(y1, o1);
                sm32[XL_OFF + tr * 52 + j + 32] = pack_bf(y2, o2);
            }
        }
    }
    __syncthreads();

    const int mt = wid >> 1, nh = wid & 1;
    const int m0 = mt * 16;

    // ---- phase A2: QKV mma (112x288, K=96), 14 warps, 2 passes of 9 n-tiles ----
    if (wid < 14) {
        for (int p = 0; p < 2; ++p) {
            float acc[9][4];
            #pragma unroll
            for (int f = 0; f < 9; ++f)
                #pragma unroll
                for (int q = 0; q < 4; ++q) acc[f][q] = 0.f;
            #pragma unroll
            for (int k = 0; k < 6; ++k) {
                int k8 = k * 8;
                uint32_t a[4];
                a[0] = sm32[XL_OFF + (m0 + g) * 52 + k8 + t];
                a[1] = sm32[XL_OFF + (m0 + g + 8) * 52 + k8 + t];
                a[2] = sm32[XL_OFF + (m0 + g) * 52 + k8 + t + 4];
                a[3] = sm32[XL_OFF + (m0 + g + 8) * 52 + k8 + t + 4];
                #pragma unroll
                for (int f = 0; f < 9; ++f) {
                    int nr = nh * 144 + p * 72 + f * 8 + g;
                    uint32_t b[2];
                    b[0] = sm32[WQ_OFF + nr * 52 + k8 + t];
                    b[1] = sm32[WQ_OFF + nr * 52 + k8 + t + 4];
                    mma16816(acc[f], a, b);
                }
            }
            #pragma unroll
            for (int f = 0; f < 9; ++f) {
                int col = nh * 144 + p * 72 + f * 8 + 2 * t;
                float bb0 = bias3[col], bb1 = bias3[col + 1];
                float v0 = acc[f][0] + bb0, v1 = acc[f][1] + bb1;
                float v2 = acc[f][2] + bb0, v3 = acc[f][3] + bb1;
                int which = col / 96, cc = col - which * 96;
                int head = cc / 24, cd = cc - head * 24;
                int r0 = m0 + g, r1 = m0 + g + 8;
                if (which == 0) {
                    const float sc = 0.20412414523193154f;
                    sm32[Q_OFF + head * 2240 + r0 * 20 + (cd >> 1)] = pack_bf(v0 * sc, v1 * sc);
                    sm32[Q_OFF + head * 2240 + r1 * 20 + (cd >> 1)] = pack_bf(v2 * sc, v3 * sc);
                } else if (which == 1) {
                    sm32[K_OFF + head * 2240 + r0 * 20 + (cd >> 1)] = pack_bf(v0, v1);
                    sm32[K_OFF + head * 2240 + r1 * 20 + (cd >> 1)] = pack_bf(v2, v3);
                } else {
                    __nv_bfloat16* vb = (__nv_bfloat16*)(sm32 + V_OFF + head * 1920);
                    vb[cd * 120 + r0]       = __float2bfloat16(v0);
                    vb[(cd + 1) * 120 + r0] = __float2bfloat16(v1);
                    vb[cd * 120 + r1]       = __float2bfloat16(v2);
                    vb[(cd + 1) * 120 + r1] = __float2bfloat16(v3);
                }
            }
        }
    }
    __syncthreads();

    // ---- phase B: per-head attention ----
    const float* mk = mask + (B_ & 255) * 9604;
    for (int h = 0; h < 4; ++h) {
        const float* bi = g_bias + h * 9604;
        const uint32_t* qh = sm32 + Q_OFF + h * 2240;
        const uint32_t* kh = sm32 + K_OFF + h * 2240;

        // scores (112x112, K=32)
        if (wid < 14) {
            float acc[7][4];
            #pragma unroll
            for (int f = 0; f < 7; ++f)
                #pragma unroll
                for (int q = 0; q < 4; ++q) acc[f][q] = 0.f;
            #pragma unroll
            for (int k = 0; k < 2; ++k) {
                int k8 = k * 8;
                uint32_t a[4];
                a[0] = qh[(m0 + g) * 20 + k8 + t];
                a[1] = qh[(m0 + g + 8) * 20 + k8 + t];
                a[2] = qh[(m0 + g) * 20 + k8 + t + 4];
                a[3] = qh[(m0 + g + 8) * 20 + k8 + t + 4];
                #pragma unroll
                for (int f = 0; f < 7; ++f) {
                    int nr = nh * 56 + f * 8 + g;
                    uint32_t b[2];
                    b[0] = kh[nr * 20 + k8 + t];
                    b[1] = kh[nr * 20 + k8 + t + 4];
                    mma16816(acc[f], a, b);
                }
            }
            #pragma unroll
            for (int f = 0; f < 7; ++f) {
                int col = nh * 56 + f * 8 + 2 * t;
                if (col < 98) {
                    int r0 = m0 + g, r1 = r0 + 8;
                    if (r0 < 98) {
                        float2 bv = *(const float2*)(bi + r0 * 98 + col);
                        float2 mv = *(const float2*)(mk + r0 * 98 + col);
                        sF[r0 * 114 + col]     = acc[f][0] + bv.x + mv.x;
                        sF[r0 * 114 + col + 1] = acc[f][1] + bv.y + mv.y;
                    }
                    if (r1 < 98) {
                        float2 bv = *(const float2*)(bi + r1 * 98 + col);
                        float2 mv = *(const float2*)(mk + r1 * 98 + col);
                        sF[r1 * 114 + col]     = acc[f][2] + bv.x + mv.x;
                        sF[r1 * 114 + col + 1] = acc[f][3] + bv.y + mv.y;
                    }
                }
            }
        }
        __syncthreads();

        // softmax + pack P to bf16 (cols>=98 zeroed)
        for (int i = wid; i < 98; i += 16) {
            float mx = -1e30f;
            for (int j = lane; j < 98; j += 32) mx = fmaxf(mx, sF[i * 114 + j]);
            mx = warp_max(mx);
            float sum = 0.f;
            for (int j = lane; j < 98; j += 32) {
                float e = __expf(sF[i * 114 + j] - mx);
                sF[i * 114 + j] = e;
                sum += e;
            }
            sum = warp_sum(sum);
            float inv = 1.f / sum;
            for (int jc = lane; jc < 56; jc += 32) {
                uint32_t u = 0;
                if (jc <= 48) {
                    float2 f2 = *(float2*)(sF + i * 114 + 2 * jc);
                    u = pack_bf(f2.x * inv, f2.y * inv);
                }
                sm32[P_OFF + i * 60 + jc] = u;
            }
        }
        // zero pad P rows so PV garbage stays finite (stale smem may be NaN)
        for (int i = tid; i < 14 * 60; i += 512)
            sm32[P_OFF + (98 + i / 60) * 60 + (i % 60)] = 0;
        __syncthreads();

        // PV (112x32, K=112)
        if (wid < 14) {
            float acc[2][4];
            #pragma unroll
            for (int f = 0; f < 2; ++f)
                #pragma unroll
                for (int q = 0; q < 4; ++q) acc[f][q] = 0.f;
            #pragma unroll
            for (int k = 0; k < 7; ++k) {
                int k8 = k * 8;
                uint32_t a[4];
                a[0] = sm32[P_OFF + (m0 + g) * 60 + k8 + t];
                a[1] = sm32[P_OFF + (m0 + g + 8) * 60 + k8 + t];
                a[2] = sm32[P_OFF + (m0 + g) * 60 + k8 + t + 4];
                a[3] = sm32[P_OFF + (m0 + g + 8) * 60 + k8 + t + 4];
                #pragma unroll
                for (int f = 0; f < 2; ++f) {
                    int nr = (nh * 2 + f) * 8 + g;
                    uint32_t b[2];
                    b[0] = sm32[V_OFF + h * 1920 + nr * 60 + k8 + t];
                    b[1] = sm32[V_OFF + h * 1920 + nr * 60 + k8 + t + 4];
                    mma16816(acc[f], a, b);
                }
            }
            #pragma unroll
            for (int f = 0; f < 2; ++f) {
                int col = (nh * 2 + f) * 8 + 2 * t;
                if (col < 24) {
                    sm32[AT_OFF + (m0 + g) * 52 + h * 12 + (col >> 1)]     = pack_bf(acc[f][0], acc[f][1]);
                    sm32[AT_OFF + (m0 + g + 8) * 52 + h * 12 + (col >> 1)] = pack_bf(acc[f][2], acc[f][3]);
                }
            }
        }
        __syncthreads();
    }

    // ---- phase C: proj (112x96, K=96) + residual + scatter ----
    for (int i = tid; i < 96 * 48; i += 512) {
        int n = i / 48, j = i - n * 48;
        sm32[WP_OFF + n * 52 + j] = g_pwt[i];
    }
    if (tid < 96) bias3[tid] = pb[tid];
    __syncthreads();

    if (wid < 14) {
        float acc[6][4];
        #pragma unroll
        for (int f = 0; f < 6; ++f)
            #pragma unroll
            for (int q = 0; q < 4; ++q) acc[f][q] = 0.f;
        #pragma unroll
        for (int k = 0; k < 6; ++k) {
            int k8 = k * 8;
            uint32_t a[4];
            a[0] = sm32[AT_OFF + (m0 + g) * 52 + k8 + t];
            a[1] = sm32[AT_OFF + (m0 + g + 8) * 52 + k8 + t];
            a[2] = sm32[AT_OFF + (m0 + g) * 52 + k8 + t + 4];
            a[3] = sm32[AT_OFF + (m0 + g + 8) * 52 + k8 + t + 4];
            #pragma unroll
            for (int f = 0; f < 6; ++f) {
                int nr = nh * 48 + f * 8 + g;
                uint32_t b[2];
                b[0] = sm32[WP_OFF + nr * 52 + k8 + t];
                b[1] = sm32[WP_OFF + nr * 52 + k8 + t + 4];
                mma16816(acc[f], a, b);
            }
        }
        #pragma unroll
        for (int f = 0; f < 6; ++f) {
            int col = nh * 48 + f * 8 + 2 * t;
            *(float2*)(sF + (m0 + g) * 114 + col)     = make_float2(acc[f][0], acc[f][1]);
            *(float2*)(sF + (m0 + g + 8) * 114 + col) = make_float2(acc[f][2], acc[f][3]);
        }
    }
    __syncthreads();

    for (int i = tid; i < 98 * 96; i += 512) {
        int row = i / 96, col = i - row * 96;
        int base = ro[row];
        g_x2[base + col] = x[base + col] + sF[row * 114 + col] + bias3[col];
    }
}

// ---------------- fused MLP via mma.sync bf16 (unchanged, passing) ----------------
#define MH_HID  0
#define MH_R    100352
#define MH_A    (MH_R)
#define MH_W1   (MH_R + 26624)
#define MH_F1B  175616
#define MH_F2B  177152
#define MH_SMEM 177536

__global__ __launch_bounds__(512, 1) void k_mlpT(const float* __restrict__ n2g,
                                                 const float* __restrict__ n2b,
                                                 const float* __restrict__ f1b,
                                                 const float* __restrict__ f2b,
                                                 float* __restrict__ out) {
    extern __shared__ char smc[];
    uint32_t* hid32 = (uint32_t*)(smc + MH_HID);
    uint32_t* A32   = (uint32_t*)(smc + MH_A);
    uint32_t* w1c32 = (uint32_t*)(smc + MH_W1);
    uint32_t* w2s32 = (uint32_t*)(smc + MH_R);
    float* obufF    = (float*)(smc + MH_R);
    float* sf1b     = (float*)(smc + MH_F1B);
    float* sf2b     = (float*)(smc + MH_F2B);

    const int tid = threadIdx.x, wid = tid >> 5, lane = tid & 31;
    const int g = lane >> 2, t = lane & 3;
    const int tok0 = blockIdx.x * 128;

    for (int i = tid; i < 384; i += 512) sf1b[i] = f1b[i];
    if (tid < 96) sf2b[tid] = f2b[tid];

    {
        float g0 = n2g[lane], g1 = n2g[lane + 32], g2 = n2g[lane + 64];
        float b0 = n2b[lane], b1 = n2b[lane + 32], b2 = n2b[lane + 64];
        for (int tr = wid; tr < 128; tr += 16) {
            const float* xr = g_x2 + (tok0 + tr) * 96;
            float v0 = xr[lane], v1 = xr[lane + 32], v2 = xr[lane + 64];
            float mean = warp_sum(v0 + v1 + v2) * (1.f / 96.f);
            float d0 = v0 - mean, d1 = v1 - mean, d2 = v2 - mean;
            float var = warp_sum(d0 * d0 + d1 * d1 + d2 * d2) * (1.f / 96.f);
            float rstd = rsqrtf(var + 1e-5f);
            float y0 = d0 * rstd * g0 + b0;
            float y1 = d1 * rstd * g1 + b1;
            float y2 = d2 * rstd * g2 + b2;
            float o0 = __shfl_xor_sync(0xffffffffu, y0, 1);
            float o1 = __shfl_xor_sync(0xffffffffu, y1, 1);
            float o2 = __shfl_xor_sync(0xffffffffu, y2, 1);
            if ((lane & 1) == 0) {
                A32[tr * 52 + (lane >> 1)]      = pack_bf(y0, o0);
                A32[tr * 52 + (lane >> 1) + 16] = pack_bf(y1, o1);
                A32[tr * 52 + (lane >> 1) + 32] = pack_bf(y2, o2);
            }
        }
    }
    __syncthreads();

    const int mrow = (wid & 7) * 16;
    const int nhalf = wid >> 3;

    for (int c = 0; c < 3; ++c) {
        for (int i = tid; i < 6144; i += 512) {
            int n = i / 48, j = i - n * 48;
            w1c32[n * 52 + j] = g_w1t[c * 6144 + i];
        }
        __syncthreads();

        float acc[8][4];
        #pragma unroll
        for (int f = 0; f < 8; ++f)
            #pragma unroll
            for (int q = 0; q < 4; ++q) acc[f][q] = 0.f;

        const int n0 = nhalf * 64;
        #pragma unroll
        for (int k = 0; k < 6; ++k) {
            const int k8 = k * 8;
            uint32_t a[4];
            a[0] = A32[(mrow + g) * 52 + k8 + t];
            a[1] = A32[(mrow + g + 8) * 52 + k8 + t];
            a[2] = A32[(mrow + g) * 52 + k8 + t + 4];
            a[3] = A32[(mrow + g + 8) * 52 + k8 + t + 4];
            #pragma unroll
            for (int f = 0; f < 8; ++f) {
                uint32_t b[2];
                b[0] = w1c32[(n0 + f * 8 + g) * 52 + k8 + t];
                b[1] = w1c32[(n0 + f * 8 + g) * 52 + k8 + t + 4];
                mma16816(acc[f], a, b);
            }
        }

        #pragma unroll
        for (int f = 0; f < 8; ++f) {
            int gcol = c * 128 + n0 + f * 8 + 2 * t;
            float u0 = acc[f][0] + sf1b[gcol];
            float u1 = acc[f][1] + sf1b[gcol + 1];
            float u2 = acc[f][2] + sf1b[gcol];
            float u3 = acc[f][3] + sf1b[gcol + 1];
            float e0 = 0.5f * u0 * (1.f + erff(u0 * 0.70710678118654752f));
            float e1 = 0.5f * u1 * (1.f + erff(u1 * 0.70710678118654752f));
            float e2 = 0.5f * u2 * (1.f + erff(u2 * 0.70710678118654752f));
            float e3 = 0.5f * u3 * (1.f + erff(u3 * 0.70710678118654752f));
            int hc = (gcol >> 1);
            hid32[(mrow + g) * 196 + hc]     = pack_bf(e0, e1);
            hid32[(mrow + g + 8) * 196 + hc] = pack_bf(e2, e3);
        }
        __syncthreads();
    }

    for (int i = tid; i < 18432; i += 512) {
        int n = i / 192, j = i - n * 192;
        w2s32[n * 196 + j] = g_w2t[i];
    }
    __syncthreads();

    {
        float acc[6][4];
        #pragma unroll
        for (int f = 0; f < 6; ++f)
            #pragma unroll
            for (int q = 0; q < 4; ++q) acc[f][q] = 0.f;

        const int n0 = nhalf * 48;
        #pragma unroll 4
        for (int k = 0; k < 24; ++k) {
            const int k8 = k * 8;
            uint32_t a[4];
            a[0] = hid32[(mrow + g) * 196 + k8 + t];
            a[1] = hid32[(mrow + g + 8) * 196 + k8 + t];
            a[2] = hid32[(mrow + g) * 196 + k8 + t + 4];
            a[3] = hid32[(mrow + g + 8) * 196 + k8 + t + 4];
            #pragma unroll
            for (int f = 0; f < 6; ++f) {
                uint32_t b[2];
                b[0] = w2s32[(n0 + f * 8 + g) * 196 + k8 + t];
                b[1] = w2s32[(n0 + f * 8 + g) * 196 + k8 + t + 4];
                mma16816(acc[f], a, b);
            }
        }
        __syncthreads();

        #pragma unroll
        for (int f = 0; f < 6; ++f) {
            int col = n0 + f * 8 + 2 * t;
            *(float2*)(obufF + (mrow + g) * 100 + col)     = make_float2(acc[f][0], acc[f][1]);
            *(float2*)(obufF + (mrow + g + 8) * 100 + col) = make_float2(acc[f][2], acc[f][3]);
        }
    }
    __syncthreads();

    {
        const float* x2t = g_x2 + tok0 * 96;
        float* outt = out + tok0 * 96;
        for (int i = tid; i < 12288; i += 512) {
            int row = i / 96, col = i - row * 96;
            outt[i] = obufF[row * 100 + col] + sf2b[col] + x2t[i];
        }
    }
}

// ---------------- launch ----------------
extern "C" void kernel_launch(void* const* d_in, const int* in_sizes, int n_in,
                              void* d_out, int out_size) {
    const float* x    = (const float*)d_in[0];
    const float* mask = (const float*)d_in[1];
    const float* n1g  = (const float*)d_in[2];
    const float* n1b  = (const float*)d_in[3];
    const float* qkvw = (const float*)d_in[4];
    const float* qkvb = (const float*)d_in[5];
    const float* rpb  = (const float*)d_in[6];
    const float* pw   = (const float*)d_in[7];
    const float* pb   = (const float*)d_in[8];
    const float* n2g  = (const float*)d_in[9];
    const float* n2b  = (const float*)d_in[10];
    const float* f1w  = (const float*)d_in[11];
    const float* f1b  = (const float*)d_in[12];
    const float* f2w  = (const float*)d_in[13];
    const float* f2b  = (const float*)d_in[14];
    float* out = (float*)d_out;

    cudaFuncSetAttribute(k_win,  cudaFuncAttributeMaxDynamicSharedMemorySize, WIN_SMEM);
    cudaFuncSetAttribute(k_mlpT, cudaFuncAttributeMaxDynamicSharedMemorySize, MH_SMEM);

    k_bias<<<98, 128>>>(rpb);
    k_wprep<<<216, 256>>>(f1w, f2w, qkvw, pw);
    k_win<<<2048, 512, WIN_SMEM>>>(x, mask, n1g, n1b, qkvb, pb);
    k_mlpT<<<1568, 512, MH_SMEM>>>(n2g, n2b, f1b, f2b, out);
}

// round 9
// speedup vs baseline: 5.0669x; 1.4667x over previous
#include <cuda_runtime.h>
#include <cuda_bf16.h>
#include <math.h>
#include <stdint.h>

#define DEV_INLINE __device__ __forceinline__

// ---------------- static scratch (allocation-free rule) ----------------
__device__ float g_x2[200704 * 96];                  // x + attn branch
__device__ float g_bias[4 * 98 * 98];                // rel-pos bias table
__device__ __align__(16) uint32_t g_w1t[18432];      // fc1^T bf16 (384 n x 96 k)
__device__ __align__(16) uint32_t g_w2t[18432];      // fc2^T bf16 (96 n x 384 k)
__device__ __align__(16) uint32_t g_qkvt[13824];     // qkv_w^T bf16 (288 n x 96 k)
__device__ __align__(16) uint32_t g_pwt[4608];       // proj_w^T bf16 (96 n x 96 k)

DEV_INLINE float warp_sum(float v) {
    #pragma unroll
    for (int o = 16; o; o >>= 1) v += __shfl_xor_sync(0xffffffffu, v, o);
    return v;
}
DEV_INLINE uint32_t pack_bf(float a, float b) {
    uint32_t lo = __bfloat16_as_ushort(__float2bfloat16(a));
    uint32_t hi = __bfloat16_as_ushort(__float2bfloat16(b));
    return (hi << 16) | lo;
}
DEV_INLINE void mma16816(float* d, const uint32_t* a, const uint32_t* b) {
    asm volatile("mma.sync.aligned.m16n8k16.row.col.f32.bf16.bf16.f32 "
        "{%0,%1,%2,%3}, {%4,%5,%6,%7}, {%8,%9}, {%0,%1,%2,%3};"
        : "+f"(d[0]), "+f"(d[1]), "+f"(d[2]), "+f"(d[3])
        : "r"(a[0]), "r"(a[1]), "r"(a[2]), "r"(a[3]), "r"(b[0]), "r"(b[1]));
}

DEV_INLINE int spat_base(int B_, int i) {
    int b = B_ >> 8, rem = B_ & 255;
    int wd = rem >> 6, wh = (rem >> 3) & 7, ww = rem & 7;
    int td = i / 49, r = i - td * 49;
    int th = r / 7, tw = r - th * 7;
    int d = (wd * 2 + td + 1) & 7;
    int hh = wh * 7 + th + 3; if (hh >= 56) hh -= 56;
    int w2 = ww * 7 + tw + 3; if (w2 >= 56) w2 -= 56;
    return (((b * 8 + d) * 56 + hh) * 56 + w2) * 96;
}

// ---------------- kernel 0: rel-pos bias table ----------------
__global__ void k_bias(const float* __restrict__ rpb) {
    int i = blockIdx.x, j = threadIdx.x;
    if (j >= 98) return;
    int di = i / 49, ri = i - di * 49, hi = ri / 7, wi = ri - hi * 7;
    int dj = j / 49, rj = j - dj * 49, hj = rj / 7, wj = rj - hj * 7;
    int r = (di - dj + 1) * 169 + (hi - hj + 6) * 13 + (wi - wj + 6);
    #pragma unroll
    for (int h = 0; h < 4; ++h)
        g_bias[h * 9604 + i * 98 + j] = rpb[r * 4 + h];
}

// ---------------- kernel: weight transposes to bf16 (N,K) k-contig ----------------
__global__ void k_wprep(const float* __restrict__ f1w, const float* __restrict__ f2w,
                        const float* __restrict__ qw, const float* __restrict__ pw) {
    int g = blockIdx.x * 256 + threadIdx.x;          // 0..55295
    if (g < 18432) {
        int n = g / 48, j = g % 48;
        g_w1t[g] = pack_bf(f1w[(2 * j) * 384 + n], f1w[(2 * j + 1) * 384 + n]);
    } else if (g < 36864) {
        int i = g - 18432;
        int n = i / 192, j = i % 192;
        g_w2t[i] = pack_bf(f2w[(2 * j) * 96 + n], f2w[(2 * j + 1) * 96 + n]);
    } else if (g < 50688) {
        int i = g - 36864;
        int n = i / 48, j = i % 48;
        g_qkvt[i] = pack_bf(qw[(2 * j) * 288 + n], qw[(2 * j + 1) * 288 + n]);
    } else if (g < 55296) {
        int i = g - 50688;
        int n = i / 48, j = i % 48;
        g_pwt[i] = pack_bf(pw[(2 * j) * 96 + n], pw[(2 * j + 1) * 96 + n]);
    }
}

// ---------------- fused window kernel: HMMA + register softmax ----------------
// u32 offsets in dynamic smem:
#define Q_OFF   0              // 4 heads x 112 x 20
#define K_OFF   8960
#define V_OFF   17920          // 4 heads x 32 dims x 60 (token pairs)
#define AT_OFF  25600          // 112 x 52
#define RO_OFF  31424          // 112 ints
#define B3_OFF  31536          // 288 floats
#define RB      31824
#define XL_OFF  RB             // 112 x 52 (phase A)
#define WQ_OFF  (RB + 5824)    // 288 x 52 (phase A)
#define PO_OFF  RB             // 112 x 100 f32 (phase C out)
#define WP2_OFF (RB + 11200)   // 96 x 52 (phase C weights)
#define WIN_U32 52624
#define WIN_SMEM (WIN_U32 * 4)

__global__ __launch_bounds__(512, 1) void k_win(const float* __restrict__ x,
                                                const float* __restrict__ mask,
                                                const float* __restrict__ n1g,
                                                const float* __restrict__ n1b,
                                                const float* __restrict__ qb,
                                                const float* __restrict__ pb) {
    extern __shared__ uint32_t sm32[];
    float* smF = (float*)sm32;
    int* ro = (int*)(sm32 + RO_OFF);
    float* bias3 = smF + B3_OFF;
    const int tid = threadIdx.x, B_ = blockIdx.x;
    const int wid = tid >> 5, lane = tid & 31;
    const int g = lane >> 2, t = lane & 3;

    // ---- phase A0: indices / weights / bias / padding ----
    if (tid < 98) ro[tid] = spat_base(B_, tid);
    for (int i = tid; i < 288; i += 512) bias3[i] = qb[i];
    for (int i = tid; i < 13824; i += 512) {            // Wqkv image
        int n = i / 48, j = i - n * 48;
        sm32[WQ_OFF + n * 52 + j] = g_qkvt[i];
    }
    for (int i = tid; i < 14 * 52; i += 512)            // zero xln pad rows
        sm32[XL_OFF + (98 + i / 52) * 52 + (i % 52)] = 0;
    for (int i = tid; i < 4 * 112 * 4; i += 512) {      // zero q/k dim-pad cols 12..15
        int h = i / 448, r = (i >> 2) % 112, c = 12 + (i & 3);
        sm32[Q_OFF + h * 2240 + r * 20 + c] = 0;
        sm32[K_OFF + h * 2240 + r * 20 + c] = 0;
    }
    __syncthreads();

    // ---- phase A1: LN1 -> bf16 A image (rows 0..97) ----
    {
        float g0 = n1g[lane], g1 = n1g[lane + 32], g2 = n1g[lane + 64];
        float b0 = n1b[lane], b1 = n1b[lane + 32], b2 = n1b[lane + 64];
        for (int tr = wid; tr < 98; tr += 16) {
            const float* xr = x + ro[tr];
            float v0 = xr[lane], v1 = xr[lane + 32], v2 = xr[lane + 64];
            float mean = warp_sum(v0 + v1 + v2) * (1.f / 96.f);
            float d0 = v0 - mean, d1 = v1 - mean, d2 = v2 - mean;
            float var = warp_sum(d0 * d0 + d1 * d1 + d2 * d2) * (1.f / 96.f);
            float rstd = rsqrtf(var + 1e-5f);
            float y0 = d0 * rstd * g0 + b0;
            float y1 = d1 * rstd * g1 + b1;
            float y2 = d2 * rstd * g2 + b2;
            float o0 = __shfl_xor_sync(0xffffffffu, y0, 1);
            float o1 = __shfl_xor_sync(0xffffffffu, y1, 1);
            float o2 = __shfl_xor_sync(0xffffffffu, y2, 1);
            if ((lane & 1) == 0) {
                int j = lane >> 1;
                sm32[XL_OFF + tr * 52 + j]      = pack_bf(y0, o0);
                sm32[XL_OFF + tr * 52 + j + 16] = pack_bf(y1, o1);
                sm32[XL_OFF + tr * 52 + j + 32] = pack_bf(y2, o2);
            }
        }
    }
    __syncthreads();

    // ---- phase A2: QKV mma (112x288, K=96), warps 0..13 ----
    if (wid < 14) {
        const int mt = wid >> 1, nh = wid & 1;
        const int m0 = mt * 16;
        for (int p = 0; p < 2; ++p) {
            float acc[9][4];
            #pragma unroll
            for (int f = 0; f < 9; ++f)
                #pragma unroll
                for (int q = 0; q < 4; ++q) acc[f][q] = 0.f;
            #pragma unroll
            for (int k = 0; k < 6; ++k) {
                int k8 = k * 8;
                uint32_t a[4];
                a[0] = sm32[XL_OFF + (m0 + g) * 52 + k8 + t];
                a[1] = sm32[XL_OFF + (m0 + g + 8) * 52 + k8 + t];
                a[2] = sm32[XL_OFF + (m0 + g) * 52 + k8 + t + 4];
                a[3] = sm32[XL_OFF + (m0 + g + 8) * 52 + k8 + t + 4];
                #pragma unroll
                for (int f = 0; f < 9; ++f) {
                    int nr = nh * 144 + p * 72 + f * 8 + g;
                    uint32_t b[2];
                    b[0] = sm32[WQ_OFF + nr * 52 + k8 + t];
                    b[1] = sm32[WQ_OFF + nr * 52 + k8 + t + 4];
                    mma16816(acc[f], a, b);
                }
            }
            #pragma unroll
            for (int f = 0; f < 9; ++f) {
                int col = nh * 144 + p * 72 + f * 8 + 2 * t;
                float bb0 = bias3[col], bb1 = bias3[col + 1];
                float v0 = acc[f][0] + bb0, v1 = acc[f][1] + bb1;
                float v2 = acc[f][2] + bb0, v3 = acc[f][3] + bb1;
                int which = col / 96, cc = col - which * 96;
                int head = cc / 24, cd = cc - head * 24;
                int r0 = m0 + g, r1 = m0 + g + 8;
                if (which == 0) {
                    const float sc = 0.20412414523193154f;
                    sm32[Q_OFF + head * 2240 + r0 * 20 + (cd >> 1)] = pack_bf(v0 * sc, v1 * sc);
                    sm32[Q_OFF + head * 2240 + r1 * 20 + (cd >> 1)] = pack_bf(v2 * sc, v3 * sc);
                } else if (which == 1) {
                    sm32[K_OFF + head * 2240 + r0 * 20 + (cd >> 1)] = pack_bf(v0, v1);
                    sm32[K_OFF + head * 2240 + r1 * 20 + (cd >> 1)] = pack_bf(v2, v3);
                } else {
                    __nv_bfloat16* vb = (__nv_bfloat16*)(sm32 + V_OFF + head * 1920);
                    vb[cd * 120 + r0]       = __float2bfloat16(v0);
                    vb[(cd + 1) * 120 + r0] = __float2bfloat16(v1);
                    vb[cd * 120 + r1]       = __float2bfloat16(v2);
                    vb[(cd + 1) * 120 + r1] = __float2bfloat16(v3);
                }
            }
        }
    }
    __syncthreads();

    // ---- phase B: attention, register softmax, NO barriers ----
    // warps 0..13: 2 heads in flight x 7 m-tiles; warps 14,15 prefetch proj weights.
    if (wid < 14) {
        const int hloc = wid & 1, mtB = wid >> 1;
        const int m0B = mtB * 16;
        const float* mk = mask + (B_ & 255) * 9604;
        const int r0 = m0B + g, r1 = r0 + 8;
        for (int p = 0; p < 2; ++p) {
            const int h = p * 2 + hloc;
            const float* bi = g_bias + h * 9604;
            const uint32_t* qh = sm32 + Q_OFF + h * 2240;
            const uint32_t* kh = sm32 + K_OFF + h * 2240;
            const uint32_t* vh = sm32 + V_OFF + h * 1920;

            // scores: 16 x 112, K=32
            float c[14][4];
            #pragma unroll
            for (int nt = 0; nt < 14; ++nt)
                #pragma unroll
                for (int q = 0; q < 4; ++q) c[nt][q] = 0.f;
            #pragma unroll
            for (int kt = 0; kt < 2; ++kt) {
                int k8 = kt * 8;
                uint32_t a[4];
                a[0] = qh[r0 * 20 + k8 + t];
                a[1] = qh[r1 * 20 + k8 + t];
                a[2] = qh[r0 * 20 + k8 + t + 4];
                a[3] = qh[r1 * 20 + k8 + t + 4];
                #pragma unroll
                for (int nt = 0; nt < 14; ++nt) {
                    uint32_t b[2];
                    b[0] = kh[(nt * 8 + g) * 20 + k8 + t];
                    b[1] = kh[(nt * 8 + g) * 20 + k8 + t + 4];
                    mma16816(c[nt], a, b);
                }
            }
            // bias + mask; mask out pad cols
            #pragma unroll
            for (int nt = 0; nt < 14; ++nt) {
                int col = nt * 8 + 2 * t;
                if (col < 98) {
                    if (r0 < 98) {
                        float2 bv = *(const float2*)(bi + r0 * 98 + col);
                        float2 mv = *(const float2*)(mk + r0 * 98 + col);
                        c[nt][0] += bv.x + mv.x; c[nt][1] += bv.y + mv.y;
                    }
                    if (r1 < 98) {
                        float2 bv = *(const float2*)(bi + r1 * 98 + col);
                        float2 mv = *(const float2*)(mk + r1 * 98 + col);
                        c[nt][2] += bv.x + mv.x; c[nt][3] += bv.y + mv.y;
                    }
                } else {
                    c[nt][0] = c[nt][1] = c[nt][2] = c[nt][3] = -1e30f;
                }
            }
            // register softmax (rows r0, r1); quad = lanes sharing g
            float mx0 = -1e30f, mx1 = -1e30f;
            #pragma unroll
            for (int nt = 0; nt < 14; ++nt) {
                mx0 = fmaxf(mx0, fmaxf(c[nt][0], c[nt][1]));
                mx1 = fmaxf(mx1, fmaxf(c[nt][2], c[nt][3]));
            }
            mx0 = fmaxf(mx0, __shfl_xor_sync(0xffffffffu, mx0, 1));
            mx0 = fmaxf(mx0, __shfl_xor_sync(0xffffffffu, mx0, 2));
            mx1 = fmaxf(mx1, __shfl_xor_sync(0xffffffffu, mx1, 1));
            mx1 = fmaxf(mx1, __shfl_xor_sync(0xffffffffu, mx1, 2));
            float s0 = 0.f, s1 = 0.f;
            #pragma unroll
            for (int nt = 0; nt < 14; ++nt) {
                c[nt][0] = __expf(c[nt][0] - mx0); s0 += c[nt][0];
                c[nt][1] = __expf(c[nt][1] - mx0); s0 += c[nt][1];
                c[nt][2] = __expf(c[nt][2] - mx1); s1 += c[nt][2];
                c[nt][3] = __expf(c[nt][3] - mx1); s1 += c[nt][3];
            }
            s0 += __shfl_xor_sync(0xffffffffu, s0, 1);
            s0 += __shfl_xor_sync(0xffffffffu, s0, 2);
            s1 += __shfl_xor_sync(0xffffffffu, s1, 1);
            s1 += __shfl_xor_sync(0xffffffffu, s1, 2);
            float inv0 = 1.f / s0, inv1 = 1.f / s1;

            // PV: P stays in registers (C-frag -> A-frag), V as B operand
            float pv[3][4];
            #pragma unroll
            for (int f = 0; f < 3; ++f)
                #pragma unroll
                for (int q = 0; q < 4; ++q) pv[f][q] = 0.f;
            #pragma unroll
            for (int kt2 = 0; kt2 < 7; ++kt2) {
                uint32_t a[4];
                a[0] = pack_bf(c[2 * kt2][0] * inv0, c[2 * kt2][1] * inv0);
                a[1] = pack_bf(c[2 * kt2][2] * inv1, c[2 * kt2][3] * inv1);
                a[2] = pack_bf(c[2 * kt2 + 1][0] * inv0, c[2 * kt2 + 1][1] * inv0);
                a[3] = pack_bf(c[2 * kt2 + 1][2] * inv1, c[2 * kt2 + 1][3] * inv1);
                int k8 = kt2 * 8;
                #pragma unroll
                for (int f = 0; f < 3; ++f) {
                    uint32_t b[2];
                    b[0] = vh[(f * 8 + g) * 60 + k8 + t];
                    b[1] = vh[(f * 8 + g) * 60 + k8 + t + 4];
                    mma16816(pv[f], a, b);
                }
            }
            // write attention output (bf16) for this head
            #pragma unroll
            for (int f = 0; f < 3; ++f) {
                int col = f * 8 + 2 * t;     // 0..22
                sm32[AT_OFF + r0 * 52 + h * 12 + (col >> 1)] = pack_bf(pv[f][0], pv[f][1]);
                sm32[AT_OFF + r1 * 52 + h * 12 + (col >> 1)] = pack_bf(pv[f][2], pv[f][3]);
            }
        }
    } else {
        // warps 14,15: prefetch proj weights + bias (XL/WQ dead, disjoint region)
        for (int i = tid - 448; i < 4608; i += 64) {
            int n = i / 48, j = i - n * 48;
            sm32[WP2_OFF + n * 52 + j] = g_pwt[i];
        }
        for (int i = tid - 448; i < 96; i += 64) bias3[i] = pb[i];
    }
    __syncthreads();

    // ---- phase C: proj (112x96, K=96) ----
    if (wid < 14) {
        const int mtC = wid >> 1, nhC = wid & 1;
        const int m0C = mtC * 16;
        float acc[6][4];
        #pragma unroll
        for (int f = 0; f < 6; ++f)
            #pragma unroll
            for (int q = 0; q < 4; ++q) acc[f][q] = 0.f;
        #pragma unroll
        for (int k = 0; k < 6; ++k) {
            int k8 = k * 8;
            uint32_t a[4];
            a[0] = sm32[AT_OFF + (m0C + g) * 52 + k8 + t];
            a[1] = sm32[AT_OFF + (m0C + g + 8) * 52 + k8 + t];
            a[2] = sm32[AT_OFF + (m0C + g) * 52 + k8 + t + 4];
            a[3] = sm32[AT_OFF + (m0C + g + 8) * 52 + k8 + t + 4];
            #pragma unroll
            for (int f = 0; f < 6; ++f) {
                int nr = nhC * 48 + f * 8 + g;
                uint32_t b[2];
                b[0] = sm32[WP2_OFF + nr * 52 + k8 + t];
                b[1] = sm32[WP2_OFF + nr * 52 + k8 + t + 4];
                mma16816(acc[f], a, b);
            }
        }
        #pragma unroll
        for (int f = 0; f < 6; ++f) {
            int col = nhC * 48 + f * 8 + 2 * t;
            *(float2*)(smF + PO_OFF + (m0C + g) * 100 + col)     = make_float2(acc[f][0], acc[f][1]);
            *(float2*)(smF + PO_OFF + (m0C + g + 8) * 100 + col) = make_float2(acc[f][2], acc[f][3]);
        }
    }
    __syncthreads();

    // ---- residual + scatter ----
    for (int i = tid; i < 98 * 96; i += 512) {
        int row = i / 96, col = i - row * 96;
        int base = ro[row];
        g_x2[base + col] = x[base + col] + smF[PO_OFF + row * 100 + col] + bias3[col];
    }
}

// ---------------- fused MLP: 64 tokens/block, 2 CTAs/SM ----------------
#define M2_A    0              // 64 x 52 (bf16 A); overlaid by OB (f32, stride 100) post-fc2
#define M2_HID  3328           // 64 x 196
#define M2_WB   15872          // 6656 (W1 chunk 128x52 / W2 chunk 96x68)
#define M2_B1   22528          // 384 f32
#define M2_B2   22912          // 96 f32
#define M2_U32  23040
#define M2_SMEM (M2_U32 * 4)

__global__ __launch_bounds__(512, 2) void k_mlpT(const float* __restrict__ n2g,
                                                 const float* __restrict__ n2b,
                                                 const float* __restrict__ f1b,
                                                 const float* __restrict__ f2b,
                                                 float* __restrict__ out) {
    extern __shared__ uint32_t smm[];
    float* smmF = (float*)smm;
    float* sf1b = smmF + M2_B1;
    float* sf2b = smmF + M2_B2;
    const int tid = threadIdx.x, wid = tid >> 5, lane = tid & 31;
    const int g = lane >> 2, t = lane & 3;
    const int tok0 = blockIdx.x * 64;

    if (tid < 384) sf1b[tid] = f1b[tid];
    if (tid >= 384 && tid < 480) sf2b[tid - 384] = f2b[tid - 384];

    // ---- LN2 -> bf16 A (stride 52 u32) ----
    {
        float g0 = n2g[lane], g1 = n2g[lane + 32], g2 = n2g[lane + 64];
        float b0 = n2b[lane], b1 = n2b[lane + 32], b2 = n2b[lane + 64];
        for (int tr = wid; tr < 64; tr += 16) {
            const float* xr = g_x2 + (tok0 + tr) * 96;
            float v0 = xr[lane], v1 = xr[lane + 32], v2 = xr[lane + 64];
            float mean = warp_sum(v0 + v1 + v2) * (1.f / 96.f);
            float d0 = v0 - mean, d1 = v1 - mean, d2 = v2 - mean;
            float var = warp_sum(d0 * d0 + d1 * d1 + d2 * d2) * (1.f / 96.f);
            float rstd = rsqrtf(var + 1e-5f);
            float y0 = d0 * rstd * g0 + b0;
            float y1 = d1 * rstd * g1 + b1;
            float y2 = d2 * rstd * g2 + b2;
            float o0 = __shfl_xor_sync(0xffffffffu, y0, 1);
            float o1 = __shfl_xor_sync(0xffffffffu, y1, 1);
            float o2 = __shfl_xor_sync(0xffffffffu, y2, 1);
            if ((lane & 1) == 0) {
                int j = lane >> 1;
                smm[M2_A + tr * 52 + j]      = pack_bf(y0, o0);
                smm[M2_A + tr * 52 + j + 16] = pack_bf(y1, o1);
                smm[M2_A + tr * 52 + j + 32] = pack_bf(y2, o2);
            }
        }
    }

    const int mt = wid & 3, nq = wid >> 2;   // 4 mtiles x 4 n-quarters
    const int mrow = mt * 16;

    // ---- fc1 (64x384, K=96): 3 n-chunks of 128 ----
    for (int c = 0; c < 3; ++c) {
        __syncthreads();                      // A ready (c=0) / prior WB reads done
        for (int i = tid; i < 6144; i += 512) {
            int n = i / 48, j = i - n * 48;
            smm[M2_WB + n * 52 + j] = g_w1t[c * 6144 + i];
        }
        __syncthreads();
        float acc[4][4];
        #pragma unroll
        for (int f = 0; f < 4; ++f)
            #pragma unroll
            for (int q = 0; q < 4; ++q) acc[f][q] = 0.f;
        #pragma unroll
        for (int k = 0; k < 6; ++k) {
            int k8 = k * 8;
            uint32_t a[4];
            a[0] = smm[M2_A + (mrow + g) * 52 + k8 + t];
            a[1] = smm[M2_A + (mrow + g + 8) * 52 + k8 + t];
            a[2] = smm[M2_A + (mrow + g) * 52 + k8 + t + 4];
            a[3] = smm[M2_A + (mrow + g + 8) * 52 + k8 + t + 4];
            #pragma unroll
            for (int f = 0; f < 4; ++f) {
                int nr = nq * 32 + f * 8 + g;
                uint32_t b[2];
                b[0] = smm[M2_WB + nr * 52 + k8 + t];
                b[1] = smm[M2_WB + nr * 52 + k8 + t + 4];
                mma16816(acc[f], a, b);
            }
        }
        #pragma unroll
        for (int f = 0; f < 4; ++f) {
            int gcol = c * 128 + nq * 32 + f * 8 + 2 * t;
            float u0 = acc[f][0] + sf1b[gcol];
            float u1 = acc[f][1] + sf1b[gcol + 1];
            float u2 = acc[f][2] + sf1b[gcol];
            float u3 = acc[f][3] + sf1b[gcol + 1];
            float e0 = 0.5f * u0 * (1.f + erff(u0 * 0.70710678118654752f));
            float e1 = 0.5f * u1 * (1.f + erff(u1 * 0.70710678118654752f));
            float e2 = 0.5f * u2 * (1.f + erff(u2 * 0.70710678118654752f));
            float e3 = 0.5f * u3 * (1.f + erff(u3 * 0.70710678118654752f));
            int hc = gcol >> 1;
            smm[M2_HID + (mrow + g) * 196 + hc]     = pack_bf(e0, e1);
            smm[M2_HID + (mrow + g + 8) * 196 + hc] = pack_bf(e2, e3);
        }
    }

    // ---- fc2 (64x96, K=384): 3 k-chunks of 128 ----
    float acc2[3][4];
    #pragma unroll
    for (int f = 0; f < 3; ++f)
        #pragma unroll
        for (int q = 0; q < 4; ++q) acc2[f][q] = 0.f;
    for (int c = 0; c < 3; ++c) {
        __syncthreads();                      // hid writes done / prior WB reads done
        for (int i = tid; i < 6144; i += 512) {
            int n = i >> 6, jj = i & 63;
            smm[M2_WB + n * 68 + jj] = g_w2t[n * 192 + c * 64 + jj];
        }
        __syncthreads();
        #pragma unroll
        for (int k = 0; k < 8; ++k) {
            int k8 = k * 8;
            uint32_t a[4];
            a[0] = smm[M2_HID + (mrow + g) * 196 + c * 64 + k8 + t];
            a[1] = smm[M2_HID + (mrow + g + 8) * 196 + c * 64 + k8 + t];
            a[2] = smm[M2_HID + (mrow + g) * 196 + c * 64 + k8 + t + 4];
            a[3] = smm[M2_HID + (mrow + g + 8) * 196 + c * 64 + k8 + t + 4];
            #pragma unroll
            for (int f = 0; f < 3; ++f) {
                int nr = nq * 24 + f * 8 + g;
                uint32_t b[2];
                b[0] = smm[M2_WB + nr * 68 + k8 + t];
                b[1] = smm[M2_WB + nr * 68 + k8 + t + 4];
                mma16816(acc2[f], a, b);
            }
        }
    }
    __syncthreads();                          // all fc2 reads done before OB overlay

    #pragma unroll
    for (int f = 0; f < 3; ++f) {
        int col = nq * 24 + f * 8 + 2 * t;    // 0..94
        *(float2*)(smmF + (mrow + g) * 100 + col)     = make_float2(acc2[f][0], acc2[f][1]);
        *(float2*)(smmF + (mrow + g + 8) * 100 + col) = make_float2(acc2[f][2], acc2[f][3]);
    }
    __syncthreads();

    // ---- writeout: out = x2 + fc2 + bias ----
    {
        const float* x2t = g_x2 + tok0 * 96;
        float* outt = out + tok0 * 96;
        for (int i = tid; i < 6144; i += 512) {
            int row = i / 96, col = i - row * 96;
            outt[i] = smmF[row * 100 + col] + sf2b[col] + x2t[i];
        }
    }
}

// ---------------- launch ----------------
extern "C" void kernel_launch(void* const* d_in, const int* in_sizes, int n_in,
                              void* d_out, int out_size) {
    const float* x    = (const float*)d_in[0];
    const float* mask = (const float*)d_in[1];
    const float* n1g  = (const float*)d_in[2];
    const float* n1b  = (const float*)d_in[3];
    const float* qkvw = (const float*)d_in[4];
    const float* qkvb = (const float*)d_in[5];
    const float* rpb  = (const float*)d_in[6];
    const float* pw   = (const float*)d_in[7];
    const float* pb   = (const float*)d_in[8];
    const float* n2g  = (const float*)d_in[9];
    const float* n2b  = (const float*)d_in[10];
    const float* f1w  = (const float*)d_in[11];
    const float* f1b  = (const float*)d_in[12];
    const float* f2w  = (const float*)d_in[13];
    const float* f2b  = (const float*)d_in[14];
    float* out = (float*)d_out;

    cudaFuncSetAttribute(k_win,  cudaFuncAttributeMaxDynamicSharedMemorySize, WIN_SMEM);
    cudaFuncSetAttribute(k_mlpT, cudaFuncAttributeMaxDynamicSharedMemorySize, M2_SMEM);

    k_bias<<<98, 128>>>(rpb);
    k_wprep<<<216, 256>>>(f1w, f2w, qkvw, pw);
    k_win<<<2048, 512, WIN_SMEM>>>(x, mask, n1g, n1b, qkvb, pb);
    k_mlpT<<<3136, 512, M2_SMEM>>>(n2g, n2b, f1b, f2b, out);
}

// round 11
// speedup vs baseline: 5.2480x; 1.0358x over previous
#include <cuda_runtime.h>
#include <cuda_bf16.h>
#include <math.h>
#include <stdint.h>

#define DEV_INLINE __device__ __forceinline__

// ---------------- static scratch (allocation-free rule) ----------------
__device__ float g_x2[200704 * 96];                  // x + attn branch
__device__ float g_bias[4 * 98 * 98];                // rel-pos bias table
// pre-swizzled smem-layout weight images (flat uint4-copyable)
__device__ __align__(16) uint32_t g_wqi[288 * 52];   // qkv^T bf16, stride 52
__device__ __align__(16) uint32_t g_pwi[96 * 52];    // proj^T bf16, stride 52
__device__ __align__(16) uint32_t g_w1c[3 * 128 * 52]; // fc1^T chunks, stride 52
__device__ __align__(16) uint32_t g_w2c[3 * 96 * 68];  // fc2^T chunks, stride 68

DEV_INLINE float warp_sum(float v) {
    #pragma unroll
    for (int o = 16; o; o >>= 1) v += __shfl_xor_sync(0xffffffffu, v, o);
    return v;
}
DEV_INLINE uint32_t pack_bf(float a, float b) {
    uint32_t lo = __bfloat16_as_ushort(__float2bfloat16(a));
    uint32_t hi = __bfloat16_as_ushort(__float2bfloat16(b));
    return (hi << 16) | lo;
}
DEV_INLINE void mma16816(float* d, const uint32_t* a, const uint32_t* b) {
    asm volatile("mma.sync.aligned.m16n8k16.row.col.f32.bf16.bf16.f32 "
        "{%0,%1,%2,%3}, {%4,%5,%6,%7}, {%8,%9}, {%0,%1,%2,%3};"
        : "+f"(d[0]), "+f"(d[1]), "+f"(d[2]), "+f"(d[3])
        : "r"(a[0]), "r"(a[1]), "r"(a[2]), "r"(a[3]), "r"(b[0]), "r"(b[1]));
}

DEV_INLINE int spat_base(int B_, int i) {
    int b = B_ >> 8, rem = B_ & 255;
    int wd = rem >> 6, wh = (rem >> 3) & 7, ww = rem & 7;
    int td = i / 49, r = i - td * 49;
    int th = r / 7, tw = r - th * 7;
    int d = (wd * 2 + td + 1) & 7;
    int hh = wh * 7 + th + 3; if (hh >= 56) hh -= 56;
    int w2 = ww * 7 + tw + 3; if (w2 >= 56) w2 -= 56;
    return (((b * 8 + d) * 56 + hh) * 56 + w2) * 96;
}

// ---------------- kernel 0: rel-pos bias table ----------------
__global__ void k_bias(const float* __restrict__ rpb) {
    int i = blockIdx.x, j = threadIdx.x;
    if (j >= 98) return;
    int di = i / 49, ri = i - di * 49, hi = ri / 7, wi = ri - hi * 7;
    int dj = j / 49, rj = j - dj * 49, hj = rj / 7, wj = rj - hj * 7;
    int r = (di - dj + 1) * 169 + (hi - hj + 6) * 13 + (wi - wj + 6);
    #pragma unroll
    for (int h = 0; h < 4; ++h)
        g_bias[h * 9604 + i * 98 + j] = rpb[r * 4 + h];
}

// ---------------- kernel: weight transposes into smem-layout images ----------------
// segments: [0,14976) wq | [14976,19968) pw | [19968,39936) w1 chunks | [39936,59520) w2 chunks
__global__ void k_wprep(const float* __restrict__ f1w, const float* __restrict__ f2w,
                        const float* __restrict__ qw, const float* __restrict__ pw) {
    int gidx = blockIdx.x * 256 + threadIdx.x;
    if (gidx < 14976) {
        int n = gidx / 52, j = gidx - n * 52;
        g_wqi[gidx] = (j < 48) ? pack_bf(qw[(2 * j) * 288 + n], qw[(2 * j + 1) * 288 + n]) : 0u;
    } else if (gidx < 19968) {
        int i = gidx - 14976;
        int n = i / 52, j = i - n * 52;
        g_pwi[i] = (j < 48) ? pack_bf(pw[(2 * j) * 96 + n], pw[(2 * j + 1) * 96 + n]) : 0u;
    } else if (gidx < 39936) {
        int i = gidx - 19968;
        int c = i / 6656, r = i - c * 6656;
        int n = r / 52, j = r - n * 52;
        g_w1c[i] = (j < 48) ? pack_bf(f1w[(2 * j) * 384 + c * 128 + n],
                                      f1w[(2 * j + 1) * 384 + c * 128 + n]) : 0u;
    } else if (gidx < 59520) {
        int i = gidx - 39936;
        int c = i / 6528, r = i - c * 6528;
        int n = r / 68, jj = r - n * 68;
        int kk = c * 64 + jj;
        g_w2c[i] = (jj < 64) ? pack_bf(f2w[(2 * kk) * 96 + n], f2w[(2 * kk + 1) * 96 + n]) : 0u;
    }
}

// ---------------- fused window kernel: HMMA + register softmax ----------------
// u32 offsets in dynamic smem:
#define Q_OFF   0              // 4 heads x 112 x 20
#define K_OFF   8960
#define V_OFF   17920          // 4 heads x 32 dims x 60 (token pairs)
#define AT_OFF  25600          // 112 x 52
#define RO_OFF  31424          // 112 ints
#define B3_OFF  31536          // 288 floats
#define RB      31824
#define XL_OFF  RB             // 112 x 52 (phase A)
#define WQ_OFF  (RB + 5824)    // 288 x 52 (phase A)
#define PO_OFF  RB             // 112 x 100 f32 (phase C out)
#define WP2_OFF (RB + 11200)   // 96 x 52 (phase C weights)
#define WIN_U32 52624
#define WIN_SMEM (WIN_U32 * 4)

__global__ __launch_bounds__(512, 1) void k_win(const float* __restrict__ x,
                                                const float* __restrict__ mask,
                                                const float* __restrict__ n1g,
                                                const float* __restrict__ n1b,
                                                const float* __restrict__ qb,
                                                const float* __restrict__ pb) {
    extern __shared__ uint32_t sm32[];
    float* smF = (float*)sm32;
    int* ro = (int*)(sm32 + RO_OFF);
    float* bias3 = smF + B3_OFF;
    const int tid = threadIdx.x, B_ = blockIdx.x;
    const int wid = tid >> 5, lane = tid & 31;
    const int g = lane >> 2, t = lane & 3;
    const int rem = B_ & 255;
    const bool hasmask = ((rem >> 6) == 3) | (((rem >> 3) & 7) == 7) | ((rem & 7) == 7);

    // ---- phase A0: indices / weights (flat uint4) / bias / padding ----
    if (tid < 98) ro[tid] = spat_base(B_, tid);
    for (int i = tid; i < 288; i += 512) bias3[i] = qb[i];
    {
        uint4* dst = (uint4*)(sm32 + WQ_OFF);
        const uint4* src = (const uint4*)g_wqi;
        for (int i = tid; i < 3744; i += 512) dst[i] = src[i];
    }
    for (int i = tid; i < 14 * 52; i += 512)            // zero xln pad rows
        sm32[XL_OFF + (98 + i / 52) * 52 + (i % 52)] = 0;
    for (int i = tid; i < 4 * 112 * 4; i += 512) {      // zero q/k dim-pad cols 12..15
        int h = i / 448, r = (i >> 2) % 112, c = 12 + (i & 3);
        sm32[Q_OFF + h * 2240 + r * 20 + c] = 0;
        sm32[K_OFF + h * 2240 + r * 20 + c] = 0;
    }
    __syncthreads();

    // ---- phase A1: LN1 -> bf16 A image (rows 0..97) ----
    {
        float g0 = n1g[lane], g1 = n1g[lane + 32], g2 = n1g[lane + 64];
        float b0 = n1b[lane], b1 = n1b[lane + 32], b2 = n1b[lane + 64];
        for (int tr = wid; tr < 98; tr += 16) {
            const float* xr = x + ro[tr];
            float v0 = xr[lane], v1 = xr[lane + 32], v2 = xr[lane + 64];
            float mean = warp_sum(v0 + v1 + v2) * (1.f / 96.f);
            float d0 = v0 - mean, d1 = v1 - mean, d2 = v2 - mean;
            float var = warp_sum(d0 * d0 + d1 * d1 + d2 * d2) * (1.f / 96.f);
            float rstd = rsqrtf(var + 1e-5f);
            float y0 = d0 * rstd * g0 + b0;
            float y1 = d1 * rstd * g1 + b1;
            float y2 = d2 * rstd * g2 + b2;
            float o0 = __shfl_xor_sync(0xffffffffu, y0, 1);
            float o1 = __shfl_xor_sync(0xffffffffu, y1, 1);
            float o2 = __shfl_xor_sync(0xffffffffu, y2, 1);
            if ((lane & 1) == 0) {
                int j = lane >> 1;
                sm32[XL_OFF + tr * 52 + j]      = pack_bf(y0, o0);
                sm32[XL_OFF + tr * 52 + j + 16] = pack_bf(y1, o1);
                sm32[XL_OFF + tr * 52 + j + 32] = pack_bf(y2, o2);
            }
        }
    }
    __syncthreads();

    // ---- phase A2: QKV mma (112x288, K=96), warps 0..13 ----
    if (wid < 14) {
        const int mt = wid >> 1, nh = wid & 1;
        const int m0 = mt * 16;
        for (int p = 0; p < 2; ++p) {
            float acc[9][4];
            #pragma unroll
            for (int f = 0; f < 9; ++f)
                #pragma unroll
                for (int q = 0; q < 4; ++q) acc[f][q] = 0.f;
            #pragma unroll
            for (int k = 0; k < 6; ++k) {
                int k8 = k * 8;
                uint32_t a[4];
                a[0] = sm32[XL_OFF + (m0 + g) * 52 + k8 + t];
                a[1] = sm32[XL_OFF + (m0 + g + 8) * 52 + k8 + t];
                a[2] = sm32[XL_OFF + (m0 + g) * 52 + k8 + t + 4];
                a[3] = sm32[XL_OFF + (m0 + g + 8) * 52 + k8 + t + 4];
                #pragma unroll
                for (int f = 0; f < 9; ++f) {
                    int nr = nh * 144 + p * 72 + f * 8 + g;
                    uint32_t b[2];
                    b[0] = sm32[WQ_OFF + nr * 52 + k8 + t];
                    b[1] = sm32[WQ_OFF + nr * 52 + k8 + t + 4];
                    mma16816(acc[f], a, b);
                }
            }
            #pragma unroll
            for (int f = 0; f < 9; ++f) {
                int col = nh * 144 + p * 72 + f * 8 + 2 * t;
                float bb0 = bias3[col], bb1 = bias3[col + 1];
                float v0 = acc[f][0] + bb0, v1 = acc[f][1] + bb1;
                float v2 = acc[f][2] + bb0, v3 = acc[f][3] + bb1;
                int which = col / 96, cc = col - which * 96;
                int head = cc / 24, cd = cc - head * 24;
                int r0 = m0 + g, r1 = m0 + g + 8;
                if (which == 0) {
                    const float sc = 0.20412414523193154f;
                    sm32[Q_OFF + head * 2240 + r0 * 20 + (cd >> 1)] = pack_bf(v0 * sc, v1 * sc);
                    sm32[Q_OFF + head * 2240 + r1 * 20 + (cd >> 1)] = pack_bf(v2 * sc, v3 * sc);
                } else if (which == 1) {
                    sm32[K_OFF + head * 2240 + r0 * 20 + (cd >> 1)] = pack_bf(v0, v1);
                    sm32[K_OFF + head * 2240 + r1 * 20 + (cd >> 1)] = pack_bf(v2, v3);
                } else {
                    __nv_bfloat16* vb = (__nv_bfloat16*)(sm32 + V_OFF + head * 1920);
                    vb[cd * 120 + r0]       = __float2bfloat16(v0);
                    vb[(cd + 1) * 120 + r0] = __float2bfloat16(v1);
                    vb[cd * 120 + r1]       = __float2bfloat16(v2);
                    vb[(cd + 1) * 120 + r1] = __float2bfloat16(v3);
                }
            }
        }
    }
    __syncthreads();

    // ---- phase B: attention, register softmax, NO barriers ----
    if (wid < 14) {
        const int hloc = wid & 1, mtB = wid >> 1;
        const int m0B = mtB * 16;
        const float* mk = mask + rem * 9604;
        const int r0 = m0B + g, r1 = r0 + 8;
        for (int p = 0; p < 2; ++p) {
            const int h = p * 2 + hloc;
            const float* bi = g_bias + h * 9604;
            const uint32_t* qh = sm32 + Q_OFF + h * 2240;
            const uint32_t* kh = sm32 + K_OFF + h * 2240;
            const uint32_t* vh = sm32 + V_OFF + h * 1920;

            // scores: 16 x 112, K=32
            float c[14][4];
            #pragma unroll
            for (int nt = 0; nt < 14; ++nt)
                #pragma unroll
                for (int q = 0; q < 4; ++q) c[nt][q] = 0.f;
            #pragma unroll
            for (int kt = 0; kt < 2; ++kt) {
                int k8 = kt * 8;
                uint32_t a[4];
                a[0] = qh[r0 * 20 + k8 + t];
                a[1] = qh[r1 * 20 + k8 + t];
                a[2] = qh[r0 * 20 + k8 + t + 4];
                a[3] = qh[r1 * 20 + k8 + t + 4];
                #pragma unroll
                for (int nt = 0; nt < 14; ++nt) {
                    uint32_t b[2];
                    b[0] = kh[(nt * 8 + g) * 20 + k8 + t];
                    b[1] = kh[(nt * 8 + g) * 20 + k8 + t + 4];
                    mma16816(c[nt], a, b);
                }
            }
            // bias (+ mask only for boundary windows); mask out pad cols
            #pragma unroll
            for (int nt = 0; nt < 14; ++nt) {
                int col = nt * 8 + 2 * t;
                if (col < 98) {
                    if (r0 < 98) {
                        float2 bv = *(const float2*)(bi + r0 * 98 + col);
                        c[nt][0] += bv.x; c[nt][1] += bv.y;
                    }
                    if (r1 < 98) {
                        float2 bv = *(const float2*)(bi + r1 * 98 + col);
                        c[nt][2] += bv.x; c[nt][3] += bv.y;
                    }
                    if (hasmask) {
                        if (r0 < 98) {
                            float2 mv = *(const float2*)(mk + r0 * 98 + col);
                            c[nt][0] += mv.x; c[nt][1] += mv.y;
                        }
                        if (r1 < 98) {
                            float2 mv = *(const float2*)(mk + r1 * 98 + col);
                            c[nt][2] += mv.x; c[nt][3] += mv.y;
                        }
                    }
                } else {
                    c[nt][0] = c[nt][1] = c[nt][2] = c[nt][3] = -1e30f;
                }
            }
            // register softmax (rows r0, r1)
            float mx0 = -1e30f, mx1 = -1e30f;
            #pragma unroll
            for (int nt = 0; nt < 14; ++nt) {
                mx0 = fmaxf(mx0, fmaxf(c[nt][0], c[nt][1]));
                mx1 = fmaxf(mx1, fmaxf(c[nt][2], c[nt][3]));
            }
            mx0 = fmaxf(mx0, __shfl_xor_sync(0xffffffffu, mx0, 1));
            mx0 = fmaxf(mx0, __shfl_xor_sync(0xffffffffu, mx0, 2));
            mx1 = fmaxf(mx1, __shfl_xor_sync(0xffffffffu, mx1, 1));
            mx1 = fmaxf(mx1, __shfl_xor_sync(0xffffffffu, mx1, 2));
            float s0 = 0.f, s1 = 0.f;
            #pragma unroll
            for (int nt = 0; nt < 14; ++nt) {
                c[nt][0] = __expf(c[nt][0] - mx0); s0 += c[nt][0];
                c[nt][1] = __expf(c[nt][1] - mx0); s0 += c[nt][1];
                c[nt][2] = __expf(c[nt][2] - mx1); s1 += c[nt][2];
                c[nt][3] = __expf(c[nt][3] - mx1); s1 += c[nt][3];
            }
            s0 += __shfl_xor_sync(0xffffffffu, s0, 1);
            s0 += __shfl_xor_sync(0xffffffffu, s0, 2);
            s1 += __shfl_xor_sync(0xffffffffu, s1, 1);
            s1 += __shfl_xor_sync(0xffffffffu, s1, 2);
            float inv0 = 1.f / s0, inv1 = 1.f / s1;

            // PV: P stays in registers (C-frag -> A-frag), V as B operand
            float pv[3][4];
            #pragma unroll
            for (int f = 0; f < 3; ++f)
                #pragma unroll
                for (int q = 0; q < 4; ++q) pv[f][q] = 0.f;
            #pragma unroll
            for (int kt2 = 0; kt2 < 7; ++kt2) {
                uint32_t a[4];
                a[0] = pack_bf(c[2 * kt2][0] * inv0, c[2 * kt2][1] * inv0);
                a[1] = pack_bf(c[2 * kt2][2] * inv1, c[2 * kt2][3] * inv1);
                a[2] = pack_bf(c[2 * kt2 + 1][0] * inv0, c[2 * kt2 + 1][1] * inv0);
                a[3] = pack_bf(c[2 * kt2 + 1][2] * inv1, c[2 * kt2 + 1][3] * inv1);
                int k8 = kt2 * 8;
                #pragma unroll
                for (int f = 0; f < 3; ++f) {
                    uint32_t b[2];
                    b[0] = vh[(f * 8 + g) * 60 + k8 + t];
                    b[1] = vh[(f * 8 + g) * 60 + k8 + t + 4];
                    mma16816(pv[f], a, b);
                }
            }
            #pragma unroll
            for (int f = 0; f < 3; ++f) {
                int col = f * 8 + 2 * t;     // 0..22
                sm32[AT_OFF + r0 * 52 + h * 12 + (col >> 1)] = pack_bf(pv[f][0], pv[f][1]);
                sm32[AT_OFF + r1 * 52 + h * 12 + (col >> 1)] = pack_bf(pv[f][2], pv[f][3]);
            }
        }
    } else {
        // warps 14,15: prefetch proj weights (flat uint4) + bias
        uint4* dst = (uint4*)(sm32 + WP2_OFF);
        const uint4* src = (const uint4*)g_pwi;
        for (int i = tid - 448; i < 1248; i += 64) dst[i] = src[i];
        for (int i = tid - 448; i < 96; i += 64) bias3[i] = pb[i];
    }
    __syncthreads();

    // ---- phase C: proj (112x96, K=96) ----
    if (wid < 14) {
        const int mtC = wid >> 1, nhC = wid & 1;
        const int m0C = mtC * 16;
        float acc[6][4];
        #pragma unroll
        for (int f = 0; f < 6; ++f)
            #pragma unroll
            for (int q = 0; q < 4; ++q) acc[f][q] = 0.f;
        #pragma unroll
        for (int k = 0; k < 6; ++k) {
            int k8 = k * 8;
            uint32_t a[4];
            a[0] = sm32[AT_OFF + (m0C + g) * 52 + k8 + t];
            a[1] = sm32[AT_OFF + (m0C + g + 8) * 52 + k8 + t];
            a[2] = sm32[AT_OFF + (m0C + g) * 52 + k8 + t + 4];
            a[3] = sm32[AT_OFF + (m0C + g + 8) * 52 + k8 + t + 4];
            #pragma unroll
            for (int f = 0; f < 6; ++f) {
                int nr = nhC * 48 + f * 8 + g;
                uint32_t b[2];
                b[0] = sm32[WP2_OFF + nr * 52 + k8 + t];
                b[1] = sm32[WP2_OFF + nr * 52 + k8 + t + 4];
                mma16816(acc[f], a, b);
            }
        }
        #pragma unroll
        for (int f = 0; f < 6; ++f) {
            int col = nhC * 48 + f * 8 + 2 * t;
            *(float2*)(smF + PO_OFF + (m0C + g) * 100 + col)     = make_float2(acc[f][0], acc[f][1]);
            *(float2*)(smF + PO_OFF + (m0C + g + 8) * 100 + col) = make_float2(acc[f][2], acc[f][3]);
        }
    }
    __syncthreads();

    // ---- residual + scatter (div-free incremental indexing) ----
    {
        int row = tid / 96, col = tid - row * 96;
        for (int i = tid; i < 98 * 96; i += 512) {
            int base = ro[row];
            g_x2[base + col] = x[base + col] + smF[PO_OFF + row * 100 + col] + bias3[col];
            col += 32; row += 5;
            if (col >= 96) { col -= 96; row += 1; }
        }
    }
}

// ---------------- fused MLP: 64 tokens/block, 2 CTAs/SM ----------------
#define M2_A    0              // 64 x 52 (bf16 A); overlaid by OB (f32, stride 100) post-fc2
#define M2_HID  3328           // 64 x 196
#define M2_WB   15872          // 6656 (W1 chunk 128x52 / W2 chunk 96x68)
#define M2_B1   22528          // 384 f32
#define M2_B2   22912          // 96 f32
#define M2_U32  23040
#define M2_SMEM (M2_U32 * 4)

__global__ __launch_bounds__(512, 2) void k_mlpT(const float* __restrict__ n2g,
                                                 const float* __restrict__ n2b,
                                                 const float* __restrict__ f1b,
                                                 const float* __restrict__ f2b,
                                                 float* __restrict__ out) {
    extern __shared__ uint32_t smm[];
    float* smmF = (float*)smm;
    float* sf1b = smmF + M2_B1;
    float* sf2b = smmF + M2_B2;
    const int tid = threadIdx.x, wid = tid >> 5, lane = tid & 31;
    const int g = lane >> 2, t = lane & 3;
    const int tok0 = blockIdx.x * 64;

    if (tid < 384) sf1b[tid] = f1b[tid];
    if (tid >= 384 && tid < 480) sf2b[tid - 384] = f2b[tid - 384];

    // ---- LN2 -> bf16 A (stride 52 u32) ----
    {
        float g0 = n2g[lane], g1 = n2g[lane + 32], g2 = n2g[lane + 64];
        float b0 = n2b[lane], b1 = n2b[lane + 32], b2 = n2b[lane + 64];
        for (int tr = wid; tr < 64; tr += 16) {
            const float* xr = g_x2 + (tok0 + tr) * 96;
            float v0 = xr[lane], v1 = xr[lane + 32], v2 = xr[lane + 64];
            float mean = warp_sum(v0 + v1 + v2) * (1.f / 96.f);
            float d0 = v0 - mean, d1 = v1 - mean, d2 = v2 - mean;
            float var = warp_sum(d0 * d0 + d1 * d1 + d2 * d2) * (1.f / 96.f);
            float rstd = rsqrtf(var + 1e-5f);
            float y0 = d0 * rstd * g0 + b0;
            float y1 = d1 * rstd * g1 + b1;
            float y2 = d2 * rstd * g2 + b2;
            float o0 = __shfl_xor_sync(0xffffffffu, y0, 1);
            float o1 = __shfl_xor_sync(0xffffffffu, y1, 1);
            float o2 = __shfl_xor_sync(0xffffffffu, y2, 1);
            if ((lane & 1) == 0) {
                int j = lane >> 1;
                smm[M2_A + tr * 52 + j]      = pack_bf(y0, o0);
                smm[M2_A + tr * 52 + j + 16] = pack_bf(y1, o1);
                smm[M2_A + tr * 52 + j + 32] = pack_bf(y2, o2);
            }
        }
    }

    const int mt = wid & 3, nq = wid >> 2;   // 4 mtiles x 4 n-quarters
    const int mrow = mt * 16;

    // ---- fc1 (64x384, K=96): 3 n-chunks of 128 (flat uint4 staging) ----
    for (int c = 0; c < 3; ++c) {
        __syncthreads();                      // A ready (c=0) / prior WB reads done
        {
            uint4* dst = (uint4*)(smm + M2_WB);
            const uint4* src = (const uint4*)(g_w1c + c * 6656);
            for (int i = tid; i < 1664; i += 512) dst[i] = src[i];
        }
        __syncthreads();
        float acc[4][4];
        #pragma unroll
        for (int f = 0; f < 4; ++f)
            #pragma unroll
            for (int q = 0; q < 4; ++q) acc[f][q] = 0.f;
        #pragma unroll
        for (int k = 0; k < 6; ++k) {
            int k8 = k * 8;
            uint32_t a[4];
            a[0] = smm[M2_A + (mrow + g) * 52 + k8 + t];
            a[1] = smm[M2_A + (mrow + g + 8) * 52 + k8 + t];
            a[2] = smm[M2_A + (mrow + g) * 52 + k8 + t + 4];
            a[3] = smm[M2_A + (mrow + g + 8) * 52 + k8 + t + 4];
            #pragma unroll
            for (int f = 0; f < 4; ++f) {
                int nr = nq * 32 + f * 8 + g;
                uint32_t b[2];
                b[0] = smm[M2_WB + nr * 52 + k8 + t];
                b[1] = smm[M2_WB + nr * 52 + k8 + t + 4];
                mma16816(acc[f], a, b);
            }
        }
        #pragma unroll
        for (int f = 0; f < 4; ++f) {
            int gcol = c * 128 + nq * 32 + f * 8 + 2 * t;
            float u0 = acc[f][0] + sf1b[gcol];
            float u1 = acc[f][1] + sf1b[gcol + 1];
            float u2 = acc[f][2] + sf1b[gcol];
            float u3 = acc[f][3] + sf1b[gcol + 1];
            float e0 = 0.5f * u0 * (1.f + erff(u0 * 0.70710678118654752f));
            float e1 = 0.5f * u1 * (1.f + erff(u1 * 0.70710678118654752f));
            float e2 = 0.5f * u2 * (1.f + erff(u2 * 0.70710678118654752f));
            float e3 = 0.5f * u3 * (1.f + erff(u3 * 0.70710678118654752f));
            int hc = gcol >> 1;
            smm[M2_HID + (mrow + g) * 196 + hc]     = pack_bf(e0, e1);
            smm[M2_HID + (mrow + g + 8) * 196 + hc] = pack_bf(e2, e3);
        }
    }

    // ---- fc2 (64x96, K=384): 3 k-chunks of 128 (flat uint4 staging) ----
    float acc2[3][4];
    #pragma unroll
    for (int f = 0; f < 3; ++f)
        #pragma unroll
        for (int q = 0; q < 4; ++q) acc2[f][q] = 0.f;
    for (int c = 0; c < 3; ++c) {
        __syncthreads();                      // hid writes done / prior WB reads done
        {
            uint4* dst = (uint4*)(smm + M2_WB);
            const uint4* src = (const uint4*)(g_w2c + c * 6528);
            for (int i = tid; i < 1632; i += 512) dst[i] = src[i];
        }
        __syncthreads();
        #pragma unroll
        for (int k = 0; k < 8; ++k) {
            int k8 = k * 8;
            uint32_t a[4];
            a[0] = smm[M2_HID + (mrow + g) * 196 + c * 64 + k8 + t];
            a[1] = smm[M2_HID + (mrow + g + 8) * 196 + c * 64 + k8 + t];
            a[2] = smm[M2_HID + (mrow + g) * 196 + c * 64 + k8 + t + 4];
            a[3] = smm[M2_HID + (mrow + g + 8) * 196 + c * 64 + k8 + t + 4];
            #pragma unroll
            for (int f = 0; f < 3; ++f) {
                int nr = nq * 24 + f * 8 + g;
                uint32_t b[2];
                b[0] = smm[M2_WB + nr * 68 + k8 + t];
                b[1] = smm[M2_WB + nr * 68 + k8 + t + 4];
                mma16816(acc2[f], a, b);
            }
        }
    }
    __syncthreads();                          // all fc2 reads done before OB overlay

    #pragma unroll
    for (int f = 0; f < 3; ++f) {
        int col = nq * 24 + f * 8 + 2 * t;    // 0..94
        *(float2*)(smmF + (mrow + g) * 100 + col)     = make_float2(acc2[f][0], acc2[f][1]);
        *(float2*)(smmF + (mrow + g + 8) * 100 + col) = make_float2(acc2[f][2], acc2[f][3]);
    }
    __syncthreads();

    // ---- writeout: out = x2 + fc2 + bias (div-free) ----
    {
        const float* x2t = g_x2 + tok0 * 96;
        float* outt = out + tok0 * 96;
        int row = tid / 96, col = tid - row * 96;
        for (int i = tid; i < 6144; i += 512) {
            outt[i] = smmF[row * 100 + col] + sf2b[col] + x2t[i];
            col += 32; row += 5;
            if (col >= 96) { col -= 96; row += 1; }
        }
    }
}

// ---------------- launch ----------------
extern "C" void kernel_launch(void* const* d_in, const int* in_sizes, int n_in,
                              void* d_out, int out_size) {
    const float* x    = (const float*)d_in[0];
    const float* mask = (const float*)d_in[1];
    const float* n1g  = (const float*)d_in[2];
    const float* n1b  = (const float*)d_in[3];
    const float* qkvw = (const float*)d_in[4];
    const float* qkvb = (const float*)d_in[5];
    const float* rpb  = (const float*)d_in[6];
    const float* pw   = (const float*)d_in[7];
    const float* pb   = (const float*)d_in[8];
    const float* n2g  = (const float*)d_in[9];
    const float* n2b  = (const float*)d_in[10];
    const float* f1w  = (const float*)d_in[11];
    const float* f1b  = (const float*)d_in[12];
    const float* f2w  = (const float*)d_in[13];
    const float* f2b  = (const float*)d_in[14];
    float* out = (float*)d_out;

    cudaFuncSetAttribute(k_win,  cudaFuncAttributeMaxDynamicSharedMemorySize, WIN_SMEM);
    cudaFuncSetAttribute(k_mlpT, cudaFuncAttributeMaxDynamicSharedMemorySize, M2_SMEM);

    k_bias<<<98, 128>>>(rpb);
    k_wprep<<<233, 256>>>(f1w, f2w, qkvw, pw);
    k_win<<<2048, 512, WIN_SMEM>>>(x, mask, n1g, n1b, qkvb, pb);
    k_mlpT<<<3136, 512, M2_SMEM>>>(n2g, n2b, f1b, f2b, out);
}

// round 12
// speedup vs baseline: 5.3791x; 1.0250x over previous
#include <cuda_runtime.h>
#include <cuda_bf16.h>
#include <math.h>
#include <stdint.h>

#define DEV_INLINE __device__ __forceinline__

// ---------------- static scratch (allocation-free rule) ----------------
__device__ float g_x2[200704 * 96];                  // x + attn branch
__device__ float g_bias[4 * 98 * 98];                // rel-pos bias table
// pre-swizzled smem-layout weight images (flat uint4-copyable)
__device__ __align__(16) uint32_t g_wqi[288 * 52];   // qkv^T bf16, stride 52
__device__ __align__(16) uint32_t g_pwi[96 * 52];    // proj^T bf16, stride 52
__device__ __align__(16) uint32_t g_w1c[3 * 128 * 52]; // fc1^T chunks, stride 52
__device__ __align__(16) uint32_t g_w2c[3 * 96 * 68];  // fc2^T chunks, stride 68

DEV_INLINE float warp_sum(float v) {
    #pragma unroll
    for (int o = 16; o; o >>= 1) v += __shfl_xor_sync(0xffffffffu, v, o);
    return v;
}
DEV_INLINE uint32_t pack_bf(float a, float b) {
    uint32_t lo = __bfloat16_as_ushort(__float2bfloat16(a));
    uint32_t hi = __bfloat16_as_ushort(__float2bfloat16(b));
    return (hi << 16) | lo;
}
DEV_INLINE void mma16816(float* d, const uint32_t* a, const uint32_t* b) {
    asm volatile("mma.sync.aligned.m16n8k16.row.col.f32.bf16.bf16.f32 "
        "{%0,%1,%2,%3}, {%4,%5,%6,%7}, {%8,%9}, {%0,%1,%2,%3};"
        : "+f"(d[0]), "+f"(d[1]), "+f"(d[2]), "+f"(d[3])
        : "r"(a[0]), "r"(a[1]), "r"(a[2]), "r"(a[3]), "r"(b[0]), "r"(b[1]));
}
DEV_INLINE uint32_t cvta_sm(const void* p) {
    return (uint32_t)__cvta_generic_to_shared(p);
}
DEV_INLINE void ldsm_x4(uint32_t* r, uint32_t addr) {
    asm volatile("ldmatrix.sync.aligned.m8n8.x4.shared.b16 {%0,%1,%2,%3}, [%4];"
        : "=r"(r[0]), "=r"(r[1]), "=r"(r[2]), "=r"(r[3]) : "r"(addr));
}
DEV_INLINE void ldsm_x2(uint32_t* r, uint32_t addr) {
    asm volatile("ldmatrix.sync.aligned.m8n8.x2.shared.b16 {%0,%1}, [%2];"
        : "=r"(r[0]), "=r"(r[1]) : "r"(addr));
}

DEV_INLINE int spat_base(int B_, int i) {
    int b = B_ >> 8, rem = B_ & 255;
    int wd = rem >> 6, wh = (rem >> 3) & 7, ww = rem & 7;
    int td = i / 49, r = i - td * 49;
    int th = r / 7, tw = r - th * 7;
    int d = (wd * 2 + td + 1) & 7;
    int hh = wh * 7 + th + 3; if (hh >= 56) hh -= 56;
    int w2 = ww * 7 + tw + 3; if (w2 >= 56) w2 -= 56;
    return (((b * 8 + d) * 56 + hh) * 56 + w2) * 96;
}

// ---------------- kernel 0: rel-pos bias table ----------------
__global__ void k_bias(const float* __restrict__ rpb) {
    int i = blockIdx.x, j = threadIdx.x;
    if (j >= 98) return;
    int di = i / 49, ri = i - di * 49, hi = ri / 7, wi = ri - hi * 7;
    int dj = j / 49, rj = j - dj * 49, hj = rj / 7, wj = rj - hj * 7;
    int r = (di - dj + 1) * 169 + (hi - hj + 6) * 13 + (wi - wj + 6);
    #pragma unroll
    for (int h = 0; h < 4; ++h)
        g_bias[h * 9604 + i * 98 + j] = rpb[r * 4 + h];
}

// ---------------- kernel: weight transposes into smem-layout images ----------------
__global__ void k_wprep(const float* __restrict__ f1w, const float* __restrict__ f2w,
                        const float* __restrict__ qw, const float* __restrict__ pw) {
    int gidx = blockIdx.x * 256 + threadIdx.x;
    if (gidx < 14976) {
        int n = gidx / 52, j = gidx - n * 52;
        g_wqi[gidx] = (j < 48) ? pack_bf(qw[(2 * j) * 288 + n], qw[(2 * j + 1) * 288 + n]) : 0u;
    } else if (gidx < 19968) {
        int i = gidx - 14976;
        int n = i / 52, j = i - n * 52;
        g_pwi[i] = (j < 48) ? pack_bf(pw[(2 * j) * 96 + n], pw[(2 * j + 1) * 96 + n]) : 0u;
    } else if (gidx < 39936) {
        int i = gidx - 19968;
        int c = i / 6656, r = i - c * 6656;
        int n = r / 52, j = r - n * 52;
        g_w1c[i] = (j < 48) ? pack_bf(f1w[(2 * j) * 384 + c * 128 + n],
                                      f1w[(2 * j + 1) * 384 + c * 128 + n]) : 0u;
    } else if (gidx < 59520) {
        int i = gidx - 39936;
        int c = i / 6528, r = i - c * 6528;
        int n = r / 68, jj = r - n * 68;
        int kk = c * 64 + jj;
        g_w2c[i] = (jj < 64) ? pack_bf(f2w[(2 * kk) * 96 + n], f2w[(2 * kk + 1) * 96 + n]) : 0u;
    }
}

// ---------------- fused window kernel: HMMA + ldmatrix + register softmax ----------------
#define Q_OFF   0              // 4 heads x 112 x 20
#define K_OFF   8960
#define V_OFF   17920          // 4 heads x 32 dims x 60 (token pairs)
#define AT_OFF  25600          // 112 x 52
#define RO_OFF  31424          // 112 ints
#define B3_OFF  31536          // 288 floats
#define RB      31824
#define XL_OFF  RB             // 112 x 52 (phase A)
#define WQ_OFF  (RB + 5824)    // 288 x 52 (phase A)
#define PO_OFF  RB             // 112 x 100 f32 (phase C out)
#define WP2_OFF (RB + 11200)   // 96 x 52 (phase C weights)
#define WIN_U32 52624
#define WIN_SMEM (WIN_U32 * 4)

__global__ __launch_bounds__(512, 1) void k_win(const float* __restrict__ x,
                                                const float* __restrict__ mask,
                                                const float* __restrict__ n1g,
                                                const float* __restrict__ n1b,
                                                const float* __restrict__ qb,
                                                const float* __restrict__ pb) {
    extern __shared__ uint32_t sm32[];
    float* smF = (float*)sm32;
    int* ro = (int*)(sm32 + RO_OFF);
    float* bias3 = smF + B3_OFF;
    const int tid = threadIdx.x, B_ = blockIdx.x;
    const int wid = tid >> 5, lane = tid & 31;
    const int g = lane >> 2, t = lane & 3;
    const int l7 = lane & 7, lqr = (lane >> 3) & 1, lqc = lane >> 4;   // ldsm lane decode
    const int rem = B_ & 255;
    const bool hasmask = ((rem >> 6) == 3) | (((rem >> 3) & 7) == 7) | ((rem & 7) == 7);
    const uint32_t sb = cvta_sm(sm32);

    // ---- phase A0 ----
    if (tid < 98) ro[tid] = spat_base(B_, tid);
    for (int i = tid; i < 288; i += 512) bias3[i] = qb[i];
    {
        uint4* dst = (uint4*)(sm32 + WQ_OFF);
        const uint4* src = (const uint4*)g_wqi;
        for (int i = tid; i < 3744; i += 512) dst[i] = src[i];
    }
    for (int i = tid; i < 14 * 52; i += 512)
        sm32[XL_OFF + (98 + i / 52) * 52 + (i % 52)] = 0;
    for (int i = tid; i < 4 * 112 * 4; i += 512) {
        int h = i / 448, r = (i >> 2) % 112, c = 12 + (i & 3);
        sm32[Q_OFF + h * 2240 + r * 20 + c] = 0;
        sm32[K_OFF + h * 2240 + r * 20 + c] = 0;
    }
    __syncthreads();

    // ---- phase A1: LN1 -> bf16 A image ----
    {
        float g0 = n1g[lane], g1 = n1g[lane + 32], g2 = n1g[lane + 64];
        float b0 = n1b[lane], b1 = n1b[lane + 32], b2 = n1b[lane + 64];
        for (int tr = wid; tr < 98; tr += 16) {
            const float* xr = x + ro[tr];
            float v0 = xr[lane], v1 = xr[lane + 32], v2 = xr[lane + 64];
            float mean = warp_sum(v0 + v1 + v2) * (1.f / 96.f);
            float d0 = v0 - mean, d1 = v1 - mean, d2 = v2 - mean;
            float var = warp_sum(d0 * d0 + d1 * d1 + d2 * d2) * (1.f / 96.f);
            float rstd = rsqrtf(var + 1e-5f);
            float y0 = d0 * rstd * g0 + b0;
            float y1 = d1 * rstd * g1 + b1;
            float y2 = d2 * rstd * g2 + b2;
            float o0 = __shfl_xor_sync(0xffffffffu, y0, 1);
            float o1 = __shfl_xor_sync(0xffffffffu, y1, 1);
            float o2 = __shfl_xor_sync(0xffffffffu, y2, 1);
            if ((lane & 1) == 0) {
                int j = lane >> 1;
                sm32[XL_OFF + tr * 52 + j]      = pack_bf(y0, o0);
                sm32[XL_OFF + tr * 52 + j + 16] = pack_bf(y1, o1);
                sm32[XL_OFF + tr * 52 + j + 32] = pack_bf(y2, o2);
            }
        }
    }
    __syncthreads();

    // ---- phase A2: QKV mma (112x288, K=96), warps 0..13, ldmatrix feed ----
    if (wid < 14) {
        const int mt = wid >> 1, nh = wid & 1;
        const int m0 = mt * 16;
        const uint32_t aA = sb + (XL_OFF + (m0 + l7 + lqr * 8) * 52) * 4 + (lqc << 4);
        const uint32_t bA = sb + (WQ_OFF + (nh * 144 + l7) * 52) * 4 + (lqr << 4);
        for (int p = 0; p < 2; ++p) {
            float acc[9][4];
            #pragma unroll
            for (int f = 0; f < 9; ++f)
                #pragma unroll
                for (int q = 0; q < 4; ++q) acc[f][q] = 0.f;
            #pragma unroll
            for (int k = 0; k < 6; ++k) {
                uint32_t a[4];
                ldsm_x4(a, aA + k * 32);
                #pragma unroll
                for (int f = 0; f < 9; ++f) {
                    uint32_t b[2];
                    ldsm_x2(b, bA + (p * 72 + f * 8) * 208 + k * 32);
                    mma16816(acc[f], a, b);
                }
            }
            #pragma unroll
            for (int f = 0; f < 9; ++f) {
                int col = nh * 144 + p * 72 + f * 8 + 2 * t;
                float bb0 = bias3[col], bb1 = bias3[col + 1];
                float v0 = acc[f][0] + bb0, v1 = acc[f][1] + bb1;
                float v2 = acc[f][2] + bb0, v3 = acc[f][3] + bb1;
                int which = col / 96, cc = col - which * 96;
                int head = cc / 24, cd = cc - head * 24;
                int r0 = m0 + g, r1 = m0 + g + 8;
                if (which == 0) {
                    const float sc = 0.20412414523193154f;
                    sm32[Q_OFF + head * 2240 + r0 * 20 + (cd >> 1)] = pack_bf(v0 * sc, v1 * sc);
                    sm32[Q_OFF + head * 2240 + r1 * 20 + (cd >> 1)] = pack_bf(v2 * sc, v3 * sc);
                } else if (which == 1) {
                    sm32[K_OFF + head * 2240 + r0 * 20 + (cd >> 1)] = pack_bf(v0, v1);
                    sm32[K_OFF + head * 2240 + r1 * 20 + (cd >> 1)] = pack_bf(v2, v3);
                } else {
                    __nv_bfloat16* vb = (__nv_bfloat16*)(sm32 + V_OFF + head * 1920);
                    vb[cd * 120 + r0]       = __float2bfloat16(v0);
                    vb[(cd + 1) * 120 + r0] = __float2bfloat16(v1);
                    vb[cd * 120 + r1]       = __float2bfloat16(v2);
                    vb[(cd + 1) * 120 + r1] = __float2bfloat16(v3);
                }
            }
        }
    }
    __syncthreads();

    // ---- phase B: attention, register softmax ----
    if (wid < 14) {
        const int hloc = wid & 1, mtB = wid >> 1;
        const int m0B = mtB * 16;
        const float* mk = mask + rem * 9604;
        const int r0 = m0B + g, r1 = r0 + 8;
        const uint32_t aQoff = sb + (Q_OFF + (m0B + l7 + lqr * 8) * 20) * 4 + (lqc << 4);
        const uint32_t bKoff = sb + (K_OFF + l7 * 20) * 4 + (lqr << 4);
        const uint32_t bVoff = sb + (V_OFF + l7 * 60) * 4 + (lqr << 4);
        for (int p = 0; p < 2; ++p) {
            const int h = p * 2 + hloc;
            const float* bi = g_bias + h * 9604;
            const uint32_t qA = aQoff + h * 8960;   // 2240 u32 = 8960 B
            const uint32_t kB = bKoff + h * 8960;
            const uint32_t vB = bVoff + h * 7680;   // 1920 u32

            // scores: 16 x 112, K=32
            float c[14][4];
            #pragma unroll
            for (int nt = 0; nt < 14; ++nt)
                #pragma unroll
                for (int q = 0; q < 4; ++q) c[nt][q] = 0.f;
            #pragma unroll
            for (int kt = 0; kt < 2; ++kt) {
                uint32_t a[4];
                ldsm_x4(a, qA + kt * 32);
                #pragma unroll
                for (int nt = 0; nt < 14; ++nt) {
                    uint32_t b[2];
                    ldsm_x2(b, kB + nt * 640 + kt * 32);
                    mma16816(c[nt], a, b);
                }
            }
            // bias (+ mask only for boundary windows); mask pad cols
            #pragma unroll
            for (int nt = 0; nt < 14; ++nt) {
                int col = nt * 8 + 2 * t;
                if (col < 98) {
                    if (r0 < 98) {
                        float2 bv = *(const float2*)(bi + r0 * 98 + col);
                        c[nt][0] += bv.x; c[nt][1] += bv.y;
                    }
                    if (r1 < 98) {
                        float2 bv = *(const float2*)(bi + r1 * 98 + col);
                        c[nt][2] += bv.x; c[nt][3] += bv.y;
                    }
                    if (hasmask) {
                        if (r0 < 98) {
                            float2 mv = *(const float2*)(mk + r0 * 98 + col);
                            c[nt][0] += mv.x; c[nt][1] += mv.y;
                        }
                        if (r1 < 98) {
                            float2 mv = *(const float2*)(mk + r1 * 98 + col);
                            c[nt][2] += mv.x; c[nt][3] += mv.y;
                        }
                    }
                } else {
                    c[nt][0] = c[nt][1] = c[nt][2] = c[nt][3] = -1e30f;
                }
            }
            // register softmax
            float mx0 = -1e30f, mx1 = -1e30f;
            #pragma unroll
            for (int nt = 0; nt < 14; ++nt) {
                mx0 = fmaxf(mx0, fmaxf(c[nt][0], c[nt][1]));
                mx1 = fmaxf(mx1, fmaxf(c[nt][2], c[nt][3]));
            }
            mx0 = fmaxf(mx0, __shfl_xor_sync(0xffffffffu, mx0, 1));
            mx0 = fmaxf(mx0, __shfl_xor_sync(0xffffffffu, mx0, 2));
            mx1 = fmaxf(mx1, __shfl_xor_sync(0xffffffffu, mx1, 1));
            mx1 = fmaxf(mx1, __shfl_xor_sync(0xffffffffu, mx1, 2));
            float s0 = 0.f, s1 = 0.f;
            #pragma unroll
            for (int nt = 0; nt < 14; ++nt) {
                c[nt][0] = __expf(c[nt][0] - mx0); s0 += c[nt][0];
                c[nt][1] = __expf(c[nt][1] - mx0); s0 += c[nt][1];
                c[nt][2] = __expf(c[nt][2] - mx1); s1 += c[nt][2];
                c[nt][3] = __expf(c[nt][3] - mx1); s1 += c[nt][3];
            }
            s0 += __shfl_xor_sync(0xffffffffu, s0, 1);
            s0 += __shfl_xor_sync(0xffffffffu, s0, 2);
            s1 += __shfl_xor_sync(0xffffffffu, s1, 1);
            s1 += __shfl_xor_sync(0xffffffffu, s1, 2);
            float inv0 = 1.f / s0, inv1 = 1.f / s1;

            // PV
            float pv[3][4];
            #pragma unroll
            for (int f = 0; f < 3; ++f)
                #pragma unroll
                for (int q = 0; q < 4; ++q) pv[f][q] = 0.f;
            #pragma unroll
            for (int kt2 = 0; kt2 < 7; ++kt2) {
                uint32_t a[4];
                a[0] = pack_bf(c[2 * kt2][0] * inv0, c[2 * kt2][1] * inv0);
                a[1] = pack_bf(c[2 * kt2][2] * inv1, c[2 * kt2][3] * inv1);
                a[2] = pack_bf(c[2 * kt2 + 1][0] * inv0, c[2 * kt2 + 1][1] * inv0);
                a[3] = pack_bf(c[2 * kt2 + 1][2] * inv1, c[2 * kt2 + 1][3] * inv1);
                #pragma unroll
                for (int f = 0; f < 3; ++f) {
                    uint32_t b[2];
                    ldsm_x2(b, vB + f * 1920 + kt2 * 32);   // 8 rows x 240 B = 1920
                    mma16816(pv[f], a, b);
                }
            }
            #pragma unroll
            for (int f = 0; f < 3; ++f) {
                int col = f * 8 + 2 * t;
                sm32[AT_OFF + r0 * 52 + h * 12 + (col >> 1)] = pack_bf(pv[f][0], pv[f][1]);
                sm32[AT_OFF + r1 * 52 + h * 12 + (col >> 1)] = pack_bf(pv[f][2], pv[f][3]);
            }
        }
    } else {
        // warps 14,15: prefetch proj weights + bias
        uint4* dst = (uint4*)(sm32 + WP2_OFF);
        const uint4* src = (const uint4*)g_pwi;
        for (int i = tid - 448; i < 1248; i += 64) dst[i] = src[i];
        for (int i = tid - 448; i < 96; i += 64) bias3[i] = pb[i];
    }
    __syncthreads();

    // ---- phase C: proj (112x96, K=96) ----
    if (wid < 14) {
        const int mtC = wid >> 1, nhC = wid & 1;
        const int m0C = mtC * 16;
        const uint32_t aC = sb + (AT_OFF + (m0C + l7 + lqr * 8) * 52) * 4 + (lqc << 4);
        const uint32_t bC = sb + (WP2_OFF + (nhC * 48 + l7) * 52) * 4 + (lqr << 4);
        float acc[6][4];
        #pragma unroll
        for (int f = 0; f < 6; ++f)
            #pragma unroll
            for (int q = 0; q < 4; ++q) acc[f][q] = 0.f;
        #pragma unroll
        for (int k = 0; k < 6; ++k) {
            uint32_t a[4];
            ldsm_x4(a, aC + k * 32);
            #pragma unroll
            for (int f = 0; f < 6; ++f) {
                uint32_t b[2];
                ldsm_x2(b, bC + f * 1664 + k * 32);
                mma16816(acc[f], a, b);
            }
        }
        #pragma unroll
        for (int f = 0; f < 6; ++f) {
            int col = nhC * 48 + f * 8 + 2 * t;
            *(float2*)(smF + PO_OFF + (m0C + g) * 100 + col)     = make_float2(acc[f][0], acc[f][1]);
            *(float2*)(smF + PO_OFF + (m0C + g + 8) * 100 + col) = make_float2(acc[f][2], acc[f][3]);
        }
    }
    __syncthreads();

    // ---- residual + scatter (div-free) ----
    {
        int row = tid / 96, col = tid - row * 96;
        for (int i = tid; i < 98 * 96; i += 512) {
            int base = ro[row];
            g_x2[base + col] = x[base + col] + smF[PO_OFF + row * 100 + col] + bias3[col];
            col += 32; row += 5;
            if (col >= 96) { col -= 96; row += 1; }
        }
    }
}

// ---------------- fused MLP: 64 tokens/block, 2 CTAs/SM, ldmatrix feed ----------------
#define M2_A    0
#define M2_HID  3328
#define M2_WB   15872
#define M2_B1   22528
#define M2_B2   22912
#define M2_U32  23040
#define M2_SMEM (M2_U32 * 4)

__global__ __launch_bounds__(512, 2) void k_mlpT(const float* __restrict__ n2g,
                                                 const float* __restrict__ n2b,
                                                 const float* __restrict__ f1b,
                                                 const float* __restrict__ f2b,
                                                 float* __restrict__ out) {
    extern __shared__ uint32_t smm[];
    float* smmF = (float*)smm;
    float* sf1b = smmF + M2_B1;
    float* sf2b = smmF + M2_B2;
    const int tid = threadIdx.x, wid = tid >> 5, lane = tid & 31;
    const int g = lane >> 2, t = lane & 3;
    const int l7 = lane & 7, lqr = (lane >> 3) & 1, lqc = lane >> 4;
    const int tok0 = blockIdx.x * 64;
    const uint32_t sb = cvta_sm(smm);

    if (tid < 384) sf1b[tid] = f1b[tid];
    if (tid >= 384 && tid < 480) sf2b[tid - 384] = f2b[tid - 384];

    // ---- LN2 -> bf16 A (stride 52) ----
    {
        float g0 = n2g[lane], g1 = n2g[lane + 32], g2 = n2g[lane + 64];
        float b0 = n2b[lane], b1 = n2b[lane + 32], b2 = n2b[lane + 64];
        for (int tr = wid; tr < 64; tr += 16) {
            const float* xr = g_x2 + (tok0 + tr) * 96;
            float v0 = xr[lane], v1 = xr[lane + 32], v2 = xr[lane + 64];
            float mean = warp_sum(v0 + v1 + v2) * (1.f / 96.f);
            float d0 = v0 - mean, d1 = v1 - mean, d2 = v2 - mean;
            float var = warp_sum(d0 * d0 + d1 * d1 + d2 * d2) * (1.f / 96.f);
            float rstd = rsqrtf(var + 1e-5f);
            float y0 = d0 * rstd * g0 + b0;
            float y1 = d1 * rstd * g1 + b1;
            float y2 = d2 * rstd * g2 + b2;
            float o0 = __shfl_xor_sync(0xffffffffu, y0, 1);
            float o1 = __shfl_xor_sync(0xffffffffu, y1, 1);
            float o2 = __shfl_xor_sync(0xffffffffu, y2, 1);
            if ((lane & 1) == 0) {
                int j = lane >> 1;
                smm[M2_A + tr * 52 + j]      = pack_bf(y0, o0);
                smm[M2_A + tr * 52 + j + 16] = pack_bf(y1, o1);
                smm[M2_A + tr * 52 + j + 32] = pack_bf(y2, o2);
            }
        }
    }

    const int mt = wid & 3, nq = wid >> 2;
    const int mrow = mt * 16;
    const uint32_t aF1 = sb + (M2_A + (mrow + l7 + lqr * 8) * 52) * 4 + (lqc << 4);
    const uint32_t bF1 = sb + (M2_WB + (nq * 32 + l7) * 52) * 4 + (lqr << 4);
    const uint32_t aF2 = sb + (M2_HID + (mrow + l7 + lqr * 8) * 196) * 4 + (lqc << 4);
    const uint32_t bF2 = sb + (M2_WB + (nq * 24 + l7) * 68) * 4 + (lqr << 4);

    // ---- fc1 (64x384, K=96): 3 n-chunks of 128 ----
    for (int c = 0; c < 3; ++c) {
        __syncthreads();
        {
            uint4* dst = (uint4*)(smm + M2_WB);
            const uint4* src = (const uint4*)(g_w1c + c * 6656);
            for (int i = tid; i < 1664; i += 512) dst[i] = src[i];
        }
        __syncthreads();
        float acc[4][4];
        #pragma unroll
        for (int f = 0; f < 4; ++f)
            #pragma unroll
            for (int q = 0; q < 4; ++q) acc[f][q] = 0.f;
        #pragma unroll
        for (int k = 0; k < 6; ++k) {
            uint32_t a[4];
            ldsm_x4(a, aF1 + k * 32);
            #pragma unroll
            for (int f = 0; f < 4; ++f) {
                uint32_t b[2];
                ldsm_x2(b, bF1 + f * 1664 + k * 32);
                mma16816(acc[f], a, b);
            }
        }
        #pragma unroll
        for (int f = 0; f < 4; ++f) {
            int gcol = c * 128 + nq * 32 + f * 8 + 2 * t;
            float u0 = acc[f][0] + sf1b[gcol];
            float u1 = acc[f][1] + sf1b[gcol + 1];
            float u2 = acc[f][2] + sf1b[gcol];
            float u3 = acc[f][3] + sf1b[gcol + 1];
            float e0 = 0.5f * u0 * (1.f + erff(u0 * 0.70710678118654752f));
            float e1 = 0.5f * u1 * (1.f + erff(u1 * 0.70710678118654752f));
            float e2 = 0.5f * u2 * (1.f + erff(u2 * 0.70710678118654752f));
            float e3 = 0.5f * u3 * (1.f + erff(u3 * 0.70710678118654752f));
            int hc = gcol >> 1;
            smm[M2_HID + (mrow + g) * 196 + hc]     = pack_bf(e0, e1);
            smm[M2_HID + (mrow + g + 8) * 196 + hc] = pack_bf(e2, e3);
        }
    }

    // ---- fc2 (64x96, K=384): 3 k-chunks of 128 ----
    float acc2[3][4];
    #pragma unroll
    for (int f = 0; f < 3; ++f)
        #pragma unroll
        for (int q = 0; q < 4; ++q) acc2[f][q] = 0.f;
    for (int c = 0; c < 3; ++c) {
        __syncthreads();
        {
            uint4* dst = (uint4*)(smm + M2_WB);
            const uint4* src = (const uint4*)(g_w2c + c * 6528);
            for (int i = tid; i < 1632; i += 512) dst[i] = src[i];
        }
        __syncthreads();
        #pragma unroll
        for (int k = 0; k < 8; ++k) {
            uint32_t a[4];
            ldsm_x4(a, aF2 + c * 256 + k * 32);      // c*64 u32 = 256 B
            #pragma unroll
            for (int f = 0; f < 3; ++f) {
                uint32_t b[2];
                ldsm_x2(b, bF2 + f * 2176 + k * 32); // 8 rows x 272 B = 2176
                mma16816(acc2[f], a, b);
            }
        }
    }
    __syncthreads();

    #pragma unroll
    for (int f = 0; f < 3; ++f) {
        int col = nq * 24 + f * 8 + 2 * t;
        *(float2*)(smmF + (mrow + g) * 100 + col)     = make_float2(acc2[f][0], acc2[f][1]);
        *(float2*)(smmF + (mrow + g + 8) * 100 + col) = make_float2(acc2[f][2], acc2[f][3]);
    }
    __syncthreads();

    // ---- writeout: out = x2 + fc2 + bias (div-free) ----
    {
        const float* x2t = g_x2 + tok0 * 96;
        float* outt = out + tok0 * 96;
        int row = tid / 96, col = tid - row * 96;
        for (int i = tid; i < 6144; i += 512) {
            outt[i] = smmF[row * 100 + col] + sf2b[col] + x2t[i];
            col += 32; row += 5;
            if (col >= 96) { col -= 96; row += 1; }
        }
    }
}

// ---------------- launch ----------------
extern "C" void kernel_launch(void* const* d_in, const int* in_sizes, int n_in,
                              void* d_out, int out_size) {
    const float* x    = (const float*)d_in[0];
    const float* mask = (const float*)d_in[1];
    const float* n1g  = (const float*)d_in[2];
    const float* n1b  = (const float*)d_in[3];
    const float* qkvw = (const float*)d_in[4];
    const float* qkvb = (const float*)d_in[5];
    const float* rpb  = (const float*)d_in[6];
    const float* pw   = (const float*)d_in[7];
    const float* pb   = (const float*)d_in[8];
    const float* n2g  = (const float*)d_in[9];
    const float* n2b  = (const float*)d_in[10];
    const float* f1w  = (const float*)d_in[11];
    const float* f1b  = (const float*)d_in[12];
    const float* f2w  = (const float*)d_in[13];
    const float* f2b  = (const float*)d_in[14];
    float* out = (float*)d_out;

    cudaFuncSetAttribute(k_win,  cudaFuncAttributeMaxDynamicSharedMemorySize, WIN_SMEM);
    cudaFuncSetAttribute(k_mlpT, cudaFuncAttributeMaxDynamicSharedMemorySize, M2_SMEM);

    k_bias<<<98, 128>>>(rpb);
    k_wprep<<<233, 256>>>(f1w, f2w, qkvw, pw);
    k_win<<<2048, 512, WIN_SMEM>>>(x, mask, n1g, n1b, qkvb, pb);
    k_mlpT<<<3136, 512, M2_SMEM>>>(n2g, n2b, f1b, f2b, out);
}

// round 15
// speedup vs baseline: 5.5032x; 1.0231x over previous
#include <cuda_runtime.h>
#include <cuda_bf16.h>
#include <math.h>
#include <stdint.h>

#define DEV_INLINE __device__ __forceinline__

// ---------------- static scratch (allocation-free rule) ----------------
__device__ float g_x2[200704 * 96];                  // x + attn branch
__device__ float g_bias[4 * 98 * 98];                // rel-pos bias table
// pre-swizzled smem-layout weight images (flat uint4-copyable)
__device__ __align__(16) uint32_t g_wqi[288 * 52];     // qkv^T bf16, stride 52
__device__ __align__(16) uint32_t g_pwi[96 * 52];      // proj^T bf16, stride 52
__device__ __align__(16) uint32_t g_w1c[4 * 96 * 52];  // fc1^T 4 n-chunks, stride 52
__device__ __align__(16) uint32_t g_w2c[4 * 96 * 52];  // fc2^T 4 k-chunks, stride 52

DEV_INLINE float warp_sum(float v) {
    #pragma unroll
    for (int o = 16; o; o >>= 1) v += __shfl_xor_sync(0xffffffffu, v, o);
    return v;
}
DEV_INLINE uint32_t pack_bf(float a, float b) {
    uint32_t lo = __bfloat16_as_ushort(__float2bfloat16(a));
    uint32_t hi = __bfloat16_as_ushort(__float2bfloat16(b));
    return (hi << 16) | lo;
}
DEV_INLINE void mma16816(float* d, const uint32_t* a, const uint32_t* b) {
    asm volatile("mma.sync.aligned.m16n8k16.row.col.f32.bf16.bf16.f32 "
        "{%0,%1,%2,%3}, {%4,%5,%6,%7}, {%8,%9}, {%0,%1,%2,%3};"
        : "+f"(d[0]), "+f"(d[1]), "+f"(d[2]), "+f"(d[3])
        : "r"(a[0]), "r"(a[1]), "r"(a[2]), "r"(a[3]), "r"(b[0]), "r"(b[1]));
}
DEV_INLINE uint32_t cvta_sm(const void* p) {
    return (uint32_t)__cvta_generic_to_shared(p);
}
DEV_INLINE void ldsm_x4(uint32_t* r, uint32_t addr) {
    asm volatile("ldmatrix.sync.aligned.m8n8.x4.shared.b16 {%0,%1,%2,%3}, [%4];"
        : "=r"(r[0]), "=r"(r[1]), "=r"(r[2]), "=r"(r[3]) : "r"(addr));
}
DEV_INLINE void ldsm_x2(uint32_t* r, uint32_t addr) {
    asm volatile("ldmatrix.sync.aligned.m8n8.x2.shared.b16 {%0,%1}, [%2];"
        : "=r"(r[0]), "=r"(r[1]) : "r"(addr));
}
DEV_INLINE void cp16(uint32_t dst, const void* src) {
    asm volatile("cp.async.ca.shared.global [%0], [%1], 16;" :: "r"(dst), "l"(src));
}
#define CP_COMMIT() asm volatile("cp.async.commit_group;" ::: "memory")
#define CP_WAIT0()  asm volatile("cp.async.wait_group 0;" ::: "memory")

DEV_INLINE int spat_base(int B_, int i) {
    int b = B_ >> 8, rem = B_ & 255;
    int wd = rem >> 6, wh = (rem >> 3) & 7, ww = rem & 7;
    int td = i / 49, r = i - td * 49;
    int th = r / 7, tw = r - th * 7;
    int d = (wd * 2 + td + 1) & 7;
    int hh = wh * 7 + th + 3; if (hh >= 56) hh -= 56;
    int w2 = ww * 7 + tw + 3; if (w2 >= 56) w2 -= 56;
    return (((b * 8 + d) * 56 + hh) * 56 + w2) * 96;
}

// ---------------- kernel 0: rel-pos bias table ----------------
__global__ void k_bias(const float* __restrict__ rpb) {
    int i = blockIdx.x, j = threadIdx.x;
    if (j >= 98) return;
    int di = i / 49, ri = i - di * 49, hi = ri / 7, wi = ri - hi * 7;
    int dj = j / 49, rj = j - dj * 49, hj = rj / 7, wj = rj - hj * 7;
    int r = (di - dj + 1) * 169 + (hi - hj + 6) * 13 + (wi - wj + 6);
    #pragma unroll
    for (int h = 0; h < 4; ++h)
        g_bias[h * 9604 + i * 98 + j] = rpb[r * 4 + h];
}

// ---------------- kernel: weight transposes into smem-layout images ----------------
// segments: [0,14976) wq | [14976,19968) pw | [19968,39936) w1 4-chunks | [39936,59904) w2 4-chunks
__global__ void k_wprep(const float* __restrict__ f1w, const float* __restrict__ f2w,
                        const float* __restrict__ qw, const float* __restrict__ pw) {
    int gidx = blockIdx.x * 256 + threadIdx.x;
    if (gidx < 14976) {
        int n = gidx / 52, j = gidx - n * 52;
        g_wqi[gidx] = (j < 48) ? pack_bf(qw[(2 * j) * 288 + n], qw[(2 * j + 1) * 288 + n]) : 0u;
    } else if (gidx < 19968) {
        int i = gidx - 14976;
        int n = i / 52, j = i - n * 52;
        g_pwi[i] = (j < 48) ? pack_bf(pw[(2 * j) * 96 + n], pw[(2 * j + 1) * 96 + n]) : 0u;
    } else if (gidx < 39936) {
        int i = gidx - 19968;
        int c = i / 4992, r = i - c * 4992;
        int n = r / 52, j = r - n * 52;
        int ng = c * 96 + n;
        g_w1c[i] = (j < 48) ? pack_bf(f1w[(2 * j) * 384 + ng],
                                      f1w[(2 * j + 1) * 384 + ng]) : 0u;
    } else if (gidx < 59904) {
        int i = gidx - 39936;
        int c = i / 4992, r = i - c * 4992;
        int n = r / 52, j = r - n * 52;
        int kk = c * 48 + j;
        g_w2c[i] = (j < 48) ? pack_bf(f2w[(2 * kk) * 96 + n], f2w[(2 * kk + 1) * 96 + n]) : 0u;
    }
}

// ---------------- fused window kernel: HMMA + ldmatrix + register softmax ----------------
#define Q_OFF   0              // 4 heads x 112 x 20
#define K_OFF   8960
#define V_OFF   17920          // 4 heads x 32 dims x 60 (token pairs)
#define AT_OFF  25600          // 112 x 52
#define RO_OFF  31424          // 112 ints
#define B3_OFF  31536          // 288 floats
#define RB      31824
#define XL_OFF  RB             // 112 x 52 (phase A)
#define WQ_OFF  (RB + 5824)    // 288 x 52 (phase A)
#define PO_OFF  RB             // 112 x 100 f32 (phase C out)
#define WP2_OFF (RB + 11200)   // 96 x 52 (phase C weights)
#define WIN_U32 52624
#define WIN_SMEM (WIN_U32 * 4)

__global__ __launch_bounds__(512, 1) void k_win(const float* __restrict__ x,
                                                const float* __restrict__ mask,
                                                const float* __restrict__ n1g,
                                                const float* __restrict__ n1b,
                                                const float* __restrict__ qb,
                                                const float* __restrict__ pb) {
    extern __shared__ uint32_t sm32[];
    float* smF = (float*)sm32;
    int* ro = (int*)(sm32 + RO_OFF);
    float* bias3 = smF + B3_OFF;
    const int tid = threadIdx.x, B_ = blockIdx.x;
    const int wid = tid >> 5, lane = tid & 31;
    const int g = lane >> 2, t = lane & 3;
    const int l7 = lane & 7, lqr = (lane >> 3) & 1, lqc = lane >> 4;
    const int rem = B_ & 255;
    const bool hasmask = ((rem >> 6) == 3) | (((rem >> 3) & 7) == 7) | ((rem & 7) == 7);
    const uint32_t sb = cvta_sm(sm32);

    // ---- phase A0: WQ via cp.async FIRST (latency hidden under LN) ----
    {
        uint32_t dst = sb + WQ_OFF * 4;
        const char* src = (const char*)g_wqi;
        for (int i = tid; i < 3744; i += 512) cp16(dst + i * 16, src + i * 16);
        CP_COMMIT();
    }
    if (tid < 98) ro[tid] = spat_base(B_, tid);
    for (int i = tid; i < 288; i += 512) bias3[i] = qb[i];
    for (int i = tid; i < 14 * 52; i += 512)
        sm32[XL_OFF + (98 + i / 52) * 52 + (i % 52)] = 0;
    for (int i = tid; i < 4 * 112 * 4; i += 512) {
        int h = i / 448, r = (i >> 2) % 112, c = 12 + (i & 3);
        sm32[Q_OFF + h * 2240 + r * 20 + c] = 0;
        sm32[K_OFF + h * 2240 + r * 20 + c] = 0;
    }

    // ---- phase A1: LN1 -> bf16 A image ----
    {
        float g0 = n1g[lane], g1 = n1g[lane + 32], g2 = n1g[lane + 64];
        float b0 = n1b[lane], b1 = n1b[lane + 32], b2 = n1b[lane + 64];
        for (int tr = wid; tr < 98; tr += 16) {
            const float* xr = x + spat_base(B_, tr);
            float v0 = xr[lane], v1 = xr[lane + 32], v2 = xr[lane + 64];
            float mean = warp_sum(v0 + v1 + v2) * (1.f / 96.f);
            float d0 = v0 - mean, d1 = v1 - mean, d2 = v2 - mean;
            float var = warp_sum(d0 * d0 + d1 * d1 + d2 * d2) * (1.f / 96.f);
            float rstd = rsqrtf(var + 1e-5f);
            float y0 = d0 * rstd * g0 + b0;
            float y1 = d1 * rstd * g1 + b1;
            float y2 = d2 * rstd * g2 + b2;
            float o0 = __shfl_xor_sync(0xffffffffu, y0, 1);
            float o1 = __shfl_xor_sync(0xffffffffu, y1, 1);
            float o2 = __shfl_xor_sync(0xffffffffu, y2, 1);
            if ((lane & 1) == 0) {
                int j = lane >> 1;
                sm32[XL_OFF + tr * 52 + j]      = pack_bf(y0, o0);
                sm32[XL_OFF + tr * 52 + j + 16] = pack_bf(y1, o1);
                sm32[XL_OFF + tr * 52 + j + 32] = pack_bf(y2, o2);
            }
        }
    }
    CP_WAIT0();
    __syncthreads();

    // ---- phase A2: QKV mma (112x288, K=96), warps 0..13, ldmatrix feed ----
    if (wid < 14) {
        const int mt = wid >> 1, nh = wid & 1;
        const int m0 = mt * 16;
        const uint32_t aA = sb + (XL_OFF + (m0 + l7 + lqr * 8) * 52) * 4 + (lqc << 4);
        const uint32_t bA = sb + (WQ_OFF + (nh * 144 + l7) * 52) * 4 + (lqr << 4);
        for (int p = 0; p < 2; ++p) {
            float acc[9][4];
            #pragma unroll
            for (int f = 0; f < 9; ++f)
                #pragma unroll
                for (int q = 0; q < 4; ++q) acc[f][q] = 0.f;
            #pragma unroll
            for (int k = 0; k < 6; ++k) {
                uint32_t a[4];
                ldsm_x4(a, aA + k * 32);
                #pragma unroll
                for (int f = 0; f < 9; ++f) {
                    uint32_t b[2];
                    ldsm_x2(b, bA + (p * 72 + f * 8) * 208 + k * 32);
                    mma16816(acc[f], a, b);
                }
            }
            #pragma unroll
            for (int f = 0; f < 9; ++f) {
                int col = nh * 144 + p * 72 + f * 8 + 2 * t;
                float bb0 = bias3[col], bb1 = bias3[col + 1];
                float v0 = acc[f][0] + bb0, v1 = acc[f][1] + bb1;
                float v2 = acc[f][2] + bb0, v3 = acc[f][3] + bb1;
                int which = col / 96, cc = col - which * 96;
                int head = cc / 24, cd = cc - head * 24;
                int r0 = m0 + g, r1 = m0 + g + 8;
                if (which == 0) {
                    const float sc = 0.20412414523193154f;
                    sm32[Q_OFF + head * 2240 + r0 * 20 + (cd >> 1)] = pack_bf(v0 * sc, v1 * sc);
                    sm32[Q_OFF + head * 2240 + r1 * 20 + (cd >> 1)] = pack_bf(v2 * sc, v3 * sc);
                } else if (which == 1) {
                    sm32[K_OFF + head * 2240 + r0 * 20 + (cd >> 1)] = pack_bf(v0, v1);
                    sm32[K_OFF + head * 2240 + r1 * 20 + (cd >> 1)] = pack_bf(v2, v3);
                } else {
                    __nv_bfloat16* vb = (__nv_bfloat16*)(sm32 + V_OFF + head * 1920);
                    vb[cd * 120 + r0]       = __float2bfloat16(v0);
                    vb[(cd + 1) * 120 + r0] = __float2bfloat16(v1);
                    vb[cd * 120 + r1]       = __float2bfloat16(v2);
                    vb[(cd + 1) * 120 + r1] = __float2bfloat16(v3);
                }
            }
        }
    }
    __syncthreads();

    // ---- phase B: attention, register softmax ----
    if (wid < 14) {
        const int hloc = wid & 1, mtB = wid >> 1;
        const int m0B = mtB * 16;
        const float* mk = mask + rem * 9604;
        const int r0 = m0B + g, r1 = r0 + 8;
        const uint32_t aQoff = sb + (Q_OFF + (m0B + l7 + lqr * 8) * 20) * 4 + (lqc << 4);
        const uint32_t bKoff = sb + (K_OFF + l7 * 20) * 4 + (lqr << 4);
        const uint32_t bVoff = sb + (V_OFF + l7 * 60) * 4 + (lqr << 4);
        for (int p = 0; p < 2; ++p) {
            const int h = p * 2 + hloc;
            const float* bi = g_bias + h * 9604;
            const uint32_t qA = aQoff + h * 8960;
            const uint32_t kB = bKoff + h * 8960;
            const uint32_t vB = bVoff + h * 7680;

            float c[14][4];
            #pragma unroll
            for (int nt = 0; nt < 14; ++nt)
                #pragma unroll
                for (int q = 0; q < 4; ++q) c[nt][q] = 0.f;
            #pragma unroll
            for (int kt = 0; kt < 2; ++kt) {
                uint32_t a[4];
                ldsm_x4(a, qA + kt * 32);
                #pragma unroll
                for (int nt = 0; nt < 14; ++nt) {
                    uint32_t b[2];
                    ldsm_x2(b, kB + nt * 640 + kt * 32);
                    mma16816(c[nt], a, b);
                }
            }
            #pragma unroll
            for (int nt = 0; nt < 14; ++nt) {
                int col = nt * 8 + 2 * t;
                if (col < 98) {
                    if (r0 < 98) {
                        float2 bv = *(const float2*)(bi + r0 * 98 + col);
                        c[nt][0] += bv.x; c[nt][1] += bv.y;
                    }
                    if (r1 < 98) {
                        float2 bv = *(const float2*)(bi + r1 * 98 + col);
                        c[nt][2] += bv.x; c[nt][3] += bv.y;
                    }
                    if (hasmask) {
                        if (r0 < 98) {
                            float2 mv = *(const float2*)(mk + r0 * 98 + col);
                            c[nt][0] += mv.x; c[nt][1] += mv.y;
                        }
                        if (r1 < 98) {
                            float2 mv = *(const float2*)(mk + r1 * 98 + col);
                            c[nt][2] += mv.x; c[nt][3] += mv.y;
                        }
                    }
                } else {
                    c[nt][0] = c[nt][1] = c[nt][2] = c[nt][3] = -1e30f;
                }
            }
            float mx0 = -1e30f, mx1 = -1e30f;
            #pragma unroll
            for (int nt = 0; nt < 14; ++nt) {
                mx0 = fmaxf(mx0, fmaxf(c[nt][0], c[nt][1]));
                mx1 = fmaxf(mx1, fmaxf(c[nt][2], c[nt][3]));
            }
            mx0 = fmaxf(mx0, __shfl_xor_sync(0xffffffffu, mx0, 1));
            mx0 = fmaxf(mx0, __shfl_xor_sync(0xffffffffu, mx0, 2));
            mx1 = fmaxf(mx1, __shfl_xor_sync(0xffffffffu, mx1, 1));
            mx1 = fmaxf(mx1, __shfl_xor_sync(0xffffffffu, mx1, 2));
            float s0 = 0.f, s1 = 0.f;
            #pragma unroll
            for (int nt = 0; nt < 14; ++nt) {
                c[nt][0] = __expf(c[nt][0] - mx0); s0 += c[nt][0];
                c[nt][1] = __expf(c[nt][1] - mx0); s0 += c[nt][1];
                c[nt][2] = __expf(c[nt][2] - mx1); s1 += c[nt][2];
                c[nt][3] = __expf(c[nt][3] - mx1); s1 += c[nt][3];
            }
            s0 += __shfl_xor_sync(0xffffffffu, s0, 1);
            s0 += __shfl_xor_sync(0xffffffffu, s0, 2);
            s1 += __shfl_xor_sync(0xffffffffu, s1, 1);
            s1 += __shfl_xor_sync(0xffffffffu, s1, 2);
            float inv0 = 1.f / s0, inv1 = 1.f / s1;

            float pv[3][4];
            #pragma unroll
            for (int f = 0; f < 3; ++f)
                #pragma unroll
                for (int q = 0; q < 4; ++q) pv[f][q] = 0.f;
            #pragma unroll
            for (int kt2 = 0; kt2 < 7; ++kt2) {
                uint32_t a[4];
                a[0] = pack_bf(c[2 * kt2][0] * inv0, c[2 * kt2][1] * inv0);
                a[1] = pack_bf(c[2 * kt2][2] * inv1, c[2 * kt2][3] * inv1);
                a[2] = pack_bf(c[2 * kt2 + 1][0] * inv0, c[2 * kt2 + 1][1] * inv0);
                a[3] = pack_bf(c[2 * kt2 + 1][2] * inv1, c[2 * kt2 + 1][3] * inv1);
                #pragma unroll
                for (int f = 0; f < 3; ++f) {
                    uint32_t b[2];
                    ldsm_x2(b, vB + f * 1920 + kt2 * 32);
                    mma16816(pv[f], a, b);
                }
            }
            #pragma unroll
            for (int f = 0; f < 3; ++f) {
                int col = f * 8 + 2 * t;
                sm32[AT_OFF + r0 * 52 + h * 12 + (col >> 1)] = pack_bf(pv[f][0], pv[f][1]);
                sm32[AT_OFF + r1 * 52 + h * 12 + (col >> 1)] = pack_bf(pv[f][2], pv[f][3]);
            }
        }
    } else {
        uint4* dst = (uint4*)(sm32 + WP2_OFF);
        const uint4* src = (const uint4*)g_pwi;
        for (int i = tid - 448; i < 1248; i += 64) dst[i] = src[i];
        for (int i = tid - 448; i < 96; i += 64) bias3[i] = pb[i];
    }
    __syncthreads();

    // ---- phase C: proj (112x96, K=96) ----
    if (wid < 14) {
        const int mtC = wid >> 1, nhC = wid & 1;
        const int m0C = mtC * 16;
        const uint32_t aC = sb + (AT_OFF + (m0C + l7 + lqr * 8) * 52) * 4 + (lqc << 4);
        const uint32_t bC = sb + (WP2_OFF + (nhC * 48 + l7) * 52) * 4 + (lqr << 4);
        float acc[6][4];
        #pragma unroll
        for (int f = 0; f < 6; ++f)
            #pragma unroll
            for (int q = 0; q < 4; ++q) acc[f][q] = 0.f;
        #pragma unroll
        for (int k = 0; k < 6; ++k) {
            uint32_t a[4];
            ldsm_x4(a, aC + k * 32);
            #pragma unroll
            for (int f = 0; f < 6; ++f) {
                uint32_t b[2];
                ldsm_x2(b, bC + f * 1664 + k * 32);
                mma16816(acc[f], a, b);
            }
        }
        #pragma unroll
        for (int f = 0; f < 6; ++f) {
            int col = nhC * 48 + f * 8 + 2 * t;
            *(float2*)(smF + PO_OFF + (m0C + g) * 100 + col)     = make_float2(acc[f][0], acc[f][1]);
            *(float2*)(smF + PO_OFF + (m0C + g + 8) * 100 + col) = make_float2(acc[f][2], acc[f][3]);
        }
    }
    __syncthreads();

    // ---- residual + scatter (div-free) ----
    {
        int row = tid / 96, col = tid - row * 96;
        for (int i = tid; i < 98 * 96; i += 512) {
            int base = ro[row];
            g_x2[base + col] = x[base + col] + smF[PO_OFF + row * 100 + col] + bias3[col];
            col += 32; row += 5;
            if (col >= 96) { col -= 96; row += 1; }
        }
    }
}

// ---------------- fused MLP: cp.async double-buffered 8-chunk pipeline ----------------
#define M2_A    0              // 64 x 52 (bf16); overlaid by OB (f32 stride 100) post-fc2
#define M2_HID  3328           // 64 x 196
#define M2_WB   15872          // 2 x 4992 double buffer
#define M2_B1   25856          // 384 f32
#define M2_B2   26240          // 96 f32
#define M2_U32  26336
#define M2_SMEM (M2_U32 * 4)

__global__ __launch_bounds__(512, 2) void k_mlpT(const float* __restrict__ n2g,
                                                 const float* __restrict__ n2b,
                                                 const float* __restrict__ f1b,
                                                 const float* __restrict__ f2b,
                                                 float* __restrict__ out) {
    extern __shared__ uint32_t smm[];
    float* smmF = (float*)smm;
    float* sf1b = smmF + M2_B1;
    float* sf2b = smmF + M2_B2;
    const int tid = threadIdx.x, wid = tid >> 5, lane = tid & 31;
    const int g = lane >> 2, t = lane & 3;
    const int l7 = lane & 7, lqr = (lane >> 3) & 1, lqc = lane >> 4;
    const int tok0 = blockIdx.x * 64;
    const uint32_t sb = cvta_sm(smm);

    // issue chunk 0 immediately (hidden under LN2)
    {
        uint32_t dst = sb + M2_WB * 4;
        const char* src = (const char*)g_w1c;
        for (int i = tid; i < 1248; i += 512) cp16(dst + i * 16, src + i * 16);
        CP_COMMIT();
    }
    if (tid < 384) sf1b[tid] = f1b[tid];
    if (tid >= 384 && tid < 480) sf2b[tid - 384] = f2b[tid - 384];

    // ---- LN2 -> bf16 A (stride 52) ----
    {
        float g0 = n2g[lane], g1 = n2g[lane + 32], g2 = n2g[lane + 64];
        float b0 = n2b[lane], b1 = n2b[lane + 32], b2 = n2b[lane + 64];
        for (int tr = wid; tr < 64; tr += 16) {
            const float* xr = g_x2 + (tok0 + tr) * 96;
            float v0 = xr[lane], v1 = xr[lane + 32], v2 = xr[lane + 64];
            float mean = warp_sum(v0 + v1 + v2) * (1.f / 96.f);
            float d0 = v0 - mean, d1 = v1 - mean, d2 = v2 - mean;
            float var = warp_sum(d0 * d0 + d1 * d1 + d2 * d2) * (1.f / 96.f);
            float rstd = rsqrtf(var + 1e-5f);
            float y0 = d0 * rstd * g0 + b0;
            float y1 = d1 * rstd * g1 + b1;
            float y2 = d2 * rstd * g2 + b2;
            float o0 = __shfl_xor_sync(0xffffffffu, y0, 1);
            float o1 = __shfl_xor_sync(0xffffffffu, y1, 1);
            float o2 = __shfl_xor_sync(0xffffffffu, y2, 1);
            if ((lane & 1) == 0) {
                int j = lane >> 1;
                smm[M2_A + tr * 52 + j]      = pack_bf(y0, o0);
                smm[M2_A + tr * 52 + j + 16] = pack_bf(y1, o1);
                smm[M2_A + tr * 52 + j + 32] = pack_bf(y2, o2);
            }
        }
    }
    CP_WAIT0();
    __syncthreads();      // A + chunk0 ready

    const int mt = wid & 3, nq = wid >> 2;
    const int mrow = mt * 16;
    const uint32_t aA = sb + (M2_A + (mrow + l7 + lqr * 8) * 52) * 4 + (lqc << 4);
    const uint32_t aH = sb + (M2_HID + (mrow + l7 + lqr * 8) * 196) * 4 + (lqc << 4);

    float acc2[3][4];
    #pragma unroll
    for (int f = 0; f < 3; ++f)
        #pragma unroll
        for (int q = 0; q < 4; ++q) acc2[f][q] = 0.f;

    for (int c = 0; c < 8; ++c) {
        const int cur = c & 1;
        if (c < 7) {  // prefetch next chunk into the free buffer
            const char* src = (c + 1 < 4) ? (const char*)(g_w1c + (c + 1) * 4992)
                                          : (const char*)(g_w2c + (c - 3) * 4992);
            uint32_t dst = sb + (M2_WB + (cur ^ 1) * 4992) * 4;
            for (int i = tid; i < 1248; i += 512) cp16(dst + i * 16, src + i * 16);
            CP_COMMIT();
        }
        const uint32_t bB = sb + (M2_WB + cur * 4992 + (nq * 24 + l7) * 52) * 4 + (lqr << 4);
        if (c < 4) {
            // fc1 chunk: 96 output cols, K=96
            float acc[3][4];
            #pragma unroll
            for (int f = 0; f < 3; ++f)
                #pragma unroll
                for (int q = 0; q < 4; ++q) acc[f][q] = 0.f;
            #pragma unroll
            for (int k = 0; k < 6; ++k) {
                uint32_t a[4];
                ldsm_x4(a, aA + k * 32);
                #pragma unroll
                for (int f = 0; f < 3; ++f) {
                    uint32_t b[2];
                    ldsm_x2(b, bB + f * 1664 + k * 32);
                    mma16816(acc[f], a, b);
                }
            }
            #pragma unroll
            for (int f = 0; f < 3; ++f) {
                int gcol = c * 96 + nq * 24 + f * 8 + 2 * t;
                float u0 = acc[f][0] + sf1b[gcol];
                float u1 = acc[f][1] + sf1b[gcol + 1];
                float u2 = acc[f][2] + sf1b[gcol];
                float u3 = acc[f][3] + sf1b[gcol + 1];
                float e0 = 0.5f * u0 * (1.f + erff(u0 * 0.70710678118654752f));
                float e1 = 0.5f * u1 * (1.f + erff(u1 * 0.70710678118654752f));
                float e2 = 0.5f * u2 * (1.f + erff(u2 * 0.70710678118654752f));
                float e3 = 0.5f * u3 * (1.f + erff(u3 * 0.70710678118654752f));
                int hc = gcol >> 1;
                smm[M2_HID + (mrow + g) * 196 + hc]     = pack_bf(e0, e1);
                smm[M2_HID + (mrow + g + 8) * 196 + hc] = pack_bf(e2, e3);
            }
        } else {
            // fc2 chunk cc=c-4: K slice [cc*96, cc*96+96)
            const uint32_t aC = aH + (c - 4) * 192;   // 48 u32 = 192 B per chunk
            #pragma unroll
            for (int k = 0; k < 6; ++k) {
                uint32_t a[4];
                ldsm_x4(a, aC + k * 32);
                #pragma unroll
                for (int f = 0; f < 3; ++f) {
                    uint32_t b[2];
                    ldsm_x2(b, bB + f * 1664 + k * 32);
                    mma16816(acc2[f], a, b);
                }
            }
        }
        if (c < 7) CP_WAIT0();
        __syncthreads();
    }

    #pragma unroll
    for (int f = 0; f < 3; ++f) {
        int col = nq * 24 + f * 8 + 2 * t;    // 0..94
        *(float2*)(smmF + (mrow + g) * 100 + col)     = make_float2(acc2[f][0], acc2[f][1]);
        *(float2*)(smmF + (mrow + g + 8) * 100 + col) = make_float2(acc2[f][2], acc2[f][3]);
    }
    __syncthreads();

    // ---- writeout: out = x2 + fc2 + bias (div-free) ----
    {
        const float* x2t = g_x2 + tok0 * 96;
        float* outt = out + tok0 * 96;
        int row = tid / 96, col = tid - row * 96;
        for (int i = tid; i < 6144; i += 512) {
            outt[i] = smmF[row * 100 + col] + sf2b[col] + x2t[i];
            col += 32; row += 5;
            if (col >= 96) { col -= 96; row += 1; }
        }
    }
}

// ---------------- launch ----------------
extern "C" void kernel_launch(void* const* d_in, const int* in_sizes, int n_in,
                              void* d_out, int out_size) {
    const float* x    = (const float*)d_in[0];
    const float* mask = (const float*)d_in[1];
    const float* n1g  = (const float*)d_in[2];
    const float* n1b  = (const float*)d_in[3];
    const float* qkvw = (const float*)d_in[4];
    const float* qkvb = (const float*)d_in[5];
    const float* rpb  = (const float*)d_in[6];
    const float* pw   = (const float*)d_in[7];
    const float* pb   = (const float*)d_in[8];
    const float* n2g  = (const float*)d_in[9];
    const float* n2b  = (const float*)d_in[10];
    const float* f1w  = (const float*)d_in[11];
    const float* f1b  = (const float*)d_in[12];
    const float* f2w  = (const float*)d_in[13];
    const float* f2b  = (const float*)d_in[14];
    float* out = (float*)d_out;

    cudaFuncSetAttribute(k_win,  cudaFuncAttributeMaxDynamicSharedMemorySize, WIN_SMEM);
    cudaFuncSetAttribute(k_mlpT, cudaFuncAttributeMaxDynamicSharedMemorySize, M2_SMEM);

    k_bias<<<98, 128>>>(rpb);
    k_wprep<<<234, 256>>>(f1w, f2w, qkvw, pw);
    k_win<<<2048, 512, WIN_SMEM>>>(x, mask, n1g, n1b, qkvb, pb);
    k_mlpT<<<3136, 512, M2_SMEM>>>(n2g, n2b, f1b, f2b, out);
}

// round 16
// speedup vs baseline: 6.1280x; 1.1135x over previous
#include <cuda_runtime.h>
#include <cuda_bf16.h>
#include <math.h>
#include <stdint.h>

#define DEV_INLINE __device__ __forceinline__

// ---------------- static scratch (allocation-free rule) ----------------
__device__ float g_x2[200704 * 96];                  // x + attn branch
__device__ float g_cb[8 * 4 * 98 * 98];              // combined bias+mask per class/head
// pre-swizzled smem-layout weight images (flat uint4-copyable)
__device__ __align__(16) uint32_t g_wqi[288 * 52];     // qkv^T bf16, stride 52
__device__ __align__(16) uint32_t g_pwi[96 * 52];      // proj^T bf16, stride 52
__device__ __align__(16) uint32_t g_w1c[4 * 96 * 52];  // fc1^T 4 n-chunks, stride 52
__device__ __align__(16) uint32_t g_w2c[4 * 96 * 52];  // fc2^T 4 k-chunks, stride 52

DEV_INLINE float warp_sum(float v) {
    #pragma unroll
    for (int o = 16; o; o >>= 1) v += __shfl_xor_sync(0xffffffffu, v, o);
    return v;
}
DEV_INLINE uint32_t pack_bf(float a, float b) {
    uint32_t lo = __bfloat16_as_ushort(__float2bfloat16(a));
    uint32_t hi = __bfloat16_as_ushort(__float2bfloat16(b));
    return (hi << 16) | lo;
}
DEV_INLINE void mma16816(float* d, const uint32_t* a, const uint32_t* b) {
    asm volatile("mma.sync.aligned.m16n8k16.row.col.f32.bf16.bf16.f32 "
        "{%0,%1,%2,%3}, {%4,%5,%6,%7}, {%8,%9}, {%0,%1,%2,%3};"
        : "+f"(d[0]), "+f"(d[1]), "+f"(d[2]), "+f"(d[3])
        : "r"(a[0]), "r"(a[1]), "r"(a[2]), "r"(a[3]), "r"(b[0]), "r"(b[1]));
}
DEV_INLINE uint32_t cvta_sm(const void* p) {
    return (uint32_t)__cvta_generic_to_shared(p);
}
DEV_INLINE void ldsm_x4(uint32_t* r, uint32_t addr) {
    asm volatile("ldmatrix.sync.aligned.m8n8.x4.shared.b16 {%0,%1,%2,%3}, [%4];"
        : "=r"(r[0]), "=r"(r[1]), "=r"(r[2]), "=r"(r[3]) : "r"(addr));
}
DEV_INLINE void ldsm_x2(uint32_t* r, uint32_t addr) {
    asm volatile("ldmatrix.sync.aligned.m8n8.x2.shared.b16 {%0,%1}, [%2];"
        : "=r"(r[0]), "=r"(r[1]) : "r"(addr));
}
DEV_INLINE void cp16(uint32_t dst, const void* src) {
    asm volatile("cp.async.ca.shared.global [%0], [%1], 16;" :: "r"(dst), "l"(src));
}
#define CP_COMMIT() asm volatile("cp.async.commit_group;" ::: "memory")
#define CP_WAIT0()  asm volatile("cp.async.wait_group 0;" ::: "memory")

// GELU via hardware tanh: error << bf16 quantization of the hidden buffer
DEV_INLINE float gelu_f(float u) {
    float z = 0.7978845608028654f * (u + 0.044715f * u * u * u);
    float th;
    asm("tanh.approx.f32 %0, %1;" : "=f"(th) : "f"(z));
    return 0.5f * u * (1.f + th);
}

DEV_INLINE int spat_base(int B_, int i) {
    int b = B_ >> 8, rem = B_ & 255;
    int wd = rem >> 6, wh = (rem >> 3) & 7, ww = rem & 7;
    int td = i / 49, r = i - td * 49;
    int th = r / 7, tw = r - th * 7;
    int d = (wd * 2 + td + 1) & 7;
    int hh = wh * 7 + th + 3; if (hh >= 56) hh -= 56;
    int w2 = ww * 7 + tw + 3; if (w2 >= 56) w2 -= 56;
    return (((b * 8 + d) * 56 + hh) * 56 + w2) * 96;
}

// ---------------- kernel 0: combined rel-pos bias + mask table ----------------
// class = (d-boundary<<2)|(h-boundary<<1)|(w-boundary); mask pattern depends only on class.
__global__ void k_bias(const float* __restrict__ rpb, const float* __restrict__ mask) {
    int i = blockIdx.x, cls = blockIdx.y, j = threadIdx.x;
    if (j >= 98) return;
    int di = i / 49, ri = i - di * 49, hi = ri / 7, wi = ri - hi * 7;
    int dj = j / 49, rj = j - dj * 49, hj = rj / 7, wj = rj - hj * 7;
    int r = (di - dj + 1) * 169 + (hi - hj + 6) * 13 + (wi - wj + 6);
    int rep = ((cls & 4) ? 3 * 64 : 0) + ((cls & 2) ? 7 * 8 : 0) + ((cls & 1) ? 7 : 0);
    float mv = mask[rep * 9604 + i * 98 + j];
    #pragma unroll
    for (int h = 0; h < 4; ++h)
        g_cb[(cls * 4 + h) * 9604 + i * 98 + j] = rpb[r * 4 + h] + mv;
}

// ---------------- kernel: weight transposes into smem-layout images ----------------
__global__ void k_wprep(const float* __restrict__ f1w, const float* __restrict__ f2w,
                        const float* __restrict__ qw, const float* __restrict__ pw) {
    int gidx = blockIdx.x * 256 + threadIdx.x;
    if (gidx < 14976) {
        int n = gidx / 52, j = gidx - n * 52;
        g_wqi[gidx] = (j < 48) ? pack_bf(qw[(2 * j) * 288 + n], qw[(2 * j + 1) * 288 + n]) : 0u;
    } else if (gidx < 19968) {
        int i = gidx - 14976;
        int n = i / 52, j = i - n * 52;
        g_pwi[i] = (j < 48) ? pack_bf(pw[(2 * j) * 96 + n], pw[(2 * j + 1) * 96 + n]) : 0u;
    } else if (gidx < 39936) {
        int i = gidx - 19968;
        int c = i / 4992, r = i - c * 4992;
        int n = r / 52, j = r - n * 52;
        int ng = c * 96 + n;
        g_w1c[i] = (j < 48) ? pack_bf(f1w[(2 * j) * 384 + ng],
                                      f1w[(2 * j + 1) * 384 + ng]) : 0u;
    } else if (gidx < 59904) {
        int i = gidx - 39936;
        int c = i / 4992, r = i - c * 4992;
        int n = r / 52, j = r - n * 52;
        int kk = c * 48 + j;
        g_w2c[i] = (j < 48) ? pack_bf(f2w[(2 * kk) * 96 + n], f2w[(2 * kk + 1) * 96 + n]) : 0u;
    }
}

// ---------------- fused window kernel: HMMA + ldmatrix + register softmax ----------------
#define Q_OFF   0              // 4 heads x 112 x 20
#define K_OFF   8960
#define V_OFF   17920          // 4 heads x 32 dims x 60 (token pairs)
#define AT_OFF  25600          // 112 x 52
#define RO_OFF  31424          // 112 ints
#define B3_OFF  31536          // 288 floats
#define RB      31824
#define XL_OFF  RB             // 112 x 52 (phase A)
#define WQ_OFF  (RB + 5824)    // 288 x 52 (phase A)
#define PO_OFF  RB             // 112 x 100 f32 (phase C out)
#define WP2_OFF (RB + 11200)   // 96 x 52 (phase C weights)
#define WIN_U32 52624
#define WIN_SMEM (WIN_U32 * 4)

__global__ __launch_bounds__(512, 1) void k_win(const float* __restrict__ x,
                                                const float* __restrict__ n1g,
                                                const float* __restrict__ n1b,
                                                const float* __restrict__ qb,
                                                const float* __restrict__ pb) {
    extern __shared__ uint32_t sm32[];
    float* smF = (float*)sm32;
    int* ro = (int*)(sm32 + RO_OFF);
    float* bias3 = smF + B3_OFF;
    const int tid = threadIdx.x, B_ = blockIdx.x;
    const int wid = tid >> 5, lane = tid & 31;
    const int g = lane >> 2, t = lane & 3;
    const int l7 = lane & 7, lqr = (lane >> 3) & 1, lqc = lane >> 4;
    const int rem = B_ & 255;
    const int cls = ((((rem >> 6) == 3) ? 4 : 0) | ((((rem >> 3) & 7) == 7) ? 2 : 0) |
                     (((rem & 7) == 7) ? 1 : 0));
    const uint32_t sb = cvta_sm(sm32);

    // ---- phase A0: WQ via cp.async FIRST (latency hidden under LN) ----
    {
        uint32_t dst = sb + WQ_OFF * 4;
        const char* src = (const char*)g_wqi;
        for (int i = tid; i < 3744; i += 512) cp16(dst + i * 16, src + i * 16);
        CP_COMMIT();
    }
    if (tid < 98) ro[tid] = spat_base(B_, tid);
    for (int i = tid; i < 288; i += 512) bias3[i] = qb[i];
    for (int i = tid; i < 14 * 52; i += 512)
        sm32[XL_OFF + (98 + i / 52) * 52 + (i % 52)] = 0;
    for (int i = tid; i < 4 * 112 * 4; i += 512) {
        int h = i / 448, r = (i >> 2) % 112, c = 12 + (i & 3);
        sm32[Q_OFF + h * 2240 + r * 20 + c] = 0;
        sm32[K_OFF + h * 2240 + r * 20 + c] = 0;
    }

    // ---- phase A1: LN1 -> bf16 A image ----
    {
        float g0 = n1g[lane], g1 = n1g[lane + 32], g2 = n1g[lane + 64];
        float b0 = n1b[lane], b1 = n1b[lane + 32], b2 = n1b[lane + 64];
        for (int tr = wid; tr < 98; tr += 16) {
            const float* xr = x + spat_base(B_, tr);
            float v0 = xr[lane], v1 = xr[lane + 32], v2 = xr[lane + 64];
            float mean = warp_sum(v0 + v1 + v2) * (1.f / 96.f);
            float d0 = v0 - mean, d1 = v1 - mean, d2 = v2 - mean;
            float var = warp_sum(d0 * d0 + d1 * d1 + d2 * d2) * (1.f / 96.f);
            float rstd = rsqrtf(var + 1e-5f);
            float y0 = d0 * rstd * g0 + b0;
            float y1 = d1 * rstd * g1 + b1;
            float y2 = d2 * rstd * g2 + b2;
            float o0 = __shfl_xor_sync(0xffffffffu, y0, 1);
            float o1 = __shfl_xor_sync(0xffffffffu, y1, 1);
            float o2 = __shfl_xor_sync(0xffffffffu, y2, 1);
            if ((lane & 1) == 0) {
                int j = lane >> 1;
                sm32[XL_OFF + tr * 52 + j]      = pack_bf(y0, o0);
                sm32[XL_OFF + tr * 52 + j + 16] = pack_bf(y1, o1);
                sm32[XL_OFF + tr * 52 + j + 32] = pack_bf(y2, o2);
            }
        }
    }
    CP_WAIT0();
    __syncthreads();

    // ---- phase A2: QKV mma (112x288, K=96), warps 0..13, ldmatrix feed ----
    if (wid < 14) {
        const int mt = wid >> 1, nh = wid & 1;
        const int m0 = mt * 16;
        const uint32_t aA = sb + (XL_OFF + (m0 + l7 + lqr * 8) * 52) * 4 + (lqc << 4);
        const uint32_t bA = sb + (WQ_OFF + (nh * 144 + l7) * 52) * 4 + (lqr << 4);
        for (int p = 0; p < 2; ++p) {
            float acc[9][4];
            #pragma unroll
            for (int f = 0; f < 9; ++f)
                #pragma unroll
                for (int q = 0; q < 4; ++q) acc[f][q] = 0.f;
            #pragma unroll
            for (int k = 0; k < 6; ++k) {
                uint32_t a[4];
                ldsm_x4(a, aA + k * 32);
                #pragma unroll
                for (int f = 0; f < 9; ++f) {
                    uint32_t b[2];
                    ldsm_x2(b, bA + (p * 72 + f * 8) * 208 + k * 32);
                    mma16816(acc[f], a, b);
                }
            }
            #pragma unroll
            for (int f = 0; f < 9; ++f) {
                int col = nh * 144 + p * 72 + f * 8 + 2 * t;
                float bb0 = bias3[col], bb1 = bias3[col + 1];
                float v0 = acc[f][0] + bb0, v1 = acc[f][1] + bb1;
                float v2 = acc[f][2] + bb0, v3 = acc[f][3] + bb1;
                int which = col / 96, cc = col - which * 96;
                int head = cc / 24, cd = cc - head * 24;
                int r0 = m0 + g, r1 = m0 + g + 8;
                if (which == 0) {
                    const float sc = 0.20412414523193154f;
                    sm32[Q_OFF + head * 2240 + r0 * 20 + (cd >> 1)] = pack_bf(v0 * sc, v1 * sc);
                    sm32[Q_OFF + head * 2240 + r1 * 20 + (cd >> 1)] = pack_bf(v2 * sc, v3 * sc);
                } else if (which == 1) {
                    sm32[K_OFF + head * 2240 + r0 * 20 + (cd >> 1)] = pack_bf(v0, v1);
                    sm32[K_OFF + head * 2240 + r1 * 20 + (cd >> 1)] = pack_bf(v2, v3);
                } else {
                    __nv_bfloat16* vb = (__nv_bfloat16*)(sm32 + V_OFF + head * 1920);
                    vb[cd * 120 + r0]       = __float2bfloat16(v0);
                    vb[(cd + 1) * 120 + r0] = __float2bfloat16(v1);
                    vb[cd * 120 + r1]       = __float2bfloat16(v2);
                    vb[(cd + 1) * 120 + r1] = __float2bfloat16(v3);
                }
            }
        }
    }
    __syncthreads();

    // ---- phase B: attention, register softmax ----
    if (wid < 14) {
        const int hloc = wid & 1, mtB = wid >> 1;
        const int m0B = mtB * 16;
        const int r0 = m0B + g, r1 = r0 + 8;
        const uint32_t aQoff = sb + (Q_OFF + (m0B + l7 + lqr * 8) * 20) * 4 + (lqc << 4);
        const uint32_t bKoff = sb + (K_OFF + l7 * 20) * 4 + (lqr << 4);
        const uint32_t bVoff = sb + (V_OFF + l7 * 60) * 4 + (lqr << 4);
        for (int p = 0; p < 2; ++p) {
            const int h = p * 2 + hloc;
            const float* bi = g_cb + (cls * 4 + h) * 9604;
            const uint32_t qA = aQoff + h * 8960;
            const uint32_t kB = bKoff + h * 8960;
            const uint32_t vB = bVoff + h * 7680;

            float c[14][4];
            #pragma unroll
            for (int nt = 0; nt < 14; ++nt)
                #pragma unroll
                for (int q = 0; q < 4; ++q) c[nt][q] = 0.f;
            #pragma unroll
            for (int kt = 0; kt < 2; ++kt) {
                uint32_t a[4];
                ldsm_x4(a, qA + kt * 32);
                #pragma unroll
                for (int nt = 0; nt < 14; ++nt) {
                    uint32_t b[2];
                    ldsm_x2(b, kB + nt * 640 + kt * 32);
                    mma16816(c[nt], a, b);
                }
            }
            // combined bias+mask (single table); mask pad cols
            #pragma unroll
            for (int nt = 0; nt < 14; ++nt) {
                int col = nt * 8 + 2 * t;
                if (col < 98) {
                    if (r0 < 98) {
                        float2 bv = *(const float2*)(bi + r0 * 98 + col);
                        c[nt][0] += bv.x; c[nt][1] += bv.y;
                    }
                    if (r1 < 98) {
                        float2 bv = *(const float2*)(bi + r1 * 98 + col);
                        c[nt][2] += bv.x; c[nt][3] += bv.y;
                    }
                } else {
                    c[nt][0] = c[nt][1] = c[nt][2] = c[nt][3] = -1e30f;
                }
            }
            float mx0 = -1e30f, mx1 = -1e30f;
            #pragma unroll
            for (int nt = 0; nt < 14; ++nt) {
                mx0 = fmaxf(mx0, fmaxf(c[nt][0], c[nt][1]));
                mx1 = fmaxf(mx1, fmaxf(c[nt][2], c[nt][3]));
            }
            mx0 = fmaxf(mx0, __shfl_xor_sync(0xffffffffu, mx0, 1));
            mx0 = fmaxf(mx0, __shfl_xor_sync(0xffffffffu, mx0, 2));
            mx1 = fmaxf(mx1, __shfl_xor_sync(0xffffffffu, mx1, 1));
            mx1 = fmaxf(mx1, __shfl_xor_sync(0xffffffffu, mx1, 2));
            float s0 = 0.f, s1 = 0.f;
            #pragma unroll
            for (int nt = 0; nt < 14; ++nt) {
                c[nt][0] = __expf(c[nt][0] - mx0); s0 += c[nt][0];
                c[nt][1] = __expf(c[nt][1] - mx0); s0 += c[nt][1];
                c[nt][2] = __expf(c[nt][2] - mx1); s1 += c[nt][2];
                c[nt][3] = __expf(c[nt][3] - mx1); s1 += c[nt][3];
            }
            s0 += __shfl_xor_sync(0xffffffffu, s0, 1);
            s0 += __shfl_xor_sync(0xffffffffu, s0, 2);
            s1 += __shfl_xor_sync(0xffffffffu, s1, 1);
            s1 += __shfl_xor_sync(0xffffffffu, s1, 2);
            float inv0 = 1.f / s0, inv1 = 1.f / s1;

            float pv[3][4];
            #pragma unroll
            for (int f = 0; f < 3; ++f)
                #pragma unroll
                for (int q = 0; q < 4; ++q) pv[f][q] = 0.f;
            #pragma unroll
            for (int kt2 = 0; kt2 < 7; ++kt2) {
                uint32_t a[4];
                a[0] = pack_bf(c[2 * kt2][0] * inv0, c[2 * kt2][1] * inv0);
                a[1] = pack_bf(c[2 * kt2][2] * inv1, c[2 * kt2][3] * inv1);
                a[2] = pack_bf(c[2 * kt2 + 1][0] * inv0, c[2 * kt2 + 1][1] * inv0);
                a[3] = pack_bf(c[2 * kt2 + 1][2] * inv1, c[2 * kt2 + 1][3] * inv1);
                #pragma unroll
                for (int f = 0; f < 3; ++f) {
                    uint32_t b[2];
                    ldsm_x2(b, vB + f * 1920 + kt2 * 32);
                    mma16816(pv[f], a, b);
                }
            }
            #pragma unroll
            for (int f = 0; f < 3; ++f) {
                int col = f * 8 + 2 * t;
                sm32[AT_OFF + r0 * 52 + h * 12 + (col >> 1)] = pack_bf(pv[f][0], pv[f][1]);
                sm32[AT_OFF + r1 * 52 + h * 12 + (col >> 1)] = pack_bf(pv[f][2], pv[f][3]);
            }
        }
    } else {
        uint4* dst = (uint4*)(sm32 + WP2_OFF);
        const uint4* src = (const uint4*)g_pwi;
        for (int i = tid - 448; i < 1248; i += 64) dst[i] = src[i];
        for (int i = tid - 448; i < 96; i += 64) bias3[i] = pb[i];
    }
    __syncthreads();

    // ---- phase C: proj (112x96, K=96) ----
    if (wid < 14) {
        const int mtC = wid >> 1, nhC = wid & 1;
        const int m0C = mtC * 16;
        const uint32_t aC = sb + (AT_OFF + (m0C + l7 + lqr * 8) * 52) * 4 + (lqc << 4);
        const uint32_t bC = sb + (WP2_OFF + (nhC * 48 + l7) * 52) * 4 + (lqr << 4);
        float acc[6][4];
        #pragma unroll
        for (int f = 0; f < 6; ++f)
            #pragma unroll
            for (int q = 0; q < 4; ++q) acc[f][q] = 0.f;
        #pragma unroll
        for (int k = 0; k < 6; ++k) {
            uint32_t a[4];
            ldsm_x4(a, aC + k * 32);
            #pragma unroll
            for (int f = 0; f < 6; ++f) {
                uint32_t b[2];
                ldsm_x2(b, bC + f * 1664 + k * 32);
                mma16816(acc[f], a, b);
            }
        }
        #pragma unroll
        for (int f = 0; f < 6; ++f) {
            int col = nhC * 48 + f * 8 + 2 * t;
            *(float2*)(smF + PO_OFF + (m0C + g) * 100 + col)     = make_float2(acc[f][0], acc[f][1]);
            *(float2*)(smF + PO_OFF + (m0C + g + 8) * 100 + col) = make_float2(acc[f][2], acc[f][3]);
        }
    }
    __syncthreads();

    // ---- residual + scatter (div-free) ----
    {
        int row = tid / 96, col = tid - row * 96;
        for (int i = tid; i < 98 * 96; i += 512) {
            int base = ro[row];
            g_x2[base + col] = x[base + col] + smF[PO_OFF + row * 100 + col] + bias3[col];
            col += 32; row += 5;
            if (col >= 96) { col -= 96; row += 1; }
        }
    }
}

// ---------------- fused MLP: cp.async double-buffered 8-chunk pipeline ----------------
#define M2_A    0              // 64 x 52 (bf16); overlaid by OB (f32 stride 100) post-fc2
#define M2_HID  3328           // 64 x 196
#define M2_WB   15872          // 2 x 4992 double buffer
#define M2_B1   25856          // 384 f32
#define M2_B2   26240          // 96 f32
#define M2_U32  26336
#define M2_SMEM (M2_U32 * 4)

__global__ __launch_bounds__(512, 2) void k_mlpT(const float* __restrict__ n2g,
                                                 const float* __restrict__ n2b,
                                                 const float* __restrict__ f1b,
                                                 const float* __restrict__ f2b,
                                                 float* __restrict__ out) {
    extern __shared__ uint32_t smm[];
    float* smmF = (float*)smm;
    float* sf1b = smmF + M2_B1;
    float* sf2b = smmF + M2_B2;
    const int tid = threadIdx.x, wid = tid >> 5, lane = tid & 31;
    const int g = lane >> 2, t = lane & 3;
    const int l7 = lane & 7, lqr = (lane >> 3) & 1, lqc = lane >> 4;
    const int tok0 = blockIdx.x * 64;
    const uint32_t sb = cvta_sm(smm);

    // issue chunk 0 immediately (hidden under LN2)
    {
        uint32_t dst = sb + M2_WB * 4;
        const char* src = (const char*)g_w1c;
        for (int i = tid; i < 1248; i += 512) cp16(dst + i * 16, src + i * 16);
        CP_COMMIT();
    }
    if (tid < 384) sf1b[tid] = f1b[tid];
    if (tid >= 384 && tid < 480) sf2b[tid - 384] = f2b[tid - 384];

    // ---- LN2 -> bf16 A (stride 52) ----
    {
        float g0 = n2g[lane], g1 = n2g[lane + 32], g2 = n2g[lane + 64];
        float b0 = n2b[lane], b1 = n2b[lane + 32], b2 = n2b[lane + 64];
        for (int tr = wid; tr < 64; tr += 16) {
            const float* xr = g_x2 + (tok0 + tr) * 96;
            float v0 = xr[lane], v1 = xr[lane + 32], v2 = xr[lane + 64];
            float mean = warp_sum(v0 + v1 + v2) * (1.f / 96.f);
            float d0 = v0 - mean, d1 = v1 - mean, d2 = v2 - mean;
            float var = warp_sum(d0 * d0 + d1 * d1 + d2 * d2) * (1.f / 96.f);
            float rstd = rsqrtf(var + 1e-5f);
            float y0 = d0 * rstd * g0 + b0;
            float y1 = d1 * rstd * g1 + b1;
            float y2 = d2 * rstd * g2 + b2;
            float o0 = __shfl_xor_sync(0xffffffffu, y0, 1);
            float o1 = __shfl_xor_sync(0xffffffffu, y1, 1);
            float o2 = __shfl_xor_sync(0xffffffffu, y2, 1);
            if ((lane & 1) == 0) {
                int j = lane >> 1;
                smm[M2_A + tr * 52 + j]      = pack_bf(y0, o0);
                smm[M2_A + tr * 52 + j + 16] = pack_bf(y1, o1);
                smm[M2_A + tr * 52 + j + 32] = pack_bf(y2, o2);
            }
        }
    }
    CP_WAIT0();
    __syncthreads();      // A + chunk0 ready

    const int mt = wid & 3, nq = wid >> 2;
    const int mrow = mt * 16;
    const uint32_t aA = sb + (M2_A + (mrow + l7 + lqr * 8) * 52) * 4 + (lqc << 4);
    const uint32_t aH = sb + (M2_HID + (mrow + l7 + lqr * 8) * 196) * 4 + (lqc << 4);

    float acc2[3][4];
    #pragma unroll
    for (int f = 0; f < 3; ++f)
        #pragma unroll
        for (int q = 0; q < 4; ++q) acc2[f][q] = 0.f;

    for (int c = 0; c < 8; ++c) {
        const int cur = c & 1;
        if (c < 7) {  // prefetch next chunk into the free buffer
            const char* src = (c + 1 < 4) ? (const char*)(g_w1c + (c + 1) * 4992)
                                          : (const char*)(g_w2c + (c - 3) * 4992);
            uint32_t dst = sb + (M2_WB + (cur ^ 1) * 4992) * 4;
            for (int i = tid; i < 1248; i += 512) cp16(dst + i * 16, src + i * 16);
            CP_COMMIT();
        }
        const uint32_t bB = sb + (M2_WB + cur * 4992 + (nq * 24 + l7) * 52) * 4 + (lqr << 4);
        if (c < 4) {
            // fc1 chunk: 96 output cols, K=96
            float acc[3][4];
            #pragma unroll
            for (int f = 0; f < 3; ++f)
                #pragma unroll
                for (int q = 0; q < 4; ++q) acc[f][q] = 0.f;
            #pragma unroll
            for (int k = 0; k < 6; ++k) {
                uint32_t a[4];
                ldsm_x4(a, aA + k * 32);
                #pragma unroll
                for (int f = 0; f < 3; ++f) {
                    uint32_t b[2];
                    ldsm_x2(b, bB + f * 1664 + k * 32);
                    mma16816(acc[f], a, b);
                }
            }
            #pragma unroll
            for (int f = 0; f < 3; ++f) {
                int gcol = c * 96 + nq * 24 + f * 8 + 2 * t;
                float e0 = gelu_f(acc[f][0] + sf1b[gcol]);
                float e1 = gelu_f(acc[f][1] + sf1b[gcol + 1]);
                float e2 = gelu_f(acc[f][2] + sf1b[gcol]);
                float e3 = gelu_f(acc[f][3] + sf1b[gcol + 1]);
                int hc = gcol >> 1;
                smm[M2_HID + (mrow + g) * 196 + hc]     = pack_bf(e0, e1);
                smm[M2_HID + (mrow + g + 8) * 196 + hc] = pack_bf(e2, e3);
            }
        } else {
            // fc2 chunk cc=c-4: K slice [cc*96, cc*96+96)
            const uint32_t aC = aH + (c - 4) * 192;   // 48 u32 = 192 B per chunk
            #pragma unroll
            for (int k = 0; k < 6; ++k) {
                uint32_t a[4];
                ldsm_x4(a, aC + k * 32);
                #pragma unroll
                for (int f = 0; f < 3; ++f) {
                    uint32_t b[2];
                    ldsm_x2(b, bB + f * 1664 + k * 32);
                    mma16816(acc2[f], a, b);
                }
            }
        }
        if (c < 7) CP_WAIT0();
        __syncthreads();
    }

    #pragma unroll
    for (int f = 0; f < 3; ++f) {
        int col = nq * 24 + f * 8 + 2 * t;    // 0..94
        *(float2*)(smmF + (mrow + g) * 100 + col)     = make_float2(acc2[f][0], acc2[f][1]);
        *(float2*)(smmF + (mrow + g + 8) * 100 + col) = make_float2(acc2[f][2], acc2[f][3]);
    }
    __syncthreads();

    // ---- writeout: out = x2 + fc2 + bias (div-free) ----
    {
        const float* x2t = g_x2 + tok0 * 96;
        float* outt = out + tok0 * 96;
        int row = tid / 96, col = tid - row * 96;
        for (int i = tid; i < 6144; i += 512) {
            outt[i] = smmF[row * 100 + col] + sf2b[col] + x2t[i];
            col += 32; row += 5;
            if (col >= 96) { col -= 96; row += 1; }
        }
    }
}

// ---------------- launch ----------------
extern "C" void kernel_launch(void* const* d_in, const int* in_sizes, int n_in,
                              void* d_out, int out_size) {
    const float* x    = (const float*)d_in[0];
    const float* mask = (const float*)d_in[1];
    const float* n1g  = (const float*)d_in[2];
    const float* n1b  = (const float*)d_in[3];
    const float* qkvw = (const float*)d_in[4];
    const float* qkvb = (const float*)d_in[5];
    const float* rpb  = (const float*)d_in[6];
    const float* pw   = (const float*)d_in[7];
    const float* pb   = (const float*)d_in[8];
    const float* n2g  = (const float*)d_in[9];
    const float* n2b  = (const float*)d_in[10];
    const float* f1w  = (const float*)d_in[11];
    const float* f1b  = (const float*)d_in[12];
    const float* f2w  = (const float*)d_in[13];
    const float* f2b  = (const float*)d_in[14];
    float* out = (float*)d_out;

    cudaFuncSetAttribute(k_win,  cudaFuncAttributeMaxDynamicSharedMemorySize, WIN_SMEM);
    cudaFuncSetAttribute(k_mlpT, cudaFuncAttributeMaxDynamicSharedMemorySize, M2_SMEM);

    k_bias<<<dim3(98, 8), 128>>>(rpb, mask);
    k_wprep<<<234, 256>>>(f1w, f2w, qkvw, pw);
    k_win<<<2048, 512, WIN_SMEM>>>(x, n1g, n1b, qkvb, pb);
    k_mlpT<<<3136, 512, M2_SMEM>>>(n2g, n2b, f1b, f2b, out);
}